// round 9
// baseline (speedup 1.0000x reference)
#include <cuda_runtime.h>
#include <cuda_bf16.h>
#include <cstdint>
#include <math.h>

#define HNUM   12
#define DMODEL 768
#define BATCH  2
#define SEQ    2048
#define DK     64
#define MTOT   (BATCH * SEQ)          // 4096
#define NA_ (MTOT * DMODEL)           // 3145728
#define NW_ (DMODEL * DMODEL)         // 589824

// ---------------------------------------------------------------------------
// Scratch (allocation-free): everything bf16 hi/lo
// ---------------------------------------------------------------------------
__device__ __nv_bfloat16 g_qh[BATCH * HNUM * SEQ * DK];
__device__ __nv_bfloat16 g_ql[BATCH * HNUM * SEQ * DK];
__device__ __nv_bfloat16 g_kh[BATCH * HNUM * SEQ * DK];
__device__ __nv_bfloat16 g_kl[BATCH * HNUM * SEQ * DK];
__device__ __nv_bfloat16 g_vh[BATCH * HNUM * SEQ * DK];
__device__ __nv_bfloat16 g_vl[BATCH * HNUM * SEQ * DK];

__device__ __nv_bfloat16 g_ah[3 * NA_];
__device__ __nv_bfloat16 g_al[3 * NA_];
__device__ __nv_bfloat16 g_wh[4 * NW_];
__device__ __nv_bfloat16 g_wl[4 * NW_];
__device__ __nv_bfloat16 g_oh[NA_];
__device__ __nv_bfloat16 g_ol[NA_];

// ---------------------------------------------------------------------------
// Helpers
// ---------------------------------------------------------------------------
__device__ __forceinline__ uint32_t smem_to_u32(const void* p) {
    uint32_t a;
    asm("{ .reg .u64 t; cvta.to.shared.u64 t, %1; cvt.u32.u64 %0, t; }"
        : "=r"(a) : "l"(p));
    return a;
}
__device__ __forceinline__ void cp16(uint32_t s, const void* g) {
    asm volatile("cp.async.cg.shared.global [%0], [%1], 16;" :: "r"(s), "l"(g));
}
#define CP_COMMIT() asm volatile("cp.async.commit_group;" ::: "memory")
#define CP_WAIT1()  asm volatile("cp.async.wait_group 1;" ::: "memory")
#define CP_WAIT0()  asm volatile("cp.async.wait_group 0;" ::: "memory")

__device__ __forceinline__ void ldsm_x4(uint32_t& r0, uint32_t& r1,
                                        uint32_t& r2, uint32_t& r3, uint32_t addr) {
    asm volatile("ldmatrix.sync.aligned.m8n8.x4.shared.b16 {%0,%1,%2,%3}, [%4];"
                 : "=r"(r0), "=r"(r1), "=r"(r2), "=r"(r3) : "r"(addr));
}
__device__ __forceinline__ void ldsm_x4_t(uint32_t& r0, uint32_t& r1,
                                          uint32_t& r2, uint32_t& r3, uint32_t addr) {
    asm volatile("ldmatrix.sync.aligned.m8n8.x4.trans.shared.b16 {%0,%1,%2,%3}, [%4];"
                 : "=r"(r0), "=r"(r1), "=r"(r2), "=r"(r3) : "r"(addr));
}
__device__ __forceinline__ void mma_bf16(float* c, const uint32_t* a,
                                         uint32_t b0, uint32_t b1) {
    asm volatile("mma.sync.aligned.m16n8k16.row.col.f32.bf16.bf16.f32 "
                 "{%0,%1,%2,%3}, {%4,%5,%6,%7}, {%8,%9}, {%0,%1,%2,%3};"
                 : "+f"(c[0]), "+f"(c[1]), "+f"(c[2]), "+f"(c[3])
                 : "r"(a[0]), "r"(a[1]), "r"(a[2]), "r"(a[3]), "r"(b0), "r"(b1));
}
__device__ __forceinline__ uint32_t pack_bf16(float x, float y) {
    __nv_bfloat162 t = __floats2bfloat162_rn(x, y);
    return *(uint32_t*)&t;
}
__device__ __forceinline__ uint32_t prmt7632(uint32_t a, uint32_t b) {
    uint32_t r;
    asm("prmt.b32 %0, %1, %2, 0x7632;" : "=r"(r) : "r"(a), "r"(b));
    return r;
}
__device__ __forceinline__ float ex2f(float x) {
    float y;
    asm("ex2.approx.ftz.f32 %0, %1;" : "=f"(y) : "f"(x));
    return y;
}
__device__ __forceinline__ void split2(float v0, float v1,
                                       uint32_t& hp, uint32_t& lp) {
    const uint32_t b0 = __float_as_uint(v0), b1 = __float_as_uint(v1);
    hp = prmt7632(b0, b1);
    const float h0 = __uint_as_float(b0 & 0xffff0000u);
    const float h1 = __uint_as_float(b1 & 0xffff0000u);
    lp = pack_bf16(v0 - h0, v1 - h1);
}

// ---------------------------------------------------------------------------
// Fused fp32 -> bf16 hi/lo split; blockIdx.y selects tensor
// ---------------------------------------------------------------------------
__global__ void __launch_bounds__(256) cvt_split_kernel(
    const float* x0, const float* x1, const float* x2, const float* x3,
    __nv_bfloat16* h0p, __nv_bfloat16* h1p, __nv_bfloat16* h2p, __nv_bfloat16* h3p,
    __nv_bfloat16* l0p, __nv_bfloat16* l1p, __nv_bfloat16* l2p, __nv_bfloat16* l3p,
    int n4)
{
    const int z = blockIdx.y;
    const float* x = (z == 0) ? x0 : (z == 1) ? x1 : (z == 2) ? x2 : x3;
    __nv_bfloat16* hi = (z == 0) ? h0p : (z == 1) ? h1p : (z == 2) ? h2p : h3p;
    __nv_bfloat16* lo = (z == 0) ? l0p : (z == 1) ? l1p : (z == 2) ? l2p : l3p;
    int i = blockIdx.x * 256 + threadIdx.x;
    if (i >= n4) return;
    float4 v = ((const float4*)x)[i];
    uint32_t hp0, lp0, hp1, lp1;
    split2(v.x, v.y, hp0, lp0);
    split2(v.z, v.w, hp1, lp1);
    ((uint32_t*)hi)[2 * i]     = hp0;
    ((uint32_t*)hi)[2 * i + 1] = hp1;
    ((uint32_t*)lo)[2 * i]     = lp0;
    ((uint32_t*)lo)[2 * i + 1] = lp1;
}

// ---------------------------------------------------------------------------
// HMMA GEMM (bf16x3), cp.async double-buffered.
// CTA tile 128x256, 8 warps as 2(M)x4(N), warp tile 64x64, K-chunk 64.
// ---------------------------------------------------------------------------
#define OFF_AH 0u
#define OFF_AL 16384u
#define OFF_BH 32768u
#define OFF_BL 65536u
#define STAGE_SZ 98304u
#define GEMM_SMEM 196608

__global__ void __launch_bounds__(256, 1) tc_gemm_kernel(
    const __nv_bfloat16* Abase_h, const __nv_bfloat16* Abase_l,
    const __nv_bfloat16* Wbase_h, const __nv_bfloat16* Wbase_l,
    const float* bias0, const float* bias1, const float* bias2,
    float* outf,
    __nv_bfloat16* o0h, __nv_bfloat16* o0l,
    __nv_bfloat16* o1h, __nv_bfloat16* o1l,
    __nv_bfloat16* o2h, __nv_bfloat16* o2l,
    float scale0, int qkv_mode)
{
    extern __shared__ __align__(16) char smem[];
    const uint32_t sb = smem_to_u32(smem);
    const int tid  = threadIdx.x;
    const int lane = tid & 31;
    const int wid  = tid >> 5;
    const int wm   = wid & 1;
    const int wn   = wid >> 1;
    const int bm = blockIdx.y * 128;
    const int bn = blockIdx.x * 256;
    const int z  = blockIdx.z;

    const __nv_bfloat16* Ah = Abase_h + (size_t)z * NA_;
    const __nv_bfloat16* Al = Abase_l + (size_t)z * NA_;
    const __nv_bfloat16* Bh = Wbase_h + (size_t)z * NW_;
    const __nv_bfloat16* Bl = Wbase_l + (size_t)z * NW_;
    const float* bias = (z == 0) ? bias0 : (z == 1) ? bias1 : bias2;
    const float scale = (z == 0) ? scale0 : 1.0f;
    __nv_bfloat16* outh = (z == 0) ? o0h : (z == 1) ? o1h : o2h;
    __nv_bfloat16* outl = (z == 0) ? o0l : (z == 1) ? o1l : o2l;

    float acc[4][8][4];
#pragma unroll
    for (int mi = 0; mi < 4; mi++)
#pragma unroll
        for (int nj = 0; nj < 8; nj++)
#pragma unroll
            for (int c = 0; c < 4; c++) acc[mi][nj][c] = 0.0f;

    const int a_row   = wm * 64 + (lane & 15);
    const int a_chalf = lane >> 4;
    const int b_nloc  = wn * 64 + (lane & 7) + ((lane >> 4) << 3);
    const int b_chalf = (lane >> 3) & 1;
    const int rm8     = lane & 7;

    auto prefetch = [&](int ch, int st) {
        const uint32_t base = sb + st * STAGE_SZ;
        const int k0 = ch * 64;
#pragma unroll
        for (int i = tid; i < 1024; i += 256) {
            const int r = i >> 3, c = i & 7;
            const uint32_t so = (uint32_t)(r * 128 + ((c ^ (r & 7)) << 4));
            const size_t ga = (size_t)(bm + r) * DMODEL + k0 + c * 8;
            cp16(base + OFF_AH + so, Ah + ga);
            cp16(base + OFF_AL + so, Al + ga);
        }
#pragma unroll
        for (int i = tid; i < 2048; i += 256) {
            const int r = i >> 3, c = i & 7;
            const uint32_t so = (uint32_t)(r * 128 + ((c ^ (r & 7)) << 4));
            const size_t gb = (size_t)(bn + r) * DMODEL + k0 + c * 8;
            cp16(base + OFF_BH + so, Bh + gb);
            cp16(base + OFF_BL + so, Bl + gb);
        }
        CP_COMMIT();
    };

    prefetch(0, 0);
    for (int ch = 0; ch < DMODEL / 64; ch++) {
        if (ch + 1 < DMODEL / 64) { prefetch(ch + 1, (ch + 1) & 1); CP_WAIT1(); }
        else                      { CP_WAIT0(); }
        __syncthreads();

        const uint32_t base = sb + (ch & 1) * STAGE_SZ;
#pragma unroll
        for (int ks = 0; ks < 4; ks++) {
            uint32_t ahf[4][4], alf[4][4];
            const uint32_t aco = (uint32_t)(((ks * 2 + a_chalf) ^ rm8) << 4);
#pragma unroll
            for (int mi = 0; mi < 4; mi++) {
                const int row = a_row + mi * 16;
                ldsm_x4(ahf[mi][0], ahf[mi][1], ahf[mi][2], ahf[mi][3],
                        base + OFF_AH + row * 128 + aco);
                ldsm_x4(alf[mi][0], alf[mi][1], alf[mi][2], alf[mi][3],
                        base + OFF_AL + row * 128 + aco);
            }
            const uint32_t bco = (uint32_t)(((ks * 2 + b_chalf) ^ rm8) << 4);
#pragma unroll
            for (int np = 0; np < 4; np++) {
                const int nrow = b_nloc + np * 16;
                uint32_t bh0, bh1, bh2, bh3, bl0, bl1, bl2, bl3;
                ldsm_x4(bh0, bh1, bh2, bh3, base + OFF_BH + nrow * 128 + bco);
                ldsm_x4(bl0, bl1, bl2, bl3, base + OFF_BL + nrow * 128 + bco);
#pragma unroll
                for (int mi = 0; mi < 4; mi++) {
                    mma_bf16(acc[mi][np * 2],     ahf[mi], bh0, bh1);
                    mma_bf16(acc[mi][np * 2],     ahf[mi], bl0, bl1);
                    mma_bf16(acc[mi][np * 2],     alf[mi], bh0, bh1);
                    mma_bf16(acc[mi][np * 2 + 1], ahf[mi], bh2, bh3);
                    mma_bf16(acc[mi][np * 2 + 1], ahf[mi], bl2, bl3);
                    mma_bf16(acc[mi][np * 2 + 1], alf[mi], bh2, bh3);
                }
            }
        }
        __syncthreads();
    }

    const int erow = bm + wm * 64 + (lane >> 2);
    const int ecol = bn + wn * 64 + (lane & 3) * 2;
#pragma unroll
    for (int mi = 0; mi < 4; mi++) {
#pragma unroll
        for (int nj = 0; nj < 8; nj++) {
            const int gc = ecol + nj * 8;
            const float b0 = bias[gc], b1 = bias[gc + 1];
#pragma unroll
            for (int half = 0; half < 2; half++) {
                const int gr = erow + mi * 16 + half * 8;
                const float v0 = (acc[mi][nj][half * 2]     + b0) * scale;
                const float v1 = (acc[mi][nj][half * 2 + 1] + b1) * scale;
                if (!qkv_mode) {
                    *(float2*)(outf + (size_t)gr * DMODEL + gc) = make_float2(v0, v1);
                } else {
                    const int b = gr >> 11, s = gr & 2047;
                    const int h = gc >> 6,  d = gc & 63;
                    const size_t oi = (((size_t)b * HNUM + h) * SEQ + s) * DK + d;
                    uint32_t hp, lp;
                    split2(v0, v1, hp, lp);
                    *(uint32_t*)(outh + oi) = hp;
                    *(uint32_t*)(outl + oi) = lp;
                }
            }
        }
    }
}

// ---------------------------------------------------------------------------
// MMA flash attention: 128-thread CTA (4 warps x 16 q-rows = 64-row q-tile),
// 64-key chunks, 2-stage cp.async, 2 CTAs/SM so softmax of one CTA overlaps
// mma of the other.
// ---------------------------------------------------------------------------
#define AT_KH 0u
#define AT_KL 8192u
#define AT_VH 16384u
#define AT_VL 24576u
#define AT_STAGE 32768u
#define ATTN_SMEM 65536

__global__ void __launch_bounds__(128, 2) attn_mma_kernel(
    const __nv_bfloat16* __restrict__ Qh, const __nv_bfloat16* __restrict__ Ql,
    const __nv_bfloat16* __restrict__ Kh, const __nv_bfloat16* __restrict__ Kl,
    const __nv_bfloat16* __restrict__ Vh, const __nv_bfloat16* __restrict__ Vl,
    const int* __restrict__ mask,
    __nv_bfloat16* __restrict__ Oh, __nv_bfloat16* __restrict__ Ol)
{
    extern __shared__ __align__(16) char smem[];
    __shared__ int msk[2][64];
    const uint32_t sb = smem_to_u32(smem);
    const int tid = threadIdx.x, lane = tid & 31, wid = tid >> 5;
    const int bh = blockIdx.y, b = bh / HNUM, h = bh % HNUM;
    const int q0 = blockIdx.x * 64;
    const size_t hb = (size_t)bh * SEQ * DK;
    const int rm8 = lane & 7;

    // Stage Q tile (64 rows hi/lo) in stage-0 K area, pull fragments
    for (int i = tid; i < 512; i += 128) {
        const int r = i >> 3, c = i & 7;
        const uint32_t so = (uint32_t)(r * 128 + ((c ^ (r & 7)) << 4));
        const size_t g = hb + (size_t)(q0 + r) * DK + c * 8;
        *(uint4*)(smem + AT_KH + so) = *(const uint4*)(Qh + g);
        *(uint4*)(smem + AT_KL + so) = *(const uint4*)(Ql + g);
    }
    if (tid < 64) msk[0][tid] = mask[b * SEQ + tid];
    __syncthreads();

    const int arow = wid * 16 + (lane & 15);
    const int ach  = lane >> 4;
    uint32_t qfh[4][4], qfl[4][4];
#pragma unroll
    for (int ks = 0; ks < 4; ks++) {
        const uint32_t co = (uint32_t)(((ks * 2 + ach) ^ rm8) << 4);
        ldsm_x4(qfh[ks][0], qfh[ks][1], qfh[ks][2], qfh[ks][3],
                sb + AT_KH + arow * 128 + co);
        ldsm_x4(qfl[ks][0], qfl[ks][1], qfl[ks][2], qfl[ks][3],
                sb + AT_KL + arow * 128 + co);
    }
    __syncthreads();

    float oacc[8][4];
#pragma unroll
    for (int nj = 0; nj < 8; nj++)
#pragma unroll
        for (int c = 0; c < 4; c++) oacc[nj][c] = 0.0f;
    float mr0 = -1e30f, mr1 = -1e30f, lr0 = 0.0f, lr1 = 0.0f;

    const int knloc = (lane & 7) + ((lane >> 4) << 3);
    const int kch   = (lane >> 3) & 1;
    const int vrow_base = (lane & 7) + (((lane >> 3) & 1) << 3);
    const int vch   = lane >> 4;
    const int c0i   = 2 * (lane & 3);

    auto prefetch_kv = [&](int ch, int st) {
        const uint32_t base = sb + st * AT_STAGE;
        const int j0 = ch * 64;
#pragma unroll
        for (int i = tid; i < 512; i += 128) {
            const int r = i >> 3, c = i & 7;
            const uint32_t so = (uint32_t)(r * 128 + ((c ^ (r & 7)) << 4));
            const size_t g = hb + (size_t)(j0 + r) * DK + c * 8;
            cp16(base + AT_KH + so, Kh + g);
            cp16(base + AT_KL + so, Kl + g);
            cp16(base + AT_VH + so, Vh + g);
            cp16(base + AT_VL + so, Vl + g);
        }
        CP_COMMIT();
    };

    prefetch_kv(0, 0);
    for (int ch = 0; ch < SEQ / 64; ch++) {
        if (ch + 1 < SEQ / 64) {
            prefetch_kv(ch + 1, (ch + 1) & 1);
            if (tid < 64) msk[(ch + 1) & 1][tid] = mask[b * SEQ + (ch + 1) * 64 + tid];
            CP_WAIT1();
        } else {
            CP_WAIT0();
        }
        __syncthreads();

        const uint32_t base = sb + (ch & 1) * AT_STAGE;
        const int* mk = msk[ch & 1];

        // S = Q K^T over 64 keys (8 n-tiles)
        float sacc[8][4];
#pragma unroll
        for (int nj = 0; nj < 8; nj++)
#pragma unroll
            for (int c = 0; c < 4; c++) sacc[nj][c] = 0.0f;

#pragma unroll
        for (int ks = 0; ks < 4; ks++) {
            const uint32_t co = (uint32_t)(((ks * 2 + kch) ^ rm8) << 4);
#pragma unroll
            for (int np = 0; np < 4; np++) {
                const int nrow = np * 16 + knloc;
                uint32_t h0, h1, h2, h3, l0, l1, l2, l3;
                ldsm_x4(h0, h1, h2, h3, base + AT_KH + nrow * 128 + co);
                ldsm_x4(l0, l1, l2, l3, base + AT_KL + nrow * 128 + co);
                mma_bf16(sacc[np * 2],     qfh[ks], h0, h1);
                mma_bf16(sacc[np * 2],     qfh[ks], l0, l1);
                mma_bf16(sacc[np * 2],     qfl[ks], h0, h1);
                mma_bf16(sacc[np * 2 + 1], qfh[ks], h2, h3);
                mma_bf16(sacc[np * 2 + 1], qfh[ks], l2, l3);
                mma_bf16(sacc[np * 2 + 1], qfl[ks], h2, h3);
            }
        }

        // Mask + online softmax (base-2)
#pragma unroll
        for (int nj = 0; nj < 8; nj++) {
            const int ki = nj * 8 + c0i;
            if (mk[ki] == 0)     { sacc[nj][0] = -1e9f; sacc[nj][2] = -1e9f; }
            if (mk[ki + 1] == 0) { sacc[nj][1] = -1e9f; sacc[nj][3] = -1e9f; }
        }
        float m0 = -1e30f, m1 = -1e30f;
#pragma unroll
        for (int nj = 0; nj < 8; nj++) {
            m0 = fmaxf(m0, fmaxf(sacc[nj][0], sacc[nj][1]));
            m1 = fmaxf(m1, fmaxf(sacc[nj][2], sacc[nj][3]));
        }
        m0 = fmaxf(m0, __shfl_xor_sync(0xffffffffu, m0, 1));
        m0 = fmaxf(m0, __shfl_xor_sync(0xffffffffu, m0, 2));
        m1 = fmaxf(m1, __shfl_xor_sync(0xffffffffu, m1, 1));
        m1 = fmaxf(m1, __shfl_xor_sync(0xffffffffu, m1, 2));
        const float mn0 = fmaxf(mr0, m0), mn1 = fmaxf(mr1, m1);
        const float al0 = ex2f(mr0 - mn0), al1 = ex2f(mr1 - mn1);
        mr0 = mn0; mr1 = mn1;

        float rs0 = 0.0f, rs1 = 0.0f;
        uint32_t phi[8][2], plo[8][2];
#pragma unroll
        for (int nj = 0; nj < 8; nj++) {
            const float p0 = ex2f(sacc[nj][0] - mn0);
            const float p1 = ex2f(sacc[nj][1] - mn0);
            const float p2 = ex2f(sacc[nj][2] - mn1);
            const float p3 = ex2f(sacc[nj][3] - mn1);
            rs0 += p0 + p1; rs1 += p2 + p3;
            split2(p0, p1, phi[nj][0], plo[nj][0]);
            split2(p2, p3, phi[nj][1], plo[nj][1]);
        }
        rs0 += __shfl_xor_sync(0xffffffffu, rs0, 1);
        rs0 += __shfl_xor_sync(0xffffffffu, rs0, 2);
        rs1 += __shfl_xor_sync(0xffffffffu, rs1, 1);
        rs1 += __shfl_xor_sync(0xffffffffu, rs1, 2);
        lr0 = lr0 * al0 + rs0;
        lr1 = lr1 * al1 + rs1;
#pragma unroll
        for (int nj = 0; nj < 8; nj++) {
            oacc[nj][0] *= al0; oacc[nj][1] *= al0;
            oacc[nj][2] *= al1; oacc[nj][3] *= al1;
        }

        // O += P @ V  over 64 keys (4 k-tiles)
#pragma unroll
        for (int kt = 0; kt < 4; kt++) {
            uint32_t pah[4] = { phi[2 * kt][0], phi[2 * kt][1],
                                phi[2 * kt + 1][0], phi[2 * kt + 1][1] };
            uint32_t pal[4] = { plo[2 * kt][0], plo[2 * kt][1],
                                plo[2 * kt + 1][0], plo[2 * kt + 1][1] };
            const int vrow = kt * 16 + vrow_base;
#pragma unroll
            for (int np = 0; np < 4; np++) {
                const uint32_t co = (uint32_t)(((np * 2 + vch) ^ rm8) << 4);
                uint32_t h0, h1, h2, h3, l0, l1, l2, l3;
                ldsm_x4_t(h0, h1, h2, h3, base + AT_VH + vrow * 128 + co);
                ldsm_x4_t(l0, l1, l2, l3, base + AT_VL + vrow * 128 + co);
                mma_bf16(oacc[np * 2],     pah, h0, h1);
                mma_bf16(oacc[np * 2],     pah, l0, l1);
                mma_bf16(oacc[np * 2],     pal, h0, h1);
                mma_bf16(oacc[np * 2 + 1], pah, h2, h3);
                mma_bf16(oacc[np * 2 + 1], pah, l2, l3);
                mma_bf16(oacc[np * 2 + 1], pal, h2, h3);
            }
        }
        __syncthreads();
    }

    const float inv0 = 1.0f / lr0, inv1 = 1.0f / lr1;
    const int s0 = q0 + wid * 16 + (lane >> 2);
#pragma unroll
    for (int nj = 0; nj < 8; nj++) {
        const int d = nj * 8 + c0i;
#pragma unroll
        for (int half = 0; half < 2; half++) {
            const int s = s0 + half * 8;
            const float v0 = oacc[nj][half * 2]     * (half ? inv1 : inv0);
            const float v1 = oacc[nj][half * 2 + 1] * (half ? inv1 : inv0);
            const size_t oi = (size_t)(b * SEQ + s) * DMODEL + h * DK + d;
            uint32_t hp, lp;
            split2(v0, v1, hp, lp);
            *(uint32_t*)(Oh + oi) = hp;
            *(uint32_t*)(Ol + oi) = lp;
        }
    }
}

// ---------------------------------------------------------------------------
// Launch
// ---------------------------------------------------------------------------
extern "C" void kernel_launch(void* const* d_in, const int* in_sizes, int n_in,
                              void* d_out, int out_size)
{
    const float* query = (const float*)d_in[0];
    const float* key   = (const float*)d_in[1];
    const float* value = (const float*)d_in[2];
    const int*   mask  = (const int*)  d_in[3];
    const float* Wq    = (const float*)d_in[4];
    const float* bq    = (const float*)d_in[5];
    const float* Wk    = (const float*)d_in[6];
    const float* bk    = (const float*)d_in[7];
    const float* Wv    = (const float*)d_in[8];
    const float* bv    = (const float*)d_in[9];
    const float* Wo    = (const float*)d_in[10];
    const float* bo    = (const float*)d_in[11];

    __nv_bfloat16 *qh, *ql, *kh, *kl, *vh, *vl, *ah, *al, *wh, *wl, *oh, *ol;
    cudaGetSymbolAddress((void**)&qh, g_qh);
    cudaGetSymbolAddress((void**)&ql, g_ql);
    cudaGetSymbolAddress((void**)&kh, g_kh);
    cudaGetSymbolAddress((void**)&kl, g_kl);
    cudaGetSymbolAddress((void**)&vh, g_vh);
    cudaGetSymbolAddress((void**)&vl, g_vl);
    cudaGetSymbolAddress((void**)&ah, g_ah);
    cudaGetSymbolAddress((void**)&al, g_al);
    cudaGetSymbolAddress((void**)&wh, g_wh);
    cudaGetSymbolAddress((void**)&wl, g_wl);
    cudaGetSymbolAddress((void**)&oh, g_oh);
    cudaGetSymbolAddress((void**)&ol, g_ol);

    cudaFuncSetAttribute(tc_gemm_kernel,
                         cudaFuncAttributeMaxDynamicSharedMemorySize, GEMM_SMEM);
    cudaFuncSetAttribute(attn_mma_kernel,
                         cudaFuncAttributeMaxDynamicSharedMemorySize, ATTN_SMEM);

    const int a4 = NA_ / 4, w4 = NW_ / 4;

    cvt_split_kernel<<<dim3((a4 + 255) / 256, 3), 256>>>(
        query, key, value, nullptr,
        ah, ah + NA_, ah + 2 * NA_, nullptr,
        al, al + NA_, al + 2 * NA_, nullptr, a4);
    cvt_split_kernel<<<dim3((w4 + 255) / 256, 4), 256>>>(
        Wq, Wk, Wv, Wo,
        wh, wh + NW_, wh + 2 * NW_, wh + 3 * NW_,
        wl, wl + NW_, wl + 2 * NW_, wl + 3 * NW_, w4);

    const float qscale = 0.125f * 1.4426950408889634f;

    tc_gemm_kernel<<<dim3(DMODEL / 256, MTOT / 128, 3), 256, GEMM_SMEM>>>(
        ah, al, wh, wl, bq, bk, bv, nullptr,
        qh, ql, kh, kl, vh, vl, qscale, 1);

    attn_mma_kernel<<<dim3(SEQ / 64, BATCH * HNUM), 128, ATTN_SMEM>>>(
        qh, ql, kh, kl, vh, vl, mask, oh, ol);

    tc_gemm_kernel<<<dim3(DMODEL / 256, MTOT / 128, 1), 256, GEMM_SMEM>>>(
        oh, ol, wh + 3 * NW_, wl + 3 * NW_, bo, nullptr, nullptr, (float*)d_out,
        nullptr, nullptr, nullptr, nullptr, nullptr, nullptr, 1.0f, 0);
}

// round 10
// speedup vs baseline: 1.0047x; 1.0047x over previous
#include <cuda_runtime.h>
#include <cuda_bf16.h>
#include <cstdint>
#include <math.h>

#define HNUM   12
#define DMODEL 768
#define BATCH  2
#define SEQ    2048
#define DK     64
#define MTOT   (BATCH * SEQ)          // 4096
#define NA_ (MTOT * DMODEL)           // 3145728
#define NW_ (DMODEL * DMODEL)         // 589824

// ---------------------------------------------------------------------------
// Scratch (allocation-free): everything bf16 hi/lo
// ---------------------------------------------------------------------------
__device__ __nv_bfloat16 g_qh[BATCH * HNUM * SEQ * DK];
__device__ __nv_bfloat16 g_ql[BATCH * HNUM * SEQ * DK];
__device__ __nv_bfloat16 g_kh[BATCH * HNUM * SEQ * DK];
__device__ __nv_bfloat16 g_kl[BATCH * HNUM * SEQ * DK];
__device__ __nv_bfloat16 g_vh[BATCH * HNUM * SEQ * DK];
__device__ __nv_bfloat16 g_vl[BATCH * HNUM * SEQ * DK];

__device__ __nv_bfloat16 g_ah[3 * NA_];
__device__ __nv_bfloat16 g_al[3 * NA_];
__device__ __nv_bfloat16 g_wh[4 * NW_];
__device__ __nv_bfloat16 g_wl[4 * NW_];
__device__ __nv_bfloat16 g_oh[NA_];
__device__ __nv_bfloat16 g_ol[NA_];

// ---------------------------------------------------------------------------
// Helpers
// ---------------------------------------------------------------------------
__device__ __forceinline__ uint32_t smem_to_u32(const void* p) {
    uint32_t a;
    asm("{ .reg .u64 t; cvta.to.shared.u64 t, %1; cvt.u32.u64 %0, t; }"
        : "=r"(a) : "l"(p));
    return a;
}
__device__ __forceinline__ void cp16(uint32_t s, const void* g) {
    asm volatile("cp.async.cg.shared.global [%0], [%1], 16;" :: "r"(s), "l"(g));
}
#define CP_COMMIT() asm volatile("cp.async.commit_group;" ::: "memory")
#define CP_WAIT1()  asm volatile("cp.async.wait_group 1;" ::: "memory")
#define CP_WAIT0()  asm volatile("cp.async.wait_group 0;" ::: "memory")

__device__ __forceinline__ void ldsm_x4(uint32_t& r0, uint32_t& r1,
                                        uint32_t& r2, uint32_t& r3, uint32_t addr) {
    asm volatile("ldmatrix.sync.aligned.m8n8.x4.shared.b16 {%0,%1,%2,%3}, [%4];"
                 : "=r"(r0), "=r"(r1), "=r"(r2), "=r"(r3) : "r"(addr));
}
__device__ __forceinline__ void ldsm_x4_t(uint32_t& r0, uint32_t& r1,
                                          uint32_t& r2, uint32_t& r3, uint32_t addr) {
    asm volatile("ldmatrix.sync.aligned.m8n8.x4.trans.shared.b16 {%0,%1,%2,%3}, [%4];"
                 : "=r"(r0), "=r"(r1), "=r"(r2), "=r"(r3) : "r"(addr));
}
__device__ __forceinline__ void mma_bf16(float* c, const uint32_t* a,
                                         uint32_t b0, uint32_t b1) {
    asm volatile("mma.sync.aligned.m16n8k16.row.col.f32.bf16.bf16.f32 "
                 "{%0,%1,%2,%3}, {%4,%5,%6,%7}, {%8,%9}, {%0,%1,%2,%3};"
                 : "+f"(c[0]), "+f"(c[1]), "+f"(c[2]), "+f"(c[3])
                 : "r"(a[0]), "r"(a[1]), "r"(a[2]), "r"(a[3]), "r"(b0), "r"(b1));
}
__device__ __forceinline__ uint32_t pack_bf16(float x, float y) {
    __nv_bfloat162 t = __floats2bfloat162_rn(x, y);
    return *(uint32_t*)&t;
}
__device__ __forceinline__ uint32_t prmt7632(uint32_t a, uint32_t b) {
    uint32_t r;
    asm("prmt.b32 %0, %1, %2, 0x7632;" : "=r"(r) : "r"(a), "r"(b));
    return r;
}
__device__ __forceinline__ float ex2f(float x) {
    float y;
    asm("ex2.approx.ftz.f32 %0, %1;" : "=f"(y) : "f"(x));
    return y;
}
__device__ __forceinline__ void split2(float v0, float v1,
                                       uint32_t& hp, uint32_t& lp) {
    const uint32_t b0 = __float_as_uint(v0), b1 = __float_as_uint(v1);
    hp = prmt7632(b0, b1);
    const float h0 = __uint_as_float(b0 & 0xffff0000u);
    const float h1 = __uint_as_float(b1 & 0xffff0000u);
    lp = pack_bf16(v0 - h0, v1 - h1);
}

// ---------------------------------------------------------------------------
// Fused fp32 -> bf16 hi/lo split; blockIdx.y selects tensor
// ---------------------------------------------------------------------------
__global__ void __launch_bounds__(256) cvt_split_kernel(
    const float* x0, const float* x1, const float* x2, const float* x3,
    __nv_bfloat16* h0p, __nv_bfloat16* h1p, __nv_bfloat16* h2p, __nv_bfloat16* h3p,
    __nv_bfloat16* l0p, __nv_bfloat16* l1p, __nv_bfloat16* l2p, __nv_bfloat16* l3p,
    int n4)
{
    const int z = blockIdx.y;
    const float* x = (z == 0) ? x0 : (z == 1) ? x1 : (z == 2) ? x2 : x3;
    __nv_bfloat16* hi = (z == 0) ? h0p : (z == 1) ? h1p : (z == 2) ? h2p : h3p;
    __nv_bfloat16* lo = (z == 0) ? l0p : (z == 1) ? l1p : (z == 2) ? l2p : l3p;
    int i = blockIdx.x * 256 + threadIdx.x;
    if (i >= n4) return;
    float4 v = ((const float4*)x)[i];
    uint32_t hp0, lp0, hp1, lp1;
    split2(v.x, v.y, hp0, lp0);
    split2(v.z, v.w, hp1, lp1);
    ((uint32_t*)hi)[2 * i]     = hp0;
    ((uint32_t*)hi)[2 * i + 1] = hp1;
    ((uint32_t*)lo)[2 * i]     = lp0;
    ((uint32_t*)lo)[2 * i + 1] = lp1;
}

// ---------------------------------------------------------------------------
// HMMA GEMM (bf16x3), cp.async double-buffered.
// CTA tile 128x256, 8 warps as 2(M)x4(N), warp tile 64x64, K-chunk 64.
// Inner mma groups are issued in 3 passes (hh, hl, lh) over independent
// accumulators to break RAW chains on the tensor pipe.
// ---------------------------------------------------------------------------
#define OFF_AH 0u
#define OFF_AL 16384u
#define OFF_BH 32768u
#define OFF_BL 65536u
#define STAGE_SZ 98304u
#define GEMM_SMEM 196608

__global__ void __launch_bounds__(256, 1) tc_gemm_kernel(
    const __nv_bfloat16* Abase_h, const __nv_bfloat16* Abase_l,
    const __nv_bfloat16* Wbase_h, const __nv_bfloat16* Wbase_l,
    const float* bias0, const float* bias1, const float* bias2,
    float* outf,
    __nv_bfloat16* o0h, __nv_bfloat16* o0l,
    __nv_bfloat16* o1h, __nv_bfloat16* o1l,
    __nv_bfloat16* o2h, __nv_bfloat16* o2l,
    float scale0, int qkv_mode)
{
    extern __shared__ __align__(16) char smem[];
    const uint32_t sb = smem_to_u32(smem);
    const int tid  = threadIdx.x;
    const int lane = tid & 31;
    const int wid  = tid >> 5;
    const int wm   = wid & 1;
    const int wn   = wid >> 1;
    const int bm = blockIdx.y * 128;
    const int bn = blockIdx.x * 256;
    const int z  = blockIdx.z;

    const __nv_bfloat16* Ah = Abase_h + (size_t)z * NA_;
    const __nv_bfloat16* Al = Abase_l + (size_t)z * NA_;
    const __nv_bfloat16* Bh = Wbase_h + (size_t)z * NW_;
    const __nv_bfloat16* Bl = Wbase_l + (size_t)z * NW_;
    const float* bias = (z == 0) ? bias0 : (z == 1) ? bias1 : bias2;
    const float scale = (z == 0) ? scale0 : 1.0f;
    __nv_bfloat16* outh = (z == 0) ? o0h : (z == 1) ? o1h : o2h;
    __nv_bfloat16* outl = (z == 0) ? o0l : (z == 1) ? o1l : o2l;

    float acc[4][8][4];
#pragma unroll
    for (int mi = 0; mi < 4; mi++)
#pragma unroll
        for (int nj = 0; nj < 8; nj++)
#pragma unroll
            for (int c = 0; c < 4; c++) acc[mi][nj][c] = 0.0f;

    const int a_row   = wm * 64 + (lane & 15);
    const int a_chalf = lane >> 4;
    const int b_nloc  = wn * 64 + (lane & 7) + ((lane >> 4) << 3);
    const int b_chalf = (lane >> 3) & 1;
    const int rm8     = lane & 7;

    auto prefetch = [&](int ch, int st) {
        const uint32_t base = sb + st * STAGE_SZ;
        const int k0 = ch * 64;
#pragma unroll
        for (int i = tid; i < 1024; i += 256) {
            const int r = i >> 3, c = i & 7;
            const uint32_t so = (uint32_t)(r * 128 + ((c ^ (r & 7)) << 4));
            const size_t ga = (size_t)(bm + r) * DMODEL + k0 + c * 8;
            cp16(base + OFF_AH + so, Ah + ga);
            cp16(base + OFF_AL + so, Al + ga);
        }
#pragma unroll
        for (int i = tid; i < 2048; i += 256) {
            const int r = i >> 3, c = i & 7;
            const uint32_t so = (uint32_t)(r * 128 + ((c ^ (r & 7)) << 4));
            const size_t gb = (size_t)(bn + r) * DMODEL + k0 + c * 8;
            cp16(base + OFF_BH + so, Bh + gb);
            cp16(base + OFF_BL + so, Bl + gb);
        }
        CP_COMMIT();
    };

    prefetch(0, 0);
    for (int ch = 0; ch < DMODEL / 64; ch++) {
        if (ch + 1 < DMODEL / 64) { prefetch(ch + 1, (ch + 1) & 1); CP_WAIT1(); }
        else                      { CP_WAIT0(); }
        __syncthreads();

        const uint32_t base = sb + (ch & 1) * STAGE_SZ;
#pragma unroll
        for (int ks = 0; ks < 4; ks++) {
            uint32_t ahf[4][4], alf[4][4];
            const uint32_t aco = (uint32_t)(((ks * 2 + a_chalf) ^ rm8) << 4);
#pragma unroll
            for (int mi = 0; mi < 4; mi++) {
                const int row = a_row + mi * 16;
                ldsm_x4(ahf[mi][0], ahf[mi][1], ahf[mi][2], ahf[mi][3],
                        base + OFF_AH + row * 128 + aco);
                ldsm_x4(alf[mi][0], alf[mi][1], alf[mi][2], alf[mi][3],
                        base + OFF_AL + row * 128 + aco);
            }
            const uint32_t bco = (uint32_t)(((ks * 2 + b_chalf) ^ rm8) << 4);
#pragma unroll
            for (int np = 0; np < 4; np++) {
                const int nrow = b_nloc + np * 16;
                uint32_t bh0, bh1, bh2, bh3, bl0, bl1, bl2, bl3;
                ldsm_x4(bh0, bh1, bh2, bh3, base + OFF_BH + nrow * 128 + bco);
                ldsm_x4(bl0, bl1, bl2, bl3, base + OFF_BL + nrow * 128 + bco);
                // pass 1: hi*hi (8 independent accumulators)
#pragma unroll
                for (int mi = 0; mi < 4; mi++) {
                    mma_bf16(acc[mi][np * 2],     ahf[mi], bh0, bh1);
                    mma_bf16(acc[mi][np * 2 + 1], ahf[mi], bh2, bh3);
                }
                // pass 2: hi*lo
#pragma unroll
                for (int mi = 0; mi < 4; mi++) {
                    mma_bf16(acc[mi][np * 2],     ahf[mi], bl0, bl1);
                    mma_bf16(acc[mi][np * 2 + 1], ahf[mi], bl2, bl3);
                }
                // pass 3: lo*hi
#pragma unroll
                for (int mi = 0; mi < 4; mi++) {
                    mma_bf16(acc[mi][np * 2],     alf[mi], bh0, bh1);
                    mma_bf16(acc[mi][np * 2 + 1], alf[mi], bh2, bh3);
                }
            }
        }
        __syncthreads();
    }

    const int erow = bm + wm * 64 + (lane >> 2);
    const int ecol = bn + wn * 64 + (lane & 3) * 2;
#pragma unroll
    for (int mi = 0; mi < 4; mi++) {
#pragma unroll
        for (int nj = 0; nj < 8; nj++) {
            const int gc = ecol + nj * 8;
            const float b0 = bias[gc], b1 = bias[gc + 1];
#pragma unroll
            for (int half = 0; half < 2; half++) {
                const int gr = erow + mi * 16 + half * 8;
                const float v0 = (acc[mi][nj][half * 2]     + b0) * scale;
                const float v1 = (acc[mi][nj][half * 2 + 1] + b1) * scale;
                if (!qkv_mode) {
                    *(float2*)(outf + (size_t)gr * DMODEL + gc) = make_float2(v0, v1);
                } else {
                    const int b = gr >> 11, s = gr & 2047;
                    const int h = gc >> 6,  d = gc & 63;
                    const size_t oi = (((size_t)b * HNUM + h) * SEQ + s) * DK + d;
                    uint32_t hp, lp;
                    split2(v0, v1, hp, lp);
                    *(uint32_t*)(outh + oi) = hp;
                    *(uint32_t*)(outl + oi) = lp;
                }
            }
        }
    }
}

// ---------------------------------------------------------------------------
// MMA flash attention: 128-thread CTA (4 warps x 16 q-rows = 64-row q-tile),
// 64-key chunks, 2-stage cp.async, 2 CTAs/SM. QK and PV issue in 3
// dependency-free passes (hh, hl, lh) with fragments batched in registers.
// ---------------------------------------------------------------------------
#define AT_KH 0u
#define AT_KL 8192u
#define AT_VH 16384u
#define AT_VL 24576u
#define AT_STAGE 32768u
#define ATTN_SMEM 65536

__global__ void __launch_bounds__(128, 2) attn_mma_kernel(
    const __nv_bfloat16* __restrict__ Qh, const __nv_bfloat16* __restrict__ Ql,
    const __nv_bfloat16* __restrict__ Kh, const __nv_bfloat16* __restrict__ Kl,
    const __nv_bfloat16* __restrict__ Vh, const __nv_bfloat16* __restrict__ Vl,
    const int* __restrict__ mask,
    __nv_bfloat16* __restrict__ Oh, __nv_bfloat16* __restrict__ Ol)
{
    extern __shared__ __align__(16) char smem[];
    __shared__ int msk[2][64];
    const uint32_t sb = smem_to_u32(smem);
    const int tid = threadIdx.x, lane = tid & 31, wid = tid >> 5;
    const int bh = blockIdx.y, b = bh / HNUM, h = bh % HNUM;
    const int q0 = blockIdx.x * 64;
    const size_t hb = (size_t)bh * SEQ * DK;
    const int rm8 = lane & 7;

    // Stage Q tile (64 rows hi/lo) in stage-0 K area, pull fragments
    for (int i = tid; i < 512; i += 128) {
        const int r = i >> 3, c = i & 7;
        const uint32_t so = (uint32_t)(r * 128 + ((c ^ (r & 7)) << 4));
        const size_t g = hb + (size_t)(q0 + r) * DK + c * 8;
        *(uint4*)(smem + AT_KH + so) = *(const uint4*)(Qh + g);
        *(uint4*)(smem + AT_KL + so) = *(const uint4*)(Ql + g);
    }
    if (tid < 64) msk[0][tid] = mask[b * SEQ + tid];
    __syncthreads();

    const int arow = wid * 16 + (lane & 15);
    const int ach  = lane >> 4;
    uint32_t qfh[4][4], qfl[4][4];
#pragma unroll
    for (int ks = 0; ks < 4; ks++) {
        const uint32_t co = (uint32_t)(((ks * 2 + ach) ^ rm8) << 4);
        ldsm_x4(qfh[ks][0], qfh[ks][1], qfh[ks][2], qfh[ks][3],
                sb + AT_KH + arow * 128 + co);
        ldsm_x4(qfl[ks][0], qfl[ks][1], qfl[ks][2], qfl[ks][3],
                sb + AT_KL + arow * 128 + co);
    }
    __syncthreads();

    float oacc[8][4];
#pragma unroll
    for (int nj = 0; nj < 8; nj++)
#pragma unroll
        for (int c = 0; c < 4; c++) oacc[nj][c] = 0.0f;
    float mr0 = -1e30f, mr1 = -1e30f, lr0 = 0.0f, lr1 = 0.0f;

    const int knloc = (lane & 7) + ((lane >> 4) << 3);
    const int kch   = (lane >> 3) & 1;
    const int vrow_base = (lane & 7) + (((lane >> 3) & 1) << 3);
    const int vch   = lane >> 4;
    const int c0i   = 2 * (lane & 3);

    auto prefetch_kv = [&](int ch, int st) {
        const uint32_t base = sb + st * AT_STAGE;
        const int j0 = ch * 64;
#pragma unroll
        for (int i = tid; i < 512; i += 128) {
            const int r = i >> 3, c = i & 7;
            const uint32_t so = (uint32_t)(r * 128 + ((c ^ (r & 7)) << 4));
            const size_t g = hb + (size_t)(j0 + r) * DK + c * 8;
            cp16(base + AT_KH + so, Kh + g);
            cp16(base + AT_KL + so, Kl + g);
            cp16(base + AT_VH + so, Vh + g);
            cp16(base + AT_VL + so, Vl + g);
        }
        CP_COMMIT();
    };

    prefetch_kv(0, 0);
    for (int ch = 0; ch < SEQ / 64; ch++) {
        if (ch + 1 < SEQ / 64) {
            prefetch_kv(ch + 1, (ch + 1) & 1);
            if (tid < 64) msk[(ch + 1) & 1][tid] = mask[b * SEQ + (ch + 1) * 64 + tid];
            CP_WAIT1();
        } else {
            CP_WAIT0();
        }
        __syncthreads();

        const uint32_t base = sb + (ch & 1) * AT_STAGE;
        const int* mk = msk[ch & 1];

        // S = Q K^T over 64 keys (8 n-tiles), 3 dependency-free passes per ks
        float sacc[8][4];
#pragma unroll
        for (int nj = 0; nj < 8; nj++)
#pragma unroll
            for (int c = 0; c < 4; c++) sacc[nj][c] = 0.0f;

#pragma unroll
        for (int ks = 0; ks < 4; ks++) {
            const uint32_t co = (uint32_t)(((ks * 2 + kch) ^ rm8) << 4);
            uint32_t kfh[4][4], kfl[4][4];
#pragma unroll
            for (int np = 0; np < 4; np++) {
                const int nrow = np * 16 + knloc;
                ldsm_x4(kfh[np][0], kfh[np][1], kfh[np][2], kfh[np][3],
                        base + AT_KH + nrow * 128 + co);
                ldsm_x4(kfl[np][0], kfl[np][1], kfl[np][2], kfl[np][3],
                        base + AT_KL + nrow * 128 + co);
            }
#pragma unroll
            for (int np = 0; np < 4; np++) {
                mma_bf16(sacc[np * 2],     qfh[ks], kfh[np][0], kfh[np][1]);
                mma_bf16(sacc[np * 2 + 1], qfh[ks], kfh[np][2], kfh[np][3]);
            }
#pragma unroll
            for (int np = 0; np < 4; np++) {
                mma_bf16(sacc[np * 2],     qfh[ks], kfl[np][0], kfl[np][1]);
                mma_bf16(sacc[np * 2 + 1], qfh[ks], kfl[np][2], kfl[np][3]);
            }
#pragma unroll
            for (int np = 0; np < 4; np++) {
                mma_bf16(sacc[np * 2],     qfl[ks], kfh[np][0], kfh[np][1]);
                mma_bf16(sacc[np * 2 + 1], qfl[ks], kfh[np][2], kfh[np][3]);
            }
        }

        // Mask + online softmax (base-2)
#pragma unroll
        for (int nj = 0; nj < 8; nj++) {
            const int ki = nj * 8 + c0i;
            if (mk[ki] == 0)     { sacc[nj][0] = -1e9f; sacc[nj][2] = -1e9f; }
            if (mk[ki + 1] == 0) { sacc[nj][1] = -1e9f; sacc[nj][3] = -1e9f; }
        }
        float m0 = -1e30f, m1 = -1e30f;
#pragma unroll
        for (int nj = 0; nj < 8; nj++) {
            m0 = fmaxf(m0, fmaxf(sacc[nj][0], sacc[nj][1]));
            m1 = fmaxf(m1, fmaxf(sacc[nj][2], sacc[nj][3]));
        }
        m0 = fmaxf(m0, __shfl_xor_sync(0xffffffffu, m0, 1));
        m0 = fmaxf(m0, __shfl_xor_sync(0xffffffffu, m0, 2));
        m1 = fmaxf(m1, __shfl_xor_sync(0xffffffffu, m1, 1));
        m1 = fmaxf(m1, __shfl_xor_sync(0xffffffffu, m1, 2));
        const float mn0 = fmaxf(mr0, m0), mn1 = fmaxf(mr1, m1);
        const float al0 = ex2f(mr0 - mn0), al1 = ex2f(mr1 - mn1);
        mr0 = mn0; mr1 = mn1;

        float rs0 = 0.0f, rs1 = 0.0f;
        uint32_t phi[8][2], plo[8][2];
#pragma unroll
        for (int nj = 0; nj < 8; nj++) {
            const float p0 = ex2f(sacc[nj][0] - mn0);
            const float p1 = ex2f(sacc[nj][1] - mn0);
            const float p2 = ex2f(sacc[nj][2] - mn1);
            const float p3 = ex2f(sacc[nj][3] - mn1);
            rs0 += p0 + p1; rs1 += p2 + p3;
            split2(p0, p1, phi[nj][0], plo[nj][0]);
            split2(p2, p3, phi[nj][1], plo[nj][1]);
        }
        rs0 += __shfl_xor_sync(0xffffffffu, rs0, 1);
        rs0 += __shfl_xor_sync(0xffffffffu, rs0, 2);
        rs1 += __shfl_xor_sync(0xffffffffu, rs1, 1);
        rs1 += __shfl_xor_sync(0xffffffffu, rs1, 2);
        lr0 = lr0 * al0 + rs0;
        lr1 = lr1 * al1 + rs1;
#pragma unroll
        for (int nj = 0; nj < 8; nj++) {
            oacc[nj][0] *= al0; oacc[nj][1] *= al0;
            oacc[nj][2] *= al1; oacc[nj][3] *= al1;
        }

        // O += P @ V over 64 keys (4 k-tiles), 3 dependency-free passes per kt
#pragma unroll
        for (int kt = 0; kt < 4; kt++) {
            uint32_t pah[4] = { phi[2 * kt][0], phi[2 * kt][1],
                                phi[2 * kt + 1][0], phi[2 * kt + 1][1] };
            uint32_t pal[4] = { plo[2 * kt][0], plo[2 * kt][1],
                                plo[2 * kt + 1][0], plo[2 * kt + 1][1] };
            const int vrow = kt * 16 + vrow_base;
            uint32_t vfh[4][4], vfl[4][4];
#pragma unroll
            for (int np = 0; np < 4; np++) {
                const uint32_t co = (uint32_t)(((np * 2 + vch) ^ rm8) << 4);
                ldsm_x4_t(vfh[np][0], vfh[np][1], vfh[np][2], vfh[np][3],
                          base + AT_VH + vrow * 128 + co);
                ldsm_x4_t(vfl[np][0], vfl[np][1], vfl[np][2], vfl[np][3],
                          base + AT_VL + vrow * 128 + co);
            }
#pragma unroll
            for (int np = 0; np < 4; np++) {
                mma_bf16(oacc[np * 2],     pah, vfh[np][0], vfh[np][1]);
                mma_bf16(oacc[np * 2 + 1], pah, vfh[np][2], vfh[np][3]);
            }
#pragma unroll
            for (int np = 0; np < 4; np++) {
                mma_bf16(oacc[np * 2],     pah, vfl[np][0], vfl[np][1]);
                mma_bf16(oacc[np * 2 + 1], pah, vfl[np][2], vfl[np][3]);
            }
#pragma unroll
            for (int np = 0; np < 4; np++) {
                mma_bf16(oacc[np * 2],     pal, vfh[np][0], vfh[np][1]);
                mma_bf16(oacc[np * 2 + 1], pal, vfh[np][2], vfh[np][3]);
            }
        }
        __syncthreads();
    }

    const float inv0 = 1.0f / lr0, inv1 = 1.0f / lr1;
    const int s0 = q0 + wid * 16 + (lane >> 2);
#pragma unroll
    for (int nj = 0; nj < 8; nj++) {
        const int d = nj * 8 + c0i;
#pragma unroll
        for (int half = 0; half < 2; half++) {
            const int s = s0 + half * 8;
            const float v0 = oacc[nj][half * 2]     * (half ? inv1 : inv0);
            const float v1 = oacc[nj][half * 2 + 1] * (half ? inv1 : inv0);
            const size_t oi = (size_t)(b * SEQ + s) * DMODEL + h * DK + d;
            uint32_t hp, lp;
            split2(v0, v1, hp, lp);
            *(uint32_t*)(Oh + oi) = hp;
            *(uint32_t*)(Ol + oi) = lp;
        }
    }
}

// ---------------------------------------------------------------------------
// Launch
// ---------------------------------------------------------------------------
extern "C" void kernel_launch(void* const* d_in, const int* in_sizes, int n_in,
                              void* d_out, int out_size)
{
    const float* query = (const float*)d_in[0];
    const float* key   = (const float*)d_in[1];
    const float* value = (const float*)d_in[2];
    const int*   mask  = (const int*)  d_in[3];
    const float* Wq    = (const float*)d_in[4];
    const float* bq    = (const float*)d_in[5];
    const float* Wk    = (const float*)d_in[6];
    const float* bk    = (const float*)d_in[7];
    const float* Wv    = (const float*)d_in[8];
    const float* bv    = (const float*)d_in[9];
    const float* Wo    = (const float*)d_in[10];
    const float* bo    = (const float*)d_in[11];

    __nv_bfloat16 *qh, *ql, *kh, *kl, *vh, *vl, *ah, *al, *wh, *wl, *oh, *ol;
    cudaGetSymbolAddress((void**)&qh, g_qh);
    cudaGetSymbolAddress((void**)&ql, g_ql);
    cudaGetSymbolAddress((void**)&kh, g_kh);
    cudaGetSymbolAddress((void**)&kl, g_kl);
    cudaGetSymbolAddress((void**)&vh, g_vh);
    cudaGetSymbolAddress((void**)&vl, g_vl);
    cudaGetSymbolAddress((void**)&ah, g_ah);
    cudaGetSymbolAddress((void**)&al, g_al);
    cudaGetSymbolAddress((void**)&wh, g_wh);
    cudaGetSymbolAddress((void**)&wl, g_wl);
    cudaGetSymbolAddress((void**)&oh, g_oh);
    cudaGetSymbolAddress((void**)&ol, g_ol);

    cudaFuncSetAttribute(tc_gemm_kernel,
                         cudaFuncAttributeMaxDynamicSharedMemorySize, GEMM_SMEM);
    cudaFuncSetAttribute(attn_mma_kernel,
                         cudaFuncAttributeMaxDynamicSharedMemorySize, ATTN_SMEM);

    const int a4 = NA_ / 4, w4 = NW_ / 4;

    cvt_split_kernel<<<dim3((a4 + 255) / 256, 3), 256>>>(
        query, key, value, nullptr,
        ah, ah + NA_, ah + 2 * NA_, nullptr,
        al, al + NA_, al + 2 * NA_, nullptr, a4);
    cvt_split_kernel<<<dim3((w4 + 255) / 256, 4), 256>>>(
        Wq, Wk, Wv, Wo,
        wh, wh + NW_, wh + 2 * NW_, wh + 3 * NW_,
        wl, wl + NW_, wl + 2 * NW_, wl + 3 * NW_, w4);

    const float qscale = 0.125f * 1.4426950408889634f;

    tc_gemm_kernel<<<dim3(DMODEL / 256, MTOT / 128, 3), 256, GEMM_SMEM>>>(
        ah, al, wh, wl, bq, bk, bv, nullptr,
        qh, ql, kh, kl, vh, vl, qscale, 1);

    attn_mma_kernel<<<dim3(SEQ / 64, BATCH * HNUM), 128, ATTN_SMEM>>>(
        qh, ql, kh, kl, vh, vl, mask, oh, ol);

    tc_gemm_kernel<<<dim3(DMODEL / 256, MTOT / 128, 1), 256, GEMM_SMEM>>>(
        oh, ol, wh + 3 * NW_, wl + 3 * NW_, bo, nullptr, nullptr, (float*)d_out,
        nullptr, nullptr, nullptr, nullptr, nullptr, nullptr, 1.0f, 0);
}

// round 11
// speedup vs baseline: 1.3164x; 1.3102x over previous
#include <cuda_runtime.h>
#include <cuda_bf16.h>
#include <cuda_fp16.h>
#include <cstdint>
#include <math.h>

#define HNUM   12
#define DMODEL 768
#define BATCH  2
#define SEQ    2048
#define DK     64
#define MTOT   (BATCH * SEQ)          // 4096
#define NA_ (MTOT * DMODEL)           // 3145728
#define NW_ (DMODEL * DMODEL)         // 589824

// ---------------------------------------------------------------------------
// Scratch: Q/K/V single fp16; GEMM inputs bf16 hi/lo; attn out bf16 hi/lo
// ---------------------------------------------------------------------------
__device__ __half g_qh[BATCH * HNUM * SEQ * DK];
__device__ __half g_kh[BATCH * HNUM * SEQ * DK];
__device__ __half g_vh[BATCH * HNUM * SEQ * DK];

__device__ __nv_bfloat16 g_ah[3 * NA_];
__device__ __nv_bfloat16 g_al[3 * NA_];
__device__ __nv_bfloat16 g_wh[4 * NW_];
__device__ __nv_bfloat16 g_wl[4 * NW_];
__device__ __nv_bfloat16 g_oh[NA_];
__device__ __nv_bfloat16 g_ol[NA_];

// ---------------------------------------------------------------------------
// Helpers
// ---------------------------------------------------------------------------
__device__ __forceinline__ uint32_t smem_to_u32(const void* p) {
    uint32_t a;
    asm("{ .reg .u64 t; cvta.to.shared.u64 t, %1; cvt.u32.u64 %0, t; }"
        : "=r"(a) : "l"(p));
    return a;
}
__device__ __forceinline__ void cp16(uint32_t s, const void* g) {
    asm volatile("cp.async.cg.shared.global [%0], [%1], 16;" :: "r"(s), "l"(g));
}
#define CP_COMMIT() asm volatile("cp.async.commit_group;" ::: "memory")
#define CP_WAIT1()  asm volatile("cp.async.wait_group 1;" ::: "memory")
#define CP_WAIT0()  asm volatile("cp.async.wait_group 0;" ::: "memory")

__device__ __forceinline__ void ldsm_x4(uint32_t& r0, uint32_t& r1,
                                        uint32_t& r2, uint32_t& r3, uint32_t addr) {
    asm volatile("ldmatrix.sync.aligned.m8n8.x4.shared.b16 {%0,%1,%2,%3}, [%4];"
                 : "=r"(r0), "=r"(r1), "=r"(r2), "=r"(r3) : "r"(addr));
}
__device__ __forceinline__ void ldsm_x4_t(uint32_t& r0, uint32_t& r1,
                                          uint32_t& r2, uint32_t& r3, uint32_t addr) {
    asm volatile("ldmatrix.sync.aligned.m8n8.x4.trans.shared.b16 {%0,%1,%2,%3}, [%4];"
                 : "=r"(r0), "=r"(r1), "=r"(r2), "=r"(r3) : "r"(addr));
}
__device__ __forceinline__ void mma_bf16(float* c, const uint32_t* a,
                                         uint32_t b0, uint32_t b1) {
    asm volatile("mma.sync.aligned.m16n8k16.row.col.f32.bf16.bf16.f32 "
                 "{%0,%1,%2,%3}, {%4,%5,%6,%7}, {%8,%9}, {%0,%1,%2,%3};"
                 : "+f"(c[0]), "+f"(c[1]), "+f"(c[2]), "+f"(c[3])
                 : "r"(a[0]), "r"(a[1]), "r"(a[2]), "r"(a[3]), "r"(b0), "r"(b1));
}
__device__ __forceinline__ void mma_fp16(float* c, const uint32_t* a,
                                         uint32_t b0, uint32_t b1) {
    asm volatile("mma.sync.aligned.m16n8k16.row.col.f32.f16.f16.f32 "
                 "{%0,%1,%2,%3}, {%4,%5,%6,%7}, {%8,%9}, {%0,%1,%2,%3};"
                 : "+f"(c[0]), "+f"(c[1]), "+f"(c[2]), "+f"(c[3])
                 : "r"(a[0]), "r"(a[1]), "r"(a[2]), "r"(a[3]), "r"(b0), "r"(b1));
}
__device__ __forceinline__ uint32_t pack_bf16(float x, float y) {
    __nv_bfloat162 t = __floats2bfloat162_rn(x, y);
    return *(uint32_t*)&t;
}
__device__ __forceinline__ uint32_t prmt7632(uint32_t a, uint32_t b) {
    uint32_t r;
    asm("prmt.b32 %0, %1, %2, 0x7632;" : "=r"(r) : "r"(a), "r"(b));
    return r;
}
__device__ __forceinline__ float ex2f(float x) {
    float y;
    asm("ex2.approx.ftz.f32 %0, %1;" : "=f"(y) : "f"(x));
    return y;
}
// bf16 truncation hi/lo split of a pair
__device__ __forceinline__ void split2(float v0, float v1,
                                       uint32_t& hp, uint32_t& lp) {
    const uint32_t b0 = __float_as_uint(v0), b1 = __float_as_uint(v1);
    hp = prmt7632(b0, b1);
    const float h0 = __uint_as_float(b0 & 0xffff0000u);
    const float h1 = __uint_as_float(b1 & 0xffff0000u);
    lp = pack_bf16(v0 - h0, v1 - h1);
}
// fp16 hi/lo split of a pair
__device__ __forceinline__ void split2h(float v0, float v1,
                                        uint32_t& hp, uint32_t& lp) {
    __half2 h = __floats2half2_rn(v0, v1);
    hp = *(uint32_t*)&h;
    const float h0 = __half2float(__low2half(h));
    const float h1 = __half2float(__high2half(h));
    __half2 l = __floats2half2_rn(v0 - h0, v1 - h1);
    lp = *(uint32_t*)&l;
}

// ---------------------------------------------------------------------------
// Fused fp32 -> bf16 hi/lo split; blockIdx.y selects tensor
// ---------------------------------------------------------------------------
__global__ void __launch_bounds__(256) cvt_split_kernel(
    const float* x0, const float* x1, const float* x2, const float* x3,
    __nv_bfloat16* h0p, __nv_bfloat16* h1p, __nv_bfloat16* h2p, __nv_bfloat16* h3p,
    __nv_bfloat16* l0p, __nv_bfloat16* l1p, __nv_bfloat16* l2p, __nv_bfloat16* l3p,
    int n4)
{
    const int z = blockIdx.y;
    const float* x = (z == 0) ? x0 : (z == 1) ? x1 : (z == 2) ? x2 : x3;
    __nv_bfloat16* hi = (z == 0) ? h0p : (z == 1) ? h1p : (z == 2) ? h2p : h3p;
    __nv_bfloat16* lo = (z == 0) ? l0p : (z == 1) ? l1p : (z == 2) ? l2p : l3p;
    int i = blockIdx.x * 256 + threadIdx.x;
    if (i >= n4) return;
    float4 v = ((const float4*)x)[i];
    uint32_t hp0, lp0, hp1, lp1;
    split2(v.x, v.y, hp0, lp0);
    split2(v.z, v.w, hp1, lp1);
    ((uint32_t*)hi)[2 * i]     = hp0;
    ((uint32_t*)hi)[2 * i + 1] = hp1;
    ((uint32_t*)lo)[2 * i]     = lp0;
    ((uint32_t*)lo)[2 * i + 1] = lp1;
}

// ---------------------------------------------------------------------------
// HMMA GEMM (bf16x3), cp.async double-buffered.
// CTA tile 128x256, 8 warps as 2(M)x4(N), warp tile 64x64, K-chunk 64.
// qkv_mode=1: blockIdx.z selects; output fp16 single [B,H,S,64].
// qkv_mode=0: fp32 row-major output.
// ---------------------------------------------------------------------------
#define OFF_AH 0u
#define OFF_AL 16384u
#define OFF_BH 32768u
#define OFF_BL 65536u
#define STAGE_SZ 98304u
#define GEMM_SMEM 196608

__global__ void __launch_bounds__(256, 1) tc_gemm_kernel(
    const __nv_bfloat16* Abase_h, const __nv_bfloat16* Abase_l,
    const __nv_bfloat16* Wbase_h, const __nv_bfloat16* Wbase_l,
    const float* bias0, const float* bias1, const float* bias2,
    float* outf,
    __half* o0h, __half* o1h, __half* o2h,
    float scale0, int qkv_mode)
{
    extern __shared__ __align__(16) char smem[];
    const uint32_t sb = smem_to_u32(smem);
    const int tid  = threadIdx.x;
    const int lane = tid & 31;
    const int wid  = tid >> 5;
    const int wm   = wid & 1;
    const int wn   = wid >> 1;
    const int bm = blockIdx.y * 128;
    const int bn = blockIdx.x * 256;
    const int z  = blockIdx.z;

    const __nv_bfloat16* Ah = Abase_h + (size_t)z * NA_;
    const __nv_bfloat16* Al = Abase_l + (size_t)z * NA_;
    const __nv_bfloat16* Bh = Wbase_h + (size_t)z * NW_;
    const __nv_bfloat16* Bl = Wbase_l + (size_t)z * NW_;
    const float* bias = (z == 0) ? bias0 : (z == 1) ? bias1 : bias2;
    const float scale = (z == 0) ? scale0 : 1.0f;
    __half* outh = (z == 0) ? o0h : (z == 1) ? o1h : o2h;

    float acc[4][8][4];
#pragma unroll
    for (int mi = 0; mi < 4; mi++)
#pragma unroll
        for (int nj = 0; nj < 8; nj++)
#pragma unroll
            for (int c = 0; c < 4; c++) acc[mi][nj][c] = 0.0f;

    const int a_row   = wm * 64 + (lane & 15);
    const int a_chalf = lane >> 4;
    const int b_nloc  = wn * 64 + (lane & 7) + ((lane >> 4) << 3);
    const int b_chalf = (lane >> 3) & 1;
    const int rm8     = lane & 7;

    auto prefetch = [&](int ch, int st) {
        const uint32_t base = sb + st * STAGE_SZ;
        const int k0 = ch * 64;
#pragma unroll
        for (int i = tid; i < 1024; i += 256) {
            const int r = i >> 3, c = i & 7;
            const uint32_t so = (uint32_t)(r * 128 + ((c ^ (r & 7)) << 4));
            const size_t ga = (size_t)(bm + r) * DMODEL + k0 + c * 8;
            cp16(base + OFF_AH + so, Ah + ga);
            cp16(base + OFF_AL + so, Al + ga);
        }
#pragma unroll
        for (int i = tid; i < 2048; i += 256) {
            const int r = i >> 3, c = i & 7;
            const uint32_t so = (uint32_t)(r * 128 + ((c ^ (r & 7)) << 4));
            const size_t gb = (size_t)(bn + r) * DMODEL + k0 + c * 8;
            cp16(base + OFF_BH + so, Bh + gb);
            cp16(base + OFF_BL + so, Bl + gb);
        }
        CP_COMMIT();
    };

    prefetch(0, 0);
    for (int ch = 0; ch < DMODEL / 64; ch++) {
        if (ch + 1 < DMODEL / 64) { prefetch(ch + 1, (ch + 1) & 1); CP_WAIT1(); }
        else                      { CP_WAIT0(); }
        __syncthreads();

        const uint32_t base = sb + (ch & 1) * STAGE_SZ;
#pragma unroll
        for (int ks = 0; ks < 4; ks++) {
            uint32_t ahf[4][4], alf[4][4];
            const uint32_t aco = (uint32_t)(((ks * 2 + a_chalf) ^ rm8) << 4);
#pragma unroll
            for (int mi = 0; mi < 4; mi++) {
                const int row = a_row + mi * 16;
                ldsm_x4(ahf[mi][0], ahf[mi][1], ahf[mi][2], ahf[mi][3],
                        base + OFF_AH + row * 128 + aco);
                ldsm_x4(alf[mi][0], alf[mi][1], alf[mi][2], alf[mi][3],
                        base + OFF_AL + row * 128 + aco);
            }
            const uint32_t bco = (uint32_t)(((ks * 2 + b_chalf) ^ rm8) << 4);
#pragma unroll
            for (int np = 0; np < 4; np++) {
                const int nrow = b_nloc + np * 16;
                uint32_t bh0, bh1, bh2, bh3, bl0, bl1, bl2, bl3;
                ldsm_x4(bh0, bh1, bh2, bh3, base + OFF_BH + nrow * 128 + bco);
                ldsm_x4(bl0, bl1, bl2, bl3, base + OFF_BL + nrow * 128 + bco);
#pragma unroll
                for (int mi = 0; mi < 4; mi++) {
                    mma_bf16(acc[mi][np * 2],     ahf[mi], bh0, bh1);
                    mma_bf16(acc[mi][np * 2 + 1], ahf[mi], bh2, bh3);
                }
#pragma unroll
                for (int mi = 0; mi < 4; mi++) {
                    mma_bf16(acc[mi][np * 2],     ahf[mi], bl0, bl1);
                    mma_bf16(acc[mi][np * 2 + 1], ahf[mi], bl2, bl3);
                }
#pragma unroll
                for (int mi = 0; mi < 4; mi++) {
                    mma_bf16(acc[mi][np * 2],     alf[mi], bh0, bh1);
                    mma_bf16(acc[mi][np * 2 + 1], alf[mi], bh2, bh3);
                }
            }
        }
        __syncthreads();
    }

    const int erow = bm + wm * 64 + (lane >> 2);
    const int ecol = bn + wn * 64 + (lane & 3) * 2;
#pragma unroll
    for (int mi = 0; mi < 4; mi++) {
#pragma unroll
        for (int nj = 0; nj < 8; nj++) {
            const int gc = ecol + nj * 8;
            const float b0 = bias[gc], b1 = bias[gc + 1];
#pragma unroll
            for (int half = 0; half < 2; half++) {
                const int gr = erow + mi * 16 + half * 8;
                const float v0 = (acc[mi][nj][half * 2]     + b0) * scale;
                const float v1 = (acc[mi][nj][half * 2 + 1] + b1) * scale;
                if (!qkv_mode) {
                    *(float2*)(outf + (size_t)gr * DMODEL + gc) = make_float2(v0, v1);
                } else {
                    const int b = gr >> 11, s = gr & 2047;
                    const int h = gc >> 6,  d = gc & 63;
                    const size_t oi = (((size_t)b * HNUM + h) * SEQ + s) * DK + d;
                    __half2 hv = __floats2half2_rn(v0, v1);
                    *(uint32_t*)(outh + oi) = *(uint32_t*)&hv;
                }
            }
        }
    }
}

// ---------------------------------------------------------------------------
// MMA flash attention (fp16): Q,K,V single fp16; QK = 1 mma group;
// PV = (Ph + Pl) * Vh (2-term fp16 P split). 128-thread CTA, 64-key chunks,
// 2-stage cp.async, 2 CTAs/SM. Output bf16 hi/lo for the final projection.
// ---------------------------------------------------------------------------
#define AT_K 0u
#define AT_V 8192u
#define AT_STAGE 16384u
#define ATTN_SMEM 32768

__global__ void __launch_bounds__(128, 2) attn_mma_kernel(
    const __half* __restrict__ Q, const __half* __restrict__ K,
    const __half* __restrict__ V, const int* __restrict__ mask,
    __nv_bfloat16* __restrict__ Oh, __nv_bfloat16* __restrict__ Ol)
{
    extern __shared__ __align__(16) char smem[];
    __shared__ int msk[2][64];
    const uint32_t sb = smem_to_u32(smem);
    const int tid = threadIdx.x, lane = tid & 31, wid = tid >> 5;
    const int bh = blockIdx.y, b = bh / HNUM, h = bh % HNUM;
    const int q0 = blockIdx.x * 64;
    const size_t hb = (size_t)bh * SEQ * DK;
    const int rm8 = lane & 7;

    // Stage Q tile (64 rows fp16, 8 KB) in stage-0 K area, pull fragments
    for (int i = tid; i < 512; i += 128) {
        const int r = i >> 3, c = i & 7;
        const uint32_t so = (uint32_t)(r * 128 + ((c ^ (r & 7)) << 4));
        *(uint4*)(smem + AT_K + so) =
            *(const uint4*)(Q + hb + (size_t)(q0 + r) * DK + c * 8);
    }
    if (tid < 64) msk[0][tid] = mask[b * SEQ + tid];
    __syncthreads();

    const int arow = wid * 16 + (lane & 15);
    const int ach  = lane >> 4;
    uint32_t qf[4][4];
#pragma unroll
    for (int ks = 0; ks < 4; ks++) {
        const uint32_t co = (uint32_t)(((ks * 2 + ach) ^ rm8) << 4);
        ldsm_x4(qf[ks][0], qf[ks][1], qf[ks][2], qf[ks][3],
                sb + AT_K + arow * 128 + co);
    }
    __syncthreads();

    float oacc[8][4];
#pragma unroll
    for (int nj = 0; nj < 8; nj++)
#pragma unroll
        for (int c = 0; c < 4; c++) oacc[nj][c] = 0.0f;
    float mr0 = -1e30f, mr1 = -1e30f, lr0 = 0.0f, lr1 = 0.0f;

    const int knloc = (lane & 7) + ((lane >> 4) << 3);
    const int kch   = (lane >> 3) & 1;
    const int vrow_base = (lane & 7) + (((lane >> 3) & 1) << 3);
    const int vch   = lane >> 4;
    const int c0i   = 2 * (lane & 3);

    auto prefetch_kv = [&](int ch, int st) {
        const uint32_t base = sb + st * AT_STAGE;
        const int j0 = ch * 64;
#pragma unroll
        for (int i = tid; i < 512; i += 128) {
            const int r = i >> 3, c = i & 7;
            const uint32_t so = (uint32_t)(r * 128 + ((c ^ (r & 7)) << 4));
            const size_t g = hb + (size_t)(j0 + r) * DK + c * 8;
            cp16(base + AT_K + so, K + g);
            cp16(base + AT_V + so, V + g);
        }
        CP_COMMIT();
    };

    prefetch_kv(0, 0);
    for (int ch = 0; ch < SEQ / 64; ch++) {
        if (ch + 1 < SEQ / 64) {
            prefetch_kv(ch + 1, (ch + 1) & 1);
            if (tid < 64) msk[(ch + 1) & 1][tid] = mask[b * SEQ + (ch + 1) * 64 + tid];
            CP_WAIT1();
        } else {
            CP_WAIT0();
        }
        __syncthreads();

        const uint32_t base = sb + (ch & 1) * AT_STAGE;
        const int* mk = msk[ch & 1];

        // S = Q K^T (single fp16 product)
        float sacc[8][4];
#pragma unroll
        for (int nj = 0; nj < 8; nj++)
#pragma unroll
            for (int c = 0; c < 4; c++) sacc[nj][c] = 0.0f;

#pragma unroll
        for (int ks = 0; ks < 4; ks++) {
            const uint32_t co = (uint32_t)(((ks * 2 + kch) ^ rm8) << 4);
            uint32_t kf[4][4];
#pragma unroll
            for (int np = 0; np < 4; np++) {
                const int nrow = np * 16 + knloc;
                ldsm_x4(kf[np][0], kf[np][1], kf[np][2], kf[np][3],
                        base + AT_K + nrow * 128 + co);
            }
#pragma unroll
            for (int np = 0; np < 4; np++) {
                mma_fp16(sacc[np * 2],     qf[ks], kf[np][0], kf[np][1]);
                mma_fp16(sacc[np * 2 + 1], qf[ks], kf[np][2], kf[np][3]);
            }
        }

        // Mask + online softmax (base-2)
#pragma unroll
        for (int nj = 0; nj < 8; nj++) {
            const int ki = nj * 8 + c0i;
            if (mk[ki] == 0)     { sacc[nj][0] = -1e9f; sacc[nj][2] = -1e9f; }
            if (mk[ki + 1] == 0) { sacc[nj][1] = -1e9f; sacc[nj][3] = -1e9f; }
        }
        float m0 = -1e30f, m1 = -1e30f;
#pragma unroll
        for (int nj = 0; nj < 8; nj++) {
            m0 = fmaxf(m0, fmaxf(sacc[nj][0], sacc[nj][1]));
            m1 = fmaxf(m1, fmaxf(sacc[nj][2], sacc[nj][3]));
        }
        m0 = fmaxf(m0, __shfl_xor_sync(0xffffffffu, m0, 1));
        m0 = fmaxf(m0, __shfl_xor_sync(0xffffffffu, m0, 2));
        m1 = fmaxf(m1, __shfl_xor_sync(0xffffffffu, m1, 1));
        m1 = fmaxf(m1, __shfl_xor_sync(0xffffffffu, m1, 2));
        const float mn0 = fmaxf(mr0, m0), mn1 = fmaxf(mr1, m1);
        const float al0 = ex2f(mr0 - mn0), al1 = ex2f(mr1 - mn1);
        mr0 = mn0; mr1 = mn1;

        float rs0 = 0.0f, rs1 = 0.0f;
        uint32_t phi[8][2], plo[8][2];
#pragma unroll
        for (int nj = 0; nj < 8; nj++) {
            const float p0 = ex2f(sacc[nj][0] - mn0);
            const float p1 = ex2f(sacc[nj][1] - mn0);
            const float p2 = ex2f(sacc[nj][2] - mn1);
            const float p3 = ex2f(sacc[nj][3] - mn1);
            rs0 += p0 + p1; rs1 += p2 + p3;
            split2h(p0, p1, phi[nj][0], plo[nj][0]);
            split2h(p2, p3, phi[nj][1], plo[nj][1]);
        }
        rs0 += __shfl_xor_sync(0xffffffffu, rs0, 1);
        rs0 += __shfl_xor_sync(0xffffffffu, rs0, 2);
        rs1 += __shfl_xor_sync(0xffffffffu, rs1, 1);
        rs1 += __shfl_xor_sync(0xffffffffu, rs1, 2);
        lr0 = lr0 * al0 + rs0;
        lr1 = lr1 * al1 + rs1;
#pragma unroll
        for (int nj = 0; nj < 8; nj++) {
            oacc[nj][0] *= al0; oacc[nj][1] *= al0;
            oacc[nj][2] *= al1; oacc[nj][3] *= al1;
        }

        // O += (Ph + Pl) @ Vh  (2 fp16 mma passes)
#pragma unroll
        for (int kt = 0; kt < 4; kt++) {
            uint32_t pah[4] = { phi[2 * kt][0], phi[2 * kt][1],
                                phi[2 * kt + 1][0], phi[2 * kt + 1][1] };
            uint32_t pal[4] = { plo[2 * kt][0], plo[2 * kt][1],
                                plo[2 * kt + 1][0], plo[2 * kt + 1][1] };
            const int vrow = kt * 16 + vrow_base;
            uint32_t vf[4][4];
#pragma unroll
            for (int np = 0; np < 4; np++) {
                const uint32_t co = (uint32_t)(((np * 2 + vch) ^ rm8) << 4);
                ldsm_x4_t(vf[np][0], vf[np][1], vf[np][2], vf[np][3],
                          base + AT_V + vrow * 128 + co);
            }
#pragma unroll
            for (int np = 0; np < 4; np++) {
                mma_fp16(oacc[np * 2],     pah, vf[np][0], vf[np][1]);
                mma_fp16(oacc[np * 2 + 1], pah, vf[np][2], vf[np][3]);
            }
#pragma unroll
            for (int np = 0; np < 4; np++) {
                mma_fp16(oacc[np * 2],     pal, vf[np][0], vf[np][1]);
                mma_fp16(oacc[np * 2 + 1], pal, vf[np][2], vf[np][3]);
            }
        }
        __syncthreads();
    }

    const float inv0 = 1.0f / lr0, inv1 = 1.0f / lr1;
    const int s0 = q0 + wid * 16 + (lane >> 2);
#pragma unroll
    for (int nj = 0; nj < 8; nj++) {
        const int d = nj * 8 + c0i;
#pragma unroll
        for (int half = 0; half < 2; half++) {
            const int s = s0 + half * 8;
            const float v0 = oacc[nj][half * 2]     * (half ? inv1 : inv0);
            const float v1 = oacc[nj][half * 2 + 1] * (half ? inv1 : inv0);
            const size_t oi = (size_t)(b * SEQ + s) * DMODEL + h * DK + d;
            uint32_t hp, lp;
            split2(v0, v1, hp, lp);
            *(uint32_t*)(Oh + oi) = hp;
            *(uint32_t*)(Ol + oi) = lp;
        }
    }
}

// ---------------------------------------------------------------------------
// Launch
// ---------------------------------------------------------------------------
extern "C" void kernel_launch(void* const* d_in, const int* in_sizes, int n_in,
                              void* d_out, int out_size)
{
    const float* query = (const float*)d_in[0];
    const float* key   = (const float*)d_in[1];
    const float* value = (const float*)d_in[2];
    const int*   mask  = (const int*)  d_in[3];
    const float* Wq    = (const float*)d_in[4];
    const float* bq    = (const float*)d_in[5];
    const float* Wk    = (const float*)d_in[6];
    const float* bk    = (const float*)d_in[7];
    const float* Wv    = (const float*)d_in[8];
    const float* bv    = (const float*)d_in[9];
    const float* Wo    = (const float*)d_in[10];
    const float* bo    = (const float*)d_in[11];

    __half *qh, *kh, *vh;
    __nv_bfloat16 *ah, *al, *wh, *wl, *oh, *ol;
    cudaGetSymbolAddress((void**)&qh, g_qh);
    cudaGetSymbolAddress((void**)&kh, g_kh);
    cudaGetSymbolAddress((void**)&vh, g_vh);
    cudaGetSymbolAddress((void**)&ah, g_ah);
    cudaGetSymbolAddress((void**)&al, g_al);
    cudaGetSymbolAddress((void**)&wh, g_wh);
    cudaGetSymbolAddress((void**)&wl, g_wl);
    cudaGetSymbolAddress((void**)&oh, g_oh);
    cudaGetSymbolAddress((void**)&ol, g_ol);

    cudaFuncSetAttribute(tc_gemm_kernel,
                         cudaFuncAttributeMaxDynamicSharedMemorySize, GEMM_SMEM);
    cudaFuncSetAttribute(attn_mma_kernel,
                         cudaFuncAttributeMaxDynamicSharedMemorySize, ATTN_SMEM);

    const int a4 = NA_ / 4, w4 = NW_ / 4;

    cvt_split_kernel<<<dim3((a4 + 255) / 256, 3), 256>>>(
        query, key, value, nullptr,
        ah, ah + NA_, ah + 2 * NA_, nullptr,
        al, al + NA_, al + 2 * NA_, nullptr, a4);
    cvt_split_kernel<<<dim3((w4 + 255) / 256, 4), 256>>>(
        Wq, Wk, Wv, Wo,
        wh, wh + NW_, wh + 2 * NW_, wh + 3 * NW_,
        wl, wl + NW_, wl + 2 * NW_, wl + 3 * NW_, w4);

    const float qscale = 0.125f * 1.4426950408889634f;

    tc_gemm_kernel<<<dim3(DMODEL / 256, MTOT / 128, 3), 256, GEMM_SMEM>>>(
        ah, al, wh, wl, bq, bk, bv, nullptr,
        qh, kh, vh, qscale, 1);

    attn_mma_kernel<<<dim3(SEQ / 64, BATCH * HNUM), 128, ATTN_SMEM>>>(
        qh, kh, vh, mask, oh, ol);

    tc_gemm_kernel<<<dim3(DMODEL / 256, MTOT / 128, 1), 256, GEMM_SMEM>>>(
        oh, ol, wh + 3 * NW_, wl + 3 * NW_, bo, nullptr, nullptr, (float*)d_out,
        nullptr, nullptr, nullptr, 1.0f, 0);
}

// round 12
// speedup vs baseline: 1.5590x; 1.1843x over previous
#include <cuda_runtime.h>
#include <cuda_bf16.h>
#include <cuda_fp16.h>
#include <cstdint>
#include <math.h>

#define HNUM   12
#define DMODEL 768
#define BATCH  2
#define SEQ    2048
#define DK     64
#define MTOT   (BATCH * SEQ)          // 4096
#define NA_ (MTOT * DMODEL)           // 3145728
#define NW_ (DMODEL * DMODEL)         // 589824

// ---------------------------------------------------------------------------
// Scratch: all fp16. Activations/attn-out 2-term (hi+lo); weights single.
// ---------------------------------------------------------------------------
__device__ __half g_q16[BATCH * HNUM * SEQ * DK];
__device__ __half g_k16[BATCH * HNUM * SEQ * DK];
__device__ __half g_v16[BATCH * HNUM * SEQ * DK];

__device__ __half g_ah[3 * NA_];
__device__ __half g_al[3 * NA_];
__device__ __half g_w16[4 * NW_];
__device__ __half g_oh[NA_];
__device__ __half g_ol[NA_];

// ---------------------------------------------------------------------------
// Helpers
// ---------------------------------------------------------------------------
__device__ __forceinline__ uint32_t smem_to_u32(const void* p) {
    uint32_t a;
    asm("{ .reg .u64 t; cvta.to.shared.u64 t, %1; cvt.u32.u64 %0, t; }"
        : "=r"(a) : "l"(p));
    return a;
}
__device__ __forceinline__ void cp16(uint32_t s, const void* g) {
    asm volatile("cp.async.cg.shared.global [%0], [%1], 16;" :: "r"(s), "l"(g));
}
#define CP_COMMIT() asm volatile("cp.async.commit_group;" ::: "memory")
#define CP_WAIT1()  asm volatile("cp.async.wait_group 1;" ::: "memory")
#define CP_WAIT0()  asm volatile("cp.async.wait_group 0;" ::: "memory")

__device__ __forceinline__ void ldsm_x4(uint32_t& r0, uint32_t& r1,
                                        uint32_t& r2, uint32_t& r3, uint32_t addr) {
    asm volatile("ldmatrix.sync.aligned.m8n8.x4.shared.b16 {%0,%1,%2,%3}, [%4];"
                 : "=r"(r0), "=r"(r1), "=r"(r2), "=r"(r3) : "r"(addr));
}
__device__ __forceinline__ void ldsm_x4_t(uint32_t& r0, uint32_t& r1,
                                          uint32_t& r2, uint32_t& r3, uint32_t addr) {
    asm volatile("ldmatrix.sync.aligned.m8n8.x4.trans.shared.b16 {%0,%1,%2,%3}, [%4];"
                 : "=r"(r0), "=r"(r1), "=r"(r2), "=r"(r3) : "r"(addr));
}
__device__ __forceinline__ void mma_fp16(float* c, const uint32_t* a,
                                         uint32_t b0, uint32_t b1) {
    asm volatile("mma.sync.aligned.m16n8k16.row.col.f32.f16.f16.f32 "
                 "{%0,%1,%2,%3}, {%4,%5,%6,%7}, {%8,%9}, {%0,%1,%2,%3};"
                 : "+f"(c[0]), "+f"(c[1]), "+f"(c[2]), "+f"(c[3])
                 : "r"(a[0]), "r"(a[1]), "r"(a[2]), "r"(a[3]), "r"(b0), "r"(b1));
}
__device__ __forceinline__ float ex2f(float x) {
    float y;
    asm("ex2.approx.ftz.f32 %0, %1;" : "=f"(y) : "f"(x));
    return y;
}
// fp16 hi/lo split of a pair -> packed hi, packed lo
__device__ __forceinline__ void split2h(float v0, float v1,
                                        uint32_t& hp, uint32_t& lp) {
    __half2 h = __floats2half2_rn(v0, v1);
    hp = *(uint32_t*)&h;
    const float h0 = __half2float(__low2half(h));
    const float h1 = __half2float(__high2half(h));
    __half2 l = __floats2half2_rn(v0 - h0, v1 - h1);
    lp = *(uint32_t*)&l;
}

// ---------------------------------------------------------------------------
// fp32 -> fp16 hi/lo split (activations); blockIdx.y selects tensor
// ---------------------------------------------------------------------------
__global__ void __launch_bounds__(256) cvt_split_h_kernel(
    const float* x0, const float* x1, const float* x2,
    __half* h0p, __half* h1p, __half* h2p,
    __half* l0p, __half* l1p, __half* l2p, int n4)
{
    const int z = blockIdx.y;
    const float* x = (z == 0) ? x0 : (z == 1) ? x1 : x2;
    __half* hi = (z == 0) ? h0p : (z == 1) ? h1p : h2p;
    __half* lo = (z == 0) ? l0p : (z == 1) ? l1p : l2p;
    int i = blockIdx.x * 256 + threadIdx.x;
    if (i >= n4) return;
    float4 v = ((const float4*)x)[i];
    uint32_t hp0, lp0, hp1, lp1;
    split2h(v.x, v.y, hp0, lp0);
    split2h(v.z, v.w, hp1, lp1);
    ((uint32_t*)hi)[2 * i]     = hp0;
    ((uint32_t*)hi)[2 * i + 1] = hp1;
    ((uint32_t*)lo)[2 * i]     = lp0;
    ((uint32_t*)lo)[2 * i + 1] = lp1;
}

// fp32 -> single fp16 (weights); blockIdx.y selects tensor
__global__ void __launch_bounds__(256) cvt_h_kernel(
    const float* x0, const float* x1, const float* x2, const float* x3,
    __half* o0, __half* o1, __half* o2, __half* o3, int n4)
{
    const int z = blockIdx.y;
    const float* x = (z == 0) ? x0 : (z == 1) ? x1 : (z == 2) ? x2 : x3;
    __half* o = (z == 0) ? o0 : (z == 1) ? o1 : (z == 2) ? o2 : o3;
    int i = blockIdx.x * 256 + threadIdx.x;
    if (i >= n4) return;
    float4 v = ((const float4*)x)[i];
    __half2 a = __floats2half2_rn(v.x, v.y);
    __half2 b = __floats2half2_rn(v.z, v.w);
    ((uint32_t*)o)[2 * i]     = *(uint32_t*)&a;
    ((uint32_t*)o)[2 * i + 1] = *(uint32_t*)&b;
}

// ---------------------------------------------------------------------------
// HMMA GEMM (fp16, A 2-term x W 1-term = 2 mmas), cp.async double-buffered.
// CTA tile 128x256, 8 warps as 2(M)x4(N), warp tile 64x64, K-chunk 64.
// qkv_mode=1: blockIdx.z selects; output single fp16 [B,H,S,64].
// qkv_mode=0: fp32 row-major output.
// ---------------------------------------------------------------------------
#define OFF_AH 0u
#define OFF_AL 16384u
#define OFF_B  32768u
#define STAGE_SZ 65536u
#define GEMM_SMEM 131072

__global__ void __launch_bounds__(256, 1) tc_gemm_kernel(
    const __half* Abase_h, const __half* Abase_l, const __half* Wbase,
    const float* bias0, const float* bias1, const float* bias2,
    float* outf,
    __half* o0h, __half* o1h, __half* o2h,
    float scale0, int qkv_mode)
{
    extern __shared__ __align__(16) char smem[];
    const uint32_t sb = smem_to_u32(smem);
    const int tid  = threadIdx.x;
    const int lane = tid & 31;
    const int wid  = tid >> 5;
    const int wm   = wid & 1;
    const int wn   = wid >> 1;
    const int bm = blockIdx.y * 128;
    const int bn = blockIdx.x * 256;
    const int z  = blockIdx.z;

    const __half* Ah = Abase_h + (size_t)z * NA_;
    const __half* Al = Abase_l + (size_t)z * NA_;
    const __half* W  = Wbase   + (size_t)z * NW_;
    const float* bias = (z == 0) ? bias0 : (z == 1) ? bias1 : bias2;
    const float scale = (z == 0) ? scale0 : 1.0f;
    __half* outh = (z == 0) ? o0h : (z == 1) ? o1h : o2h;

    float acc[4][8][4];
#pragma unroll
    for (int mi = 0; mi < 4; mi++)
#pragma unroll
        for (int nj = 0; nj < 8; nj++)
#pragma unroll
            for (int c = 0; c < 4; c++) acc[mi][nj][c] = 0.0f;

    const int a_row   = wm * 64 + (lane & 15);
    const int a_chalf = lane >> 4;
    const int b_nloc  = wn * 64 + (lane & 7) + ((lane >> 4) << 3);
    const int b_chalf = (lane >> 3) & 1;
    const int rm8     = lane & 7;

    auto prefetch = [&](int ch, int st) {
        const uint32_t base = sb + st * STAGE_SZ;
        const int k0 = ch * 64;
#pragma unroll
        for (int i = tid; i < 1024; i += 256) {
            const int r = i >> 3, c = i & 7;
            const uint32_t so = (uint32_t)(r * 128 + ((c ^ (r & 7)) << 4));
            const size_t ga = (size_t)(bm + r) * DMODEL + k0 + c * 8;
            cp16(base + OFF_AH + so, Ah + ga);
            cp16(base + OFF_AL + so, Al + ga);
        }
#pragma unroll
        for (int i = tid; i < 2048; i += 256) {
            const int r = i >> 3, c = i & 7;
            const uint32_t so = (uint32_t)(r * 128 + ((c ^ (r & 7)) << 4));
            cp16(base + OFF_B + so, W + (size_t)(bn + r) * DMODEL + k0 + c * 8);
        }
        CP_COMMIT();
    };

    prefetch(0, 0);
    for (int ch = 0; ch < DMODEL / 64; ch++) {
        if (ch + 1 < DMODEL / 64) { prefetch(ch + 1, (ch + 1) & 1); CP_WAIT1(); }
        else                      { CP_WAIT0(); }
        __syncthreads();

        const uint32_t base = sb + (ch & 1) * STAGE_SZ;
#pragma unroll
        for (int ks = 0; ks < 4; ks++) {
            uint32_t ahf[4][4], alf[4][4];
            const uint32_t aco = (uint32_t)(((ks * 2 + a_chalf) ^ rm8) << 4);
#pragma unroll
            for (int mi = 0; mi < 4; mi++) {
                const int row = a_row + mi * 16;
                ldsm_x4(ahf[mi][0], ahf[mi][1], ahf[mi][2], ahf[mi][3],
                        base + OFF_AH + row * 128 + aco);
                ldsm_x4(alf[mi][0], alf[mi][1], alf[mi][2], alf[mi][3],
                        base + OFF_AL + row * 128 + aco);
            }
            const uint32_t bco = (uint32_t)(((ks * 2 + b_chalf) ^ rm8) << 4);
#pragma unroll
            for (int np = 0; np < 4; np++) {
                const int nrow = b_nloc + np * 16;
                uint32_t b0, b1, b2, b3;
                ldsm_x4(b0, b1, b2, b3, base + OFF_B + nrow * 128 + bco);
                // pass 1: Ah * W (8 independent accumulators)
#pragma unroll
                for (int mi = 0; mi < 4; mi++) {
                    mma_fp16(acc[mi][np * 2],     ahf[mi], b0, b1);
                    mma_fp16(acc[mi][np * 2 + 1], ahf[mi], b2, b3);
                }
                // pass 2: Al * W
#pragma unroll
                for (int mi = 0; mi < 4; mi++) {
                    mma_fp16(acc[mi][np * 2],     alf[mi], b0, b1);
                    mma_fp16(acc[mi][np * 2 + 1], alf[mi], b2, b3);
                }
            }
        }
        __syncthreads();
    }

    const int erow = bm + wm * 64 + (lane >> 2);
    const int ecol = bn + wn * 64 + (lane & 3) * 2;
#pragma unroll
    for (int mi = 0; mi < 4; mi++) {
#pragma unroll
        for (int nj = 0; nj < 8; nj++) {
            const int gc = ecol + nj * 8;
            const float b0 = bias[gc], b1 = bias[gc + 1];
#pragma unroll
            for (int half = 0; half < 2; half++) {
                const int gr = erow + mi * 16 + half * 8;
                const float v0 = (acc[mi][nj][half * 2]     + b0) * scale;
                const float v1 = (acc[mi][nj][half * 2 + 1] + b1) * scale;
                if (!qkv_mode) {
                    *(float2*)(outf + (size_t)gr * DMODEL + gc) = make_float2(v0, v1);
                } else {
                    const int b = gr >> 11, s = gr & 2047;
                    const int h = gc >> 6,  d = gc & 63;
                    const size_t oi = (((size_t)b * HNUM + h) * SEQ + s) * DK + d;
                    __half2 hv = __floats2half2_rn(v0, v1);
                    *(uint32_t*)(outh + oi) = *(uint32_t*)&hv;
                }
            }
        }
    }
}

// ---------------------------------------------------------------------------
// MMA flash attention (fp16): Q,K,V single fp16; QK = 1 mma group;
// PV = (Ph + Pl) * V. 128-thread CTA, 64-key chunks, 2-stage cp.async,
// 2 CTAs/SM. Output fp16 hi/lo for the final projection.
// ---------------------------------------------------------------------------
#define AT_K 0u
#define AT_V 8192u
#define AT_STAGE 16384u
#define ATTN_SMEM 32768

__global__ void __launch_bounds__(128, 2) attn_mma_kernel(
    const __half* __restrict__ Q, const __half* __restrict__ K,
    const __half* __restrict__ V, const int* __restrict__ mask,
    __half* __restrict__ Oh, __half* __restrict__ Ol)
{
    extern __shared__ __align__(16) char smem[];
    __shared__ int msk[2][64];
    const uint32_t sb = smem_to_u32(smem);
    const int tid = threadIdx.x, lane = tid & 31, wid = tid >> 5;
    const int bh = blockIdx.y, b = bh / HNUM, h = bh % HNUM;
    const int q0 = blockIdx.x * 64;
    const size_t hb = (size_t)bh * SEQ * DK;
    const int rm8 = lane & 7;

    for (int i = tid; i < 512; i += 128) {
        const int r = i >> 3, c = i & 7;
        const uint32_t so = (uint32_t)(r * 128 + ((c ^ (r & 7)) << 4));
        *(uint4*)(smem + AT_K + so) =
            *(const uint4*)(Q + hb + (size_t)(q0 + r) * DK + c * 8);
    }
    if (tid < 64) msk[0][tid] = mask[b * SEQ + tid];
    __syncthreads();

    const int arow = wid * 16 + (lane & 15);
    const int ach  = lane >> 4;
    uint32_t qf[4][4];
#pragma unroll
    for (int ks = 0; ks < 4; ks++) {
        const uint32_t co = (uint32_t)(((ks * 2 + ach) ^ rm8) << 4);
        ldsm_x4(qf[ks][0], qf[ks][1], qf[ks][2], qf[ks][3],
                sb + AT_K + arow * 128 + co);
    }
    __syncthreads();

    float oacc[8][4];
#pragma unroll
    for (int nj = 0; nj < 8; nj++)
#pragma unroll
        for (int c = 0; c < 4; c++) oacc[nj][c] = 0.0f;
    float mr0 = -1e30f, mr1 = -1e30f, lr0 = 0.0f, lr1 = 0.0f;

    const int knloc = (lane & 7) + ((lane >> 4) << 3);
    const int kch   = (lane >> 3) & 1;
    const int vrow_base = (lane & 7) + (((lane >> 3) & 1) << 3);
    const int vch   = lane >> 4;
    const int c0i   = 2 * (lane & 3);

    auto prefetch_kv = [&](int ch, int st) {
        const uint32_t base = sb + st * AT_STAGE;
        const int j0 = ch * 64;
#pragma unroll
        for (int i = tid; i < 512; i += 128) {
            const int r = i >> 3, c = i & 7;
            const uint32_t so = (uint32_t)(r * 128 + ((c ^ (r & 7)) << 4));
            const size_t g = hb + (size_t)(j0 + r) * DK + c * 8;
            cp16(base + AT_K + so, K + g);
            cp16(base + AT_V + so, V + g);
        }
        CP_COMMIT();
    };

    prefetch_kv(0, 0);
    for (int ch = 0; ch < SEQ / 64; ch++) {
        if (ch + 1 < SEQ / 64) {
            prefetch_kv(ch + 1, (ch + 1) & 1);
            if (tid < 64) msk[(ch + 1) & 1][tid] = mask[b * SEQ + (ch + 1) * 64 + tid];
            CP_WAIT1();
        } else {
            CP_WAIT0();
        }
        __syncthreads();

        const uint32_t base = sb + (ch & 1) * AT_STAGE;
        const int* mk = msk[ch & 1];

        float sacc[8][4];
#pragma unroll
        for (int nj = 0; nj < 8; nj++)
#pragma unroll
            for (int c = 0; c < 4; c++) sacc[nj][c] = 0.0f;

#pragma unroll
        for (int ks = 0; ks < 4; ks++) {
            const uint32_t co = (uint32_t)(((ks * 2 + kch) ^ rm8) << 4);
            uint32_t kf[4][4];
#pragma unroll
            for (int np = 0; np < 4; np++) {
                const int nrow = np * 16 + knloc;
                ldsm_x4(kf[np][0], kf[np][1], kf[np][2], kf[np][3],
                        base + AT_K + nrow * 128 + co);
            }
#pragma unroll
            for (int np = 0; np < 4; np++) {
                mma_fp16(sacc[np * 2],     qf[ks], kf[np][0], kf[np][1]);
                mma_fp16(sacc[np * 2 + 1], qf[ks], kf[np][2], kf[np][3]);
            }
        }

#pragma unroll
        for (int nj = 0; nj < 8; nj++) {
            const int ki = nj * 8 + c0i;
            if (mk[ki] == 0)     { sacc[nj][0] = -1e9f; sacc[nj][2] = -1e9f; }
            if (mk[ki + 1] == 0) { sacc[nj][1] = -1e9f; sacc[nj][3] = -1e9f; }
        }
        float m0 = -1e30f, m1 = -1e30f;
#pragma unroll
        for (int nj = 0; nj < 8; nj++) {
            m0 = fmaxf(m0, fmaxf(sacc[nj][0], sacc[nj][1]));
            m1 = fmaxf(m1, fmaxf(sacc[nj][2], sacc[nj][3]));
        }
        m0 = fmaxf(m0, __shfl_xor_sync(0xffffffffu, m0, 1));
        m0 = fmaxf(m0, __shfl_xor_sync(0xffffffffu, m0, 2));
        m1 = fmaxf(m1, __shfl_xor_sync(0xffffffffu, m1, 1));
        m1 = fmaxf(m1, __shfl_xor_sync(0xffffffffu, m1, 2));
        const float mn0 = fmaxf(mr0, m0), mn1 = fmaxf(mr1, m1);
        const float al0 = ex2f(mr0 - mn0), al1 = ex2f(mr1 - mn1);
        mr0 = mn0; mr1 = mn1;

        float rs0 = 0.0f, rs1 = 0.0f;
        uint32_t phi[8][2], plo[8][2];
#pragma unroll
        for (int nj = 0; nj < 8; nj++) {
            const float p0 = ex2f(sacc[nj][0] - mn0);
            const float p1 = ex2f(sacc[nj][1] - mn0);
            const float p2 = ex2f(sacc[nj][2] - mn1);
            const float p3 = ex2f(sacc[nj][3] - mn1);
            rs0 += p0 + p1; rs1 += p2 + p3;
            split2h(p0, p1, phi[nj][0], plo[nj][0]);
            split2h(p2, p3, phi[nj][1], plo[nj][1]);
        }
        rs0 += __shfl_xor_sync(0xffffffffu, rs0, 1);
        rs0 += __shfl_xor_sync(0xffffffffu, rs0, 2);
        rs1 += __shfl_xor_sync(0xffffffffu, rs1, 1);
        rs1 += __shfl_xor_sync(0xffffffffu, rs1, 2);
        lr0 = lr0 * al0 + rs0;
        lr1 = lr1 * al1 + rs1;
#pragma unroll
        for (int nj = 0; nj < 8; nj++) {
            oacc[nj][0] *= al0; oacc[nj][1] *= al0;
            oacc[nj][2] *= al1; oacc[nj][3] *= al1;
        }

#pragma unroll
        for (int kt = 0; kt < 4; kt++) {
            uint32_t pah[4] = { phi[2 * kt][0], phi[2 * kt][1],
                                phi[2 * kt + 1][0], phi[2 * kt + 1][1] };
            uint32_t pal[4] = { plo[2 * kt][0], plo[2 * kt][1],
                                plo[2 * kt + 1][0], plo[2 * kt + 1][1] };
            const int vrow = kt * 16 + vrow_base;
            uint32_t vf[4][4];
#pragma unroll
            for (int np = 0; np < 4; np++) {
                const uint32_t co = (uint32_t)(((np * 2 + vch) ^ rm8) << 4);
                ldsm_x4_t(vf[np][0], vf[np][1], vf[np][2], vf[np][3],
                          base + AT_V + vrow * 128 + co);
            }
#pragma unroll
            for (int np = 0; np < 4; np++) {
                mma_fp16(oacc[np * 2],     pah, vf[np][0], vf[np][1]);
                mma_fp16(oacc[np * 2 + 1], pah, vf[np][2], vf[np][3]);
            }
#pragma unroll
            for (int np = 0; np < 4; np++) {
                mma_fp16(oacc[np * 2],     pal, vf[np][0], vf[np][1]);
                mma_fp16(oacc[np * 2 + 1], pal, vf[np][2], vf[np][3]);
            }
        }
        __syncthreads();
    }

    const float inv0 = 1.0f / lr0, inv1 = 1.0f / lr1;
    const int s0 = q0 + wid * 16 + (lane >> 2);
#pragma unroll
    for (int nj = 0; nj < 8; nj++) {
        const int d = nj * 8 + c0i;
#pragma unroll
        for (int half = 0; half < 2; half++) {
            const int s = s0 + half * 8;
            const float v0 = oacc[nj][half * 2]     * (half ? inv1 : inv0);
            const float v1 = oacc[nj][half * 2 + 1] * (half ? inv1 : inv0);
            const size_t oi = (size_t)(b * SEQ + s) * DMODEL + h * DK + d;
            uint32_t hp, lp;
            split2h(v0, v1, hp, lp);
            *(uint32_t*)(Oh + oi) = hp;
            *(uint32_t*)(Ol + oi) = lp;
        }
    }
}

// ---------------------------------------------------------------------------
// Launch
// ---------------------------------------------------------------------------
extern "C" void kernel_launch(void* const* d_in, const int* in_sizes, int n_in,
                              void* d_out, int out_size)
{
    const float* query = (const float*)d_in[0];
    const float* key   = (const float*)d_in[1];
    const float* value = (const float*)d_in[2];
    const int*   mask  = (const int*)  d_in[3];
    const float* Wq    = (const float*)d_in[4];
    const float* bq    = (const float*)d_in[5];
    const float* Wk    = (const float*)d_in[6];
    const float* bk    = (const float*)d_in[7];
    const float* Wv    = (const float*)d_in[8];
    const float* bv    = (const float*)d_in[9];
    const float* Wo    = (const float*)d_in[10];
    const float* bo    = (const float*)d_in[11];

    __half *q16, *k16, *v16, *ah, *al, *w16, *oh, *ol;
    cudaGetSymbolAddress((void**)&q16, g_q16);
    cudaGetSymbolAddress((void**)&k16, g_k16);
    cudaGetSymbolAddress((void**)&v16, g_v16);
    cudaGetSymbolAddress((void**)&ah, g_ah);
    cudaGetSymbolAddress((void**)&al, g_al);
    cudaGetSymbolAddress((void**)&w16, g_w16);
    cudaGetSymbolAddress((void**)&oh, g_oh);
    cudaGetSymbolAddress((void**)&ol, g_ol);

    cudaFuncSetAttribute(tc_gemm_kernel,
                         cudaFuncAttributeMaxDynamicSharedMemorySize, GEMM_SMEM);
    cudaFuncSetAttribute(attn_mma_kernel,
                         cudaFuncAttributeMaxDynamicSharedMemorySize, ATTN_SMEM);

    const int a4 = NA_ / 4, w4 = NW_ / 4;

    cvt_split_h_kernel<<<dim3((a4 + 255) / 256, 3), 256>>>(
        query, key, value,
        ah, ah + NA_, ah + 2 * NA_,
        al, al + NA_, al + 2 * NA_, a4);
    cvt_h_kernel<<<dim3((w4 + 255) / 256, 4), 256>>>(
        Wq, Wk, Wv, Wo,
        w16, w16 + NW_, w16 + 2 * NW_, w16 + 3 * NW_, w4);

    const float qscale = 0.125f * 1.4426950408889634f;

    tc_gemm_kernel<<<dim3(DMODEL / 256, MTOT / 128, 3), 256, GEMM_SMEM>>>(
        ah, al, w16, bq, bk, bv, nullptr,
        q16, k16, v16, qscale, 1);

    attn_mma_kernel<<<dim3(SEQ / 64, BATCH * HNUM), 128, ATTN_SMEM>>>(
        q16, k16, v16, mask, oh, ol);

    tc_gemm_kernel<<<dim3(DMODEL / 256, MTOT / 128, 1), 256, GEMM_SMEM>>>(
        oh, ol, w16 + 3 * NW_, bo, nullptr, nullptr, (float*)d_out,
        nullptr, nullptr, nullptr, 1.0f, 0);
}

// round 13
// speedup vs baseline: 1.7518x; 1.1237x over previous
#include <cuda_runtime.h>
#include <cuda_bf16.h>
#include <cuda_fp16.h>
#include <cstdint>
#include <math.h>

#define HNUM   12
#define DMODEL 768
#define BATCH  2
#define SEQ    2048
#define DK     64
#define MTOT   (BATCH * SEQ)          // 4096
#define NA_ (MTOT * DMODEL)           // 3145728
#define NW_ (DMODEL * DMODEL)         // 589824

// ---------------------------------------------------------------------------
// Scratch: all fp16. Activations/attn-out 2-term (hi+lo); weights single.
// ---------------------------------------------------------------------------
__device__ __half g_q16[BATCH * HNUM * SEQ * DK];
__device__ __half g_k16[BATCH * HNUM * SEQ * DK];
__device__ __half g_v16[BATCH * HNUM * SEQ * DK];

__device__ __half g_ah[3 * NA_];
__device__ __half g_al[3 * NA_];
__device__ __half g_w16[4 * NW_];
__device__ __half g_oh[NA_];
__device__ __half g_ol[NA_];

// ---------------------------------------------------------------------------
// Helpers
// ---------------------------------------------------------------------------
__device__ __forceinline__ uint32_t smem_to_u32(const void* p) {
    uint32_t a;
    asm("{ .reg .u64 t; cvta.to.shared.u64 t, %1; cvt.u32.u64 %0, t; }"
        : "=r"(a) : "l"(p));
    return a;
}
__device__ __forceinline__ void cp16(uint32_t s, const void* g) {
    asm volatile("cp.async.cg.shared.global [%0], [%1], 16;" :: "r"(s), "l"(g));
}
#define CP_COMMIT() asm volatile("cp.async.commit_group;" ::: "memory")
#define CP_WAIT1()  asm volatile("cp.async.wait_group 1;" ::: "memory")
#define CP_WAIT0()  asm volatile("cp.async.wait_group 0;" ::: "memory")

__device__ __forceinline__ void ldsm_x4(uint32_t& r0, uint32_t& r1,
                                        uint32_t& r2, uint32_t& r3, uint32_t addr) {
    asm volatile("ldmatrix.sync.aligned.m8n8.x4.shared.b16 {%0,%1,%2,%3}, [%4];"
                 : "=r"(r0), "=r"(r1), "=r"(r2), "=r"(r3) : "r"(addr));
}
__device__ __forceinline__ void ldsm_x4_t(uint32_t& r0, uint32_t& r1,
                                          uint32_t& r2, uint32_t& r3, uint32_t addr) {
    asm volatile("ldmatrix.sync.aligned.m8n8.x4.trans.shared.b16 {%0,%1,%2,%3}, [%4];"
                 : "=r"(r0), "=r"(r1), "=r"(r2), "=r"(r3) : "r"(addr));
}
__device__ __forceinline__ void mma_fp16(float* c, const uint32_t* a,
                                         uint32_t b0, uint32_t b1) {
    asm volatile("mma.sync.aligned.m16n8k16.row.col.f32.f16.f16.f32 "
                 "{%0,%1,%2,%3}, {%4,%5,%6,%7}, {%8,%9}, {%0,%1,%2,%3};"
                 : "+f"(c[0]), "+f"(c[1]), "+f"(c[2]), "+f"(c[3])
                 : "r"(a[0]), "r"(a[1]), "r"(a[2]), "r"(a[3]), "r"(b0), "r"(b1));
}
__device__ __forceinline__ float ex2f(float x) {
    float y;
    asm("ex2.approx.ftz.f32 %0, %1;" : "=f"(y) : "f"(x));
    return y;
}
// fp16 hi/lo split of a pair -> packed hi, packed lo
__device__ __forceinline__ void split2h(float v0, float v1,
                                        uint32_t& hp, uint32_t& lp) {
    __half2 h = __floats2half2_rn(v0, v1);
    hp = *(uint32_t*)&h;
    const float h0 = __half2float(__low2half(h));
    const float h1 = __half2float(__high2half(h));
    __half2 l = __floats2half2_rn(v0 - h0, v1 - h1);
    lp = *(uint32_t*)&l;
}
__device__ __forceinline__ uint32_t pack2h(float v0, float v1) {
    __half2 h = __floats2half2_rn(v0, v1);
    return *(uint32_t*)&h;
}

// ---------------------------------------------------------------------------
// fp32 -> fp16 hi/lo split (activations); blockIdx.y selects tensor
// ---------------------------------------------------------------------------
__global__ void __launch_bounds__(256) cvt_split_h_kernel(
    const float* x0, const float* x1, const float* x2,
    __half* h0p, __half* h1p, __half* h2p,
    __half* l0p, __half* l1p, __half* l2p, int n4)
{
    const int z = blockIdx.y;
    const float* x = (z == 0) ? x0 : (z == 1) ? x1 : x2;
    __half* hi = (z == 0) ? h0p : (z == 1) ? h1p : h2p;
    __half* lo = (z == 0) ? l0p : (z == 1) ? l1p : l2p;
    int i = blockIdx.x * 256 + threadIdx.x;
    if (i >= n4) return;
    float4 v = ((const float4*)x)[i];
    uint32_t hp0, lp0, hp1, lp1;
    split2h(v.x, v.y, hp0, lp0);
    split2h(v.z, v.w, hp1, lp1);
    ((uint32_t*)hi)[2 * i]     = hp0;
    ((uint32_t*)hi)[2 * i + 1] = hp1;
    ((uint32_t*)lo)[2 * i]     = lp0;
    ((uint32_t*)lo)[2 * i + 1] = lp1;
}

// fp32 -> single fp16 (weights); blockIdx.y selects tensor
__global__ void __launch_bounds__(256) cvt_h_kernel(
    const float* x0, const float* x1, const float* x2, const float* x3,
    __half* o0, __half* o1, __half* o2, __half* o3, int n4)
{
    const int z = blockIdx.y;
    const float* x = (z == 0) ? x0 : (z == 1) ? x1 : (z == 2) ? x2 : x3;
    __half* o = (z == 0) ? o0 : (z == 1) ? o1 : (z == 2) ? o2 : o3;
    int i = blockIdx.x * 256 + threadIdx.x;
    if (i >= n4) return;
    float4 v = ((const float4*)x)[i];
    __half2 a = __floats2half2_rn(v.x, v.y);
    __half2 b = __floats2half2_rn(v.z, v.w);
    ((uint32_t*)o)[2 * i]     = *(uint32_t*)&a;
    ((uint32_t*)o)[2 * i + 1] = *(uint32_t*)&b;
}

// ---------------------------------------------------------------------------
// HMMA GEMM (fp16, A 2-term x W 1-term = 2 mmas), cp.async double-buffered.
// CTA tile 128x256, 8 warps as 2(M)x4(N), warp tile 64x64, K-chunk 64.
// ---------------------------------------------------------------------------
#define OFF_AH 0u
#define OFF_AL 16384u
#define OFF_B  32768u
#define STAGE_SZ 65536u
#define GEMM_SMEM 131072

__global__ void __launch_bounds__(256, 1) tc_gemm_kernel(
    const __half* Abase_h, const __half* Abase_l, const __half* Wbase,
    const float* bias0, const float* bias1, const float* bias2,
    float* outf,
    __half* o0h, __half* o1h, __half* o2h,
    float scale0, int qkv_mode)
{
    extern __shared__ __align__(16) char smem[];
    const uint32_t sb = smem_to_u32(smem);
    const int tid  = threadIdx.x;
    const int lane = tid & 31;
    const int wid  = tid >> 5;
    const int wm   = wid & 1;
    const int wn   = wid >> 1;
    const int bm = blockIdx.y * 128;
    const int bn = blockIdx.x * 256;
    const int z  = blockIdx.z;

    const __half* Ah = Abase_h + (size_t)z * NA_;
    const __half* Al = Abase_l + (size_t)z * NA_;
    const __half* W  = Wbase   + (size_t)z * NW_;
    const float* bias = (z == 0) ? bias0 : (z == 1) ? bias1 : bias2;
    const float scale = (z == 0) ? scale0 : 1.0f;
    __half* outh = (z == 0) ? o0h : (z == 1) ? o1h : o2h;

    float acc[4][8][4];
#pragma unroll
    for (int mi = 0; mi < 4; mi++)
#pragma unroll
        for (int nj = 0; nj < 8; nj++)
#pragma unroll
            for (int c = 0; c < 4; c++) acc[mi][nj][c] = 0.0f;

    const int a_row   = wm * 64 + (lane & 15);
    const int a_chalf = lane >> 4;
    const int b_nloc  = wn * 64 + (lane & 7) + ((lane >> 4) << 3);
    const int b_chalf = (lane >> 3) & 1;
    const int rm8     = lane & 7;

    auto prefetch = [&](int ch, int st) {
        const uint32_t base = sb + st * STAGE_SZ;
        const int k0 = ch * 64;
#pragma unroll
        for (int i = tid; i < 1024; i += 256) {
            const int r = i >> 3, c = i & 7;
            const uint32_t so = (uint32_t)(r * 128 + ((c ^ (r & 7)) << 4));
            const size_t ga = (size_t)(bm + r) * DMODEL + k0 + c * 8;
            cp16(base + OFF_AH + so, Ah + ga);
            cp16(base + OFF_AL + so, Al + ga);
        }
#pragma unroll
        for (int i = tid; i < 2048; i += 256) {
            const int r = i >> 3, c = i & 7;
            const uint32_t so = (uint32_t)(r * 128 + ((c ^ (r & 7)) << 4));
            cp16(base + OFF_B + so, W + (size_t)(bn + r) * DMODEL + k0 + c * 8);
        }
        CP_COMMIT();
    };

    prefetch(0, 0);
    for (int ch = 0; ch < DMODEL / 64; ch++) {
        if (ch + 1 < DMODEL / 64) { prefetch(ch + 1, (ch + 1) & 1); CP_WAIT1(); }
        else                      { CP_WAIT0(); }
        __syncthreads();

        const uint32_t base = sb + (ch & 1) * STAGE_SZ;
#pragma unroll
        for (int ks = 0; ks < 4; ks++) {
            uint32_t ahf[4][4], alf[4][4];
            const uint32_t aco = (uint32_t)(((ks * 2 + a_chalf) ^ rm8) << 4);
#pragma unroll
            for (int mi = 0; mi < 4; mi++) {
                const int row = a_row + mi * 16;
                ldsm_x4(ahf[mi][0], ahf[mi][1], ahf[mi][2], ahf[mi][3],
                        base + OFF_AH + row * 128 + aco);
                ldsm_x4(alf[mi][0], alf[mi][1], alf[mi][2], alf[mi][3],
                        base + OFF_AL + row * 128 + aco);
            }
            const uint32_t bco = (uint32_t)(((ks * 2 + b_chalf) ^ rm8) << 4);
#pragma unroll
            for (int np = 0; np < 4; np++) {
                const int nrow = b_nloc + np * 16;
                uint32_t b0, b1, b2, b3;
                ldsm_x4(b0, b1, b2, b3, base + OFF_B + nrow * 128 + bco);
#pragma unroll
                for (int mi = 0; mi < 4; mi++) {
                    mma_fp16(acc[mi][np * 2],     ahf[mi], b0, b1);
                    mma_fp16(acc[mi][np * 2 + 1], ahf[mi], b2, b3);
                }
#pragma unroll
                for (int mi = 0; mi < 4; mi++) {
                    mma_fp16(acc[mi][np * 2],     alf[mi], b0, b1);
                    mma_fp16(acc[mi][np * 2 + 1], alf[mi], b2, b3);
                }
            }
        }
        __syncthreads();
    }

    const int erow = bm + wm * 64 + (lane >> 2);
    const int ecol = bn + wn * 64 + (lane & 3) * 2;
#pragma unroll
    for (int mi = 0; mi < 4; mi++) {
#pragma unroll
        for (int nj = 0; nj < 8; nj++) {
            const int gc = ecol + nj * 8;
            const float b0 = bias[gc], b1 = bias[gc + 1];
#pragma unroll
            for (int half = 0; half < 2; half++) {
                const int gr = erow + mi * 16 + half * 8;
                const float v0 = (acc[mi][nj][half * 2]     + b0) * scale;
                const float v1 = (acc[mi][nj][half * 2 + 1] + b1) * scale;
                if (!qkv_mode) {
                    *(float2*)(outf + (size_t)gr * DMODEL + gc) = make_float2(v0, v1);
                } else {
                    const int b = gr >> 11, s = gr & 2047;
                    const int h = gc >> 6,  d = gc & 63;
                    const size_t oi = (((size_t)b * HNUM + h) * SEQ + s) * DK + d;
                    *(uint32_t*)(outh + oi) = pack2h(v0, v1);
                }
            }
        }
    }
}

// ---------------------------------------------------------------------------
// MMA flash attention (fp16): Q,K,V,P all single fp16. 128-thread CTA,
// 128-key chunks (one softmax pass per 128 keys), 2-stage cp.async,
// 2 CTAs/SM. Output fp16 hi/lo for the final projection.
// ---------------------------------------------------------------------------
#define AT_K 0u
#define AT_V 16384u
#define AT_STAGE 32768u
#define ATTN_SMEM 65536

__global__ void __launch_bounds__(128, 2) attn_mma_kernel(
    const __half* __restrict__ Q, const __half* __restrict__ K,
    const __half* __restrict__ V, const int* __restrict__ mask,
    __half* __restrict__ Oh, __half* __restrict__ Ol)
{
    extern __shared__ __align__(16) char smem[];
    __shared__ int msk[2][128];
    const uint32_t sb = smem_to_u32(smem);
    const int tid = threadIdx.x, lane = tid & 31, wid = tid >> 5;
    const int bh = blockIdx.y, b = bh / HNUM, h = bh % HNUM;
    const int q0 = blockIdx.x * 64;
    const size_t hb = (size_t)bh * SEQ * DK;
    const int rm8 = lane & 7;

    // Stage Q tile (64 rows fp16, 8 KB) in stage-0 K area, pull fragments
    for (int i = tid; i < 512; i += 128) {
        const int r = i >> 3, c = i & 7;
        const uint32_t so = (uint32_t)(r * 128 + ((c ^ (r & 7)) << 4));
        *(uint4*)(smem + AT_K + so) =
            *(const uint4*)(Q + hb + (size_t)(q0 + r) * DK + c * 8);
    }
    __syncthreads();

    const int arow = wid * 16 + (lane & 15);
    const int ach  = lane >> 4;
    uint32_t qf[4][4];
#pragma unroll
    for (int ks = 0; ks < 4; ks++) {
        const uint32_t co = (uint32_t)(((ks * 2 + ach) ^ rm8) << 4);
        ldsm_x4(qf[ks][0], qf[ks][1], qf[ks][2], qf[ks][3],
                sb + AT_K + arow * 128 + co);
    }
    __syncthreads();

    float oacc[8][4];
#pragma unroll
    for (int nj = 0; nj < 8; nj++)
#pragma unroll
        for (int c = 0; c < 4; c++) oacc[nj][c] = 0.0f;
    float mr0 = -1e30f, mr1 = -1e30f, lr0 = 0.0f, lr1 = 0.0f;

    const int knloc = (lane & 7) + ((lane >> 4) << 3);
    const int kch   = (lane >> 3) & 1;
    const int vrow_base = (lane & 7) + (((lane >> 3) & 1) << 3);
    const int vch   = lane >> 4;
    const int c0i   = 2 * (lane & 3);

    auto prefetch_kv = [&](int ch, int st) {
        const uint32_t base = sb + st * AT_STAGE;
        const int j0 = ch * 128;
#pragma unroll
        for (int i = tid; i < 1024; i += 128) {
            const int r = i >> 3, c = i & 7;
            const uint32_t so = (uint32_t)(r * 128 + ((c ^ (r & 7)) << 4));
            const size_t g = hb + (size_t)(j0 + r) * DK + c * 8;
            cp16(base + AT_K + so, K + g);
            cp16(base + AT_V + so, V + g);
        }
        CP_COMMIT();
    };

    prefetch_kv(0, 0);
    if (tid < 128) msk[0][tid] = mask[b * SEQ + tid];
    for (int ch = 0; ch < SEQ / 128; ch++) {
        if (ch + 1 < SEQ / 128) {
            prefetch_kv(ch + 1, (ch + 1) & 1);
            msk[(ch + 1) & 1][tid] = mask[b * SEQ + (ch + 1) * 128 + tid];
            CP_WAIT1();
        } else {
            CP_WAIT0();
        }
        __syncthreads();

        const uint32_t base = sb + (ch & 1) * AT_STAGE;
        const int* mk = msk[ch & 1];

        // S = Q K^T over 128 keys (16 n-tiles)
        float sacc[16][4];
#pragma unroll
        for (int nj = 0; nj < 16; nj++)
#pragma unroll
            for (int c = 0; c < 4; c++) sacc[nj][c] = 0.0f;

#pragma unroll
        for (int ks = 0; ks < 4; ks++) {
            const uint32_t co = (uint32_t)(((ks * 2 + kch) ^ rm8) << 4);
#pragma unroll
            for (int np = 0; np < 8; np++) {
                const int nrow = np * 16 + knloc;
                uint32_t k0, k1, k2, k3;
                ldsm_x4(k0, k1, k2, k3, base + AT_K + nrow * 128 + co);
                mma_fp16(sacc[np * 2],     qf[ks], k0, k1);
                mma_fp16(sacc[np * 2 + 1], qf[ks], k2, k3);
            }
        }

        // Mask + online softmax (base-2)
#pragma unroll
        for (int nj = 0; nj < 16; nj++) {
            const int ki = nj * 8 + c0i;
            if (mk[ki] == 0)     { sacc[nj][0] = -1e9f; sacc[nj][2] = -1e9f; }
            if (mk[ki + 1] == 0) { sacc[nj][1] = -1e9f; sacc[nj][3] = -1e9f; }
        }
        float m0 = -1e30f, m1 = -1e30f;
#pragma unroll
        for (int nj = 0; nj < 16; nj++) {
            m0 = fmaxf(m0, fmaxf(sacc[nj][0], sacc[nj][1]));
            m1 = fmaxf(m1, fmaxf(sacc[nj][2], sacc[nj][3]));
        }
        m0 = fmaxf(m0, __shfl_xor_sync(0xffffffffu, m0, 1));
        m0 = fmaxf(m0, __shfl_xor_sync(0xffffffffu, m0, 2));
        m1 = fmaxf(m1, __shfl_xor_sync(0xffffffffu, m1, 1));
        m1 = fmaxf(m1, __shfl_xor_sync(0xffffffffu, m1, 2));
        const float mn0 = fmaxf(mr0, m0), mn1 = fmaxf(mr1, m1);
        const float al0 = ex2f(mr0 - mn0), al1 = ex2f(mr1 - mn1);
        mr0 = mn0; mr1 = mn1;

        float rs0 = 0.0f, rs1 = 0.0f;
        uint32_t phi[16][2];
#pragma unroll
        for (int nj = 0; nj < 16; nj++) {
            const float p0 = ex2f(sacc[nj][0] - mn0);
            const float p1 = ex2f(sacc[nj][1] - mn0);
            const float p2 = ex2f(sacc[nj][2] - mn1);
            const float p3 = ex2f(sacc[nj][3] - mn1);
            rs0 += p0 + p1; rs1 += p2 + p3;
            phi[nj][0] = pack2h(p0, p1);
            phi[nj][1] = pack2h(p2, p3);
        }
        rs0 += __shfl_xor_sync(0xffffffffu, rs0, 1);
        rs0 += __shfl_xor_sync(0xffffffffu, rs0, 2);
        rs1 += __shfl_xor_sync(0xffffffffu, rs1, 1);
        rs1 += __shfl_xor_sync(0xffffffffu, rs1, 2);
        lr0 = lr0 * al0 + rs0;
        lr1 = lr1 * al1 + rs1;
#pragma unroll
        for (int nj = 0; nj < 8; nj++) {
            oacc[nj][0] *= al0; oacc[nj][1] *= al0;
            oacc[nj][2] *= al1; oacc[nj][3] *= al1;
        }

        // O += P @ V over 128 keys (8 k-tiles, single fp16 P)
#pragma unroll
        for (int kt = 0; kt < 8; kt++) {
            uint32_t pah[4] = { phi[2 * kt][0], phi[2 * kt][1],
                                phi[2 * kt + 1][0], phi[2 * kt + 1][1] };
            const int vrow = kt * 16 + vrow_base;
#pragma unroll
            for (int np = 0; np < 4; np++) {
                const uint32_t co = (uint32_t)(((np * 2 + vch) ^ rm8) << 4);
                uint32_t v0, v1, v2, v3;
                ldsm_x4_t(v0, v1, v2, v3, base + AT_V + vrow * 128 + co);
                mma_fp16(oacc[np * 2],     pah, v0, v1);
                mma_fp16(oacc[np * 2 + 1], pah, v2, v3);
            }
        }
        __syncthreads();
    }

    const float inv0 = 1.0f / lr0, inv1 = 1.0f / lr1;
    const int s0 = q0 + wid * 16 + (lane >> 2);
#pragma unroll
    for (int nj = 0; nj < 8; nj++) {
        const int d = nj * 8 + c0i;
#pragma unroll
        for (int half = 0; half < 2; half++) {
            const int s = s0 + half * 8;
            const float v0 = oacc[nj][half * 2]     * (half ? inv1 : inv0);
            const float v1 = oacc[nj][half * 2 + 1] * (half ? inv1 : inv0);
            const size_t oi = (size_t)(b * SEQ + s) * DMODEL + h * DK + d;
            uint32_t hp, lp;
            split2h(v0, v1, hp, lp);
            *(uint32_t*)(Oh + oi) = hp;
            *(uint32_t*)(Ol + oi) = lp;
        }
    }
}

// ---------------------------------------------------------------------------
// Launch
// ---------------------------------------------------------------------------
extern "C" void kernel_launch(void* const* d_in, const int* in_sizes, int n_in,
                              void* d_out, int out_size)
{
    const float* query = (const float*)d_in[0];
    const float* key   = (const float*)d_in[1];
    const float* value = (const float*)d_in[2];
    const int*   mask  = (const int*)  d_in[3];
    const float* Wq    = (const float*)d_in[4];
    const float* bq    = (const float*)d_in[5];
    const float* Wk    = (const float*)d_in[6];
    const float* bk    = (const float*)d_in[7];
    const float* Wv    = (const float*)d_in[8];
    const float* bv    = (const float*)d_in[9];
    const float* Wo    = (const float*)d_in[10];
    const float* bo    = (const float*)d_in[11];

    __half *q16, *k16, *v16, *ah, *al, *w16, *oh, *ol;
    cudaGetSymbolAddress((void**)&q16, g_q16);
    cudaGetSymbolAddress((void**)&k16, g_k16);
    cudaGetSymbolAddress((void**)&v16, g_v16);
    cudaGetSymbolAddress((void**)&ah, g_ah);
    cudaGetSymbolAddress((void**)&al, g_al);
    cudaGetSymbolAddress((void**)&w16, g_w16);
    cudaGetSymbolAddress((void**)&oh, g_oh);
    cudaGetSymbolAddress((void**)&ol, g_ol);

    cudaFuncSetAttribute(tc_gemm_kernel,
                         cudaFuncAttributeMaxDynamicSharedMemorySize, GEMM_SMEM);
    cudaFuncSetAttribute(attn_mma_kernel,
                         cudaFuncAttributeMaxDynamicSharedMemorySize, ATTN_SMEM);

    const int a4 = NA_ / 4, w4 = NW_ / 4;

    cvt_split_h_kernel<<<dim3((a4 + 255) / 256, 3), 256>>>(
        query, key, value,
        ah, ah + NA_, ah + 2 * NA_,
        al, al + NA_, al + 2 * NA_, a4);
    cvt_h_kernel<<<dim3((w4 + 255) / 256, 4), 256>>>(
        Wq, Wk, Wv, Wo,
        w16, w16 + NW_, w16 + 2 * NW_, w16 + 3 * NW_, w4);

    const float qscale = 0.125f * 1.4426950408889634f;

    tc_gemm_kernel<<<dim3(DMODEL / 256, MTOT / 128, 3), 256, GEMM_SMEM>>>(
        ah, al, w16, bq, bk, bv, nullptr,
        q16, k16, v16, qscale, 1);

    attn_mma_kernel<<<dim3(SEQ / 64, BATCH * HNUM), 128, ATTN_SMEM>>>(
        q16, k16, v16, mask, oh, ol);

    tc_gemm_kernel<<<dim3(DMODEL / 256, MTOT / 128, 1), 256, GEMM_SMEM>>>(
        oh, ol, w16 + 3 * NW_, bo, nullptr, nullptr, (float*)d_out,
        nullptr, nullptr, nullptr, 1.0f, 0);
}

// round 14
// speedup vs baseline: 1.8137x; 1.0353x over previous
#include <cuda_runtime.h>
#include <cuda_bf16.h>
#include <cuda_fp16.h>
#include <cstdint>
#include <math.h>

#define HNUM   12
#define DMODEL 768
#define BATCH  2
#define SEQ    2048
#define DK     64
#define MTOT   (BATCH * SEQ)          // 4096
#define NA_ (MTOT * DMODEL)           // 3145728
#define NW_ (DMODEL * DMODEL)         // 589824

// ---------------------------------------------------------------------------
// Scratch: all fp16. Input activations 2-term; weights & attn-out single.
// ---------------------------------------------------------------------------
__device__ __half g_q16[BATCH * HNUM * SEQ * DK];
__device__ __half g_k16[BATCH * HNUM * SEQ * DK];
__device__ __half g_v16[BATCH * HNUM * SEQ * DK];

__device__ __half g_ah[3 * NA_];
__device__ __half g_al[3 * NA_];
__device__ __half g_w16[4 * NW_];
__device__ __half g_oh[NA_];

// ---------------------------------------------------------------------------
// Helpers
// ---------------------------------------------------------------------------
__device__ __forceinline__ uint32_t smem_to_u32(const void* p) {
    uint32_t a;
    asm("{ .reg .u64 t; cvta.to.shared.u64 t, %1; cvt.u32.u64 %0, t; }"
        : "=r"(a) : "l"(p));
    return a;
}
__device__ __forceinline__ void cp16(uint32_t s, const void* g) {
    asm volatile("cp.async.cg.shared.global [%0], [%1], 16;" :: "r"(s), "l"(g));
}
#define CP_COMMIT() asm volatile("cp.async.commit_group;" ::: "memory")
#define CP_WAIT1()  asm volatile("cp.async.wait_group 1;" ::: "memory")
#define CP_WAIT0()  asm volatile("cp.async.wait_group 0;" ::: "memory")

__device__ __forceinline__ void ldsm_x4(uint32_t& r0, uint32_t& r1,
                                        uint32_t& r2, uint32_t& r3, uint32_t addr) {
    asm volatile("ldmatrix.sync.aligned.m8n8.x4.shared.b16 {%0,%1,%2,%3}, [%4];"
                 : "=r"(r0), "=r"(r1), "=r"(r2), "=r"(r3) : "r"(addr));
}
__device__ __forceinline__ void ldsm_x4_t(uint32_t& r0, uint32_t& r1,
                                          uint32_t& r2, uint32_t& r3, uint32_t addr) {
    asm volatile("ldmatrix.sync.aligned.m8n8.x4.trans.shared.b16 {%0,%1,%2,%3}, [%4];"
                 : "=r"(r0), "=r"(r1), "=r"(r2), "=r"(r3) : "r"(addr));
}
__device__ __forceinline__ void mma_fp16(float* c, const uint32_t* a,
                                         uint32_t b0, uint32_t b1) {
    asm volatile("mma.sync.aligned.m16n8k16.row.col.f32.f16.f16.f32 "
                 "{%0,%1,%2,%3}, {%4,%5,%6,%7}, {%8,%9}, {%0,%1,%2,%3};"
                 : "+f"(c[0]), "+f"(c[1]), "+f"(c[2]), "+f"(c[3])
                 : "r"(a[0]), "r"(a[1]), "r"(a[2]), "r"(a[3]), "r"(b0), "r"(b1));
}
__device__ __forceinline__ float ex2f(float x) {
    float y;
    asm("ex2.approx.ftz.f32 %0, %1;" : "=f"(y) : "f"(x));
    return y;
}
// packed fp16x2 exp2
__device__ __forceinline__ uint32_t ex2h2(uint32_t x) {
    uint32_t y;
    asm("ex2.approx.f16x2 %0, %1;" : "=r"(y) : "r"(x));
    return y;
}
__device__ __forceinline__ uint32_t pack2h(float v0, float v1) {
    __half2 h = __floats2half2_rn(v0, v1);
    return *(uint32_t*)&h;
}
// fp16 hi/lo split of a pair
__device__ __forceinline__ void split2h(float v0, float v1,
                                        uint32_t& hp, uint32_t& lp) {
    __half2 h = __floats2half2_rn(v0, v1);
    hp = *(uint32_t*)&h;
    const float h0 = __half2float(__low2half(h));
    const float h1 = __half2float(__high2half(h));
    __half2 l = __floats2half2_rn(v0 - h0, v1 - h1);
    lp = *(uint32_t*)&l;
}

// ---------------------------------------------------------------------------
// fp32 -> fp16 hi/lo split (activations); blockIdx.y selects tensor
// ---------------------------------------------------------------------------
__global__ void __launch_bounds__(256) cvt_split_h_kernel(
    const float* x0, const float* x1, const float* x2,
    __half* h0p, __half* h1p, __half* h2p,
    __half* l0p, __half* l1p, __half* l2p, int n4)
{
    const int z = blockIdx.y;
    const float* x = (z == 0) ? x0 : (z == 1) ? x1 : x2;
    __half* hi = (z == 0) ? h0p : (z == 1) ? h1p : h2p;
    __half* lo = (z == 0) ? l0p : (z == 1) ? l1p : l2p;
    int i = blockIdx.x * 256 + threadIdx.x;
    if (i >= n4) return;
    float4 v = ((const float4*)x)[i];
    uint32_t hp0, lp0, hp1, lp1;
    split2h(v.x, v.y, hp0, lp0);
    split2h(v.z, v.w, hp1, lp1);
    ((uint32_t*)hi)[2 * i]     = hp0;
    ((uint32_t*)hi)[2 * i + 1] = hp1;
    ((uint32_t*)lo)[2 * i]     = lp0;
    ((uint32_t*)lo)[2 * i + 1] = lp1;
}

// fp32 -> single fp16 (weights); blockIdx.y selects tensor
__global__ void __launch_bounds__(256) cvt_h_kernel(
    const float* x0, const float* x1, const float* x2, const float* x3,
    __half* o0, __half* o1, __half* o2, __half* o3, int n4)
{
    const int z = blockIdx.y;
    const float* x = (z == 0) ? x0 : (z == 1) ? x1 : (z == 2) ? x2 : x3;
    __half* o = (z == 0) ? o0 : (z == 1) ? o1 : (z == 2) ? o2 : o3;
    int i = blockIdx.x * 256 + threadIdx.x;
    if (i >= n4) return;
    float4 v = ((const float4*)x)[i];
    ((uint32_t*)o)[2 * i]     = pack2h(v.x, v.y);
    ((uint32_t*)o)[2 * i + 1] = pack2h(v.z, v.w);
}

// ---------------------------------------------------------------------------
// HMMA GEMM (fp16): A (1 or 2 term) x W (1 term). cp.async double-buffered.
// CTA tile 128x256, 8 warps as 2(M)x4(N), warp tile 64x64, K-chunk 64.
// ---------------------------------------------------------------------------
#define OFF_AH 0u
#define OFF_AL 16384u
#define OFF_B  32768u
#define STAGE_SZ 65536u
#define GEMM_SMEM 131072

__global__ void __launch_bounds__(256, 1) tc_gemm_kernel(
    const __half* Abase_h, const __half* Abase_l, const __half* Wbase,
    const float* bias0, const float* bias1, const float* bias2,
    float* outf,
    __half* o0h, __half* o1h, __half* o2h,
    float scale0, int qkv_mode, int a_two_term)
{
    extern __shared__ __align__(16) char smem[];
    const uint32_t sb = smem_to_u32(smem);
    const int tid  = threadIdx.x;
    const int lane = tid & 31;
    const int wid  = tid >> 5;
    const int wm   = wid & 1;
    const int wn   = wid >> 1;
    const int bm = blockIdx.y * 128;
    const int bn = blockIdx.x * 256;
    const int z  = blockIdx.z;

    const __half* Ah = Abase_h + (size_t)z * NA_;
    const __half* Al = Abase_l ? (Abase_l + (size_t)z * NA_) : nullptr;
    const __half* W  = Wbase   + (size_t)z * NW_;
    const float* bias = (z == 0) ? bias0 : (z == 1) ? bias1 : bias2;
    const float scale = (z == 0) ? scale0 : 1.0f;
    __half* outh = (z == 0) ? o0h : (z == 1) ? o1h : o2h;

    float acc[4][8][4];
#pragma unroll
    for (int mi = 0; mi < 4; mi++)
#pragma unroll
        for (int nj = 0; nj < 8; nj++)
#pragma unroll
            for (int c = 0; c < 4; c++) acc[mi][nj][c] = 0.0f;

    const int a_row   = wm * 64 + (lane & 15);
    const int a_chalf = lane >> 4;
    const int b_nloc  = wn * 64 + (lane & 7) + ((lane >> 4) << 3);
    const int b_chalf = (lane >> 3) & 1;
    const int rm8     = lane & 7;

    auto prefetch = [&](int ch, int st) {
        const uint32_t base = sb + st * STAGE_SZ;
        const int k0 = ch * 64;
#pragma unroll
        for (int i = tid; i < 1024; i += 256) {
            const int r = i >> 3, c = i & 7;
            const uint32_t so = (uint32_t)(r * 128 + ((c ^ (r & 7)) << 4));
            const size_t ga = (size_t)(bm + r) * DMODEL + k0 + c * 8;
            cp16(base + OFF_AH + so, Ah + ga);
            if (a_two_term) cp16(base + OFF_AL + so, Al + ga);
        }
#pragma unroll
        for (int i = tid; i < 2048; i += 256) {
            const int r = i >> 3, c = i & 7;
            const uint32_t so = (uint32_t)(r * 128 + ((c ^ (r & 7)) << 4));
            cp16(base + OFF_B + so, W + (size_t)(bn + r) * DMODEL + k0 + c * 8);
        }
        CP_COMMIT();
    };

    prefetch(0, 0);
    for (int ch = 0; ch < DMODEL / 64; ch++) {
        if (ch + 1 < DMODEL / 64) { prefetch(ch + 1, (ch + 1) & 1); CP_WAIT1(); }
        else                      { CP_WAIT0(); }
        __syncthreads();

        const uint32_t base = sb + (ch & 1) * STAGE_SZ;
#pragma unroll
        for (int ks = 0; ks < 4; ks++) {
            uint32_t ahf[4][4], alf[4][4];
            const uint32_t aco = (uint32_t)(((ks * 2 + a_chalf) ^ rm8) << 4);
#pragma unroll
            for (int mi = 0; mi < 4; mi++) {
                const int row = a_row + mi * 16;
                ldsm_x4(ahf[mi][0], ahf[mi][1], ahf[mi][2], ahf[mi][3],
                        base + OFF_AH + row * 128 + aco);
                if (a_two_term)
                    ldsm_x4(alf[mi][0], alf[mi][1], alf[mi][2], alf[mi][3],
                            base + OFF_AL + row * 128 + aco);
            }
            const uint32_t bco = (uint32_t)(((ks * 2 + b_chalf) ^ rm8) << 4);
#pragma unroll
            for (int np = 0; np < 4; np++) {
                const int nrow = b_nloc + np * 16;
                uint32_t b0, b1, b2, b3;
                ldsm_x4(b0, b1, b2, b3, base + OFF_B + nrow * 128 + bco);
#pragma unroll
                for (int mi = 0; mi < 4; mi++) {
                    mma_fp16(acc[mi][np * 2],     ahf[mi], b0, b1);
                    mma_fp16(acc[mi][np * 2 + 1], ahf[mi], b2, b3);
                }
                if (a_two_term) {
#pragma unroll
                    for (int mi = 0; mi < 4; mi++) {
                        mma_fp16(acc[mi][np * 2],     alf[mi], b0, b1);
                        mma_fp16(acc[mi][np * 2 + 1], alf[mi], b2, b3);
                    }
                }
            }
        }
        __syncthreads();
    }

    const int erow = bm + wm * 64 + (lane >> 2);
    const int ecol = bn + wn * 64 + (lane & 3) * 2;
#pragma unroll
    for (int mi = 0; mi < 4; mi++) {
#pragma unroll
        for (int nj = 0; nj < 8; nj++) {
            const int gc = ecol + nj * 8;
            const float b0 = bias[gc], b1 = bias[gc + 1];
#pragma unroll
            for (int half = 0; half < 2; half++) {
                const int gr = erow + mi * 16 + half * 8;
                const float v0 = (acc[mi][nj][half * 2]     + b0) * scale;
                const float v1 = (acc[mi][nj][half * 2 + 1] + b1) * scale;
                if (!qkv_mode) {
                    *(float2*)(outf + (size_t)gr * DMODEL + gc) = make_float2(v0, v1);
                } else {
                    const int b = gr >> 11, s = gr & 2047;
                    const int h = gc >> 6,  d = gc & 63;
                    const size_t oi = (((size_t)b * HNUM + h) * SEQ + s) * DK + d;
                    *(uint32_t*)(outh + oi) = pack2h(v0, v1);
                }
            }
        }
    }
}

// ---------------------------------------------------------------------------
// MMA flash attention (fp16): Q,K,V,P single fp16. 128-thread CTA,
// 128-key chunks, 2-stage cp.async, 2 CTAs/SM.
// Softmax uses ex2.approx.f16x2 (half the MUFU ops; result is the packed
// fp16 P fragment directly). Row-sum via half2 group sums -> fp32.
// Output single fp16 [B,S,H*64].
// ---------------------------------------------------------------------------
#define AT_K 0u
#define AT_V 16384u
#define AT_STAGE 32768u
#define ATTN_SMEM 65536

__global__ void __launch_bounds__(128, 2) attn_mma_kernel(
    const __half* __restrict__ Q, const __half* __restrict__ K,
    const __half* __restrict__ V, const int* __restrict__ mask,
    __half* __restrict__ Oh)
{
    extern __shared__ __align__(16) char smem[];
    __shared__ int msk[2][128];
    const uint32_t sb = smem_to_u32(smem);
    const int tid = threadIdx.x, lane = tid & 31, wid = tid >> 5;
    const int bh = blockIdx.y, b = bh / HNUM, h = bh % HNUM;
    const int q0 = blockIdx.x * 64;
    const size_t hb = (size_t)bh * SEQ * DK;
    const int rm8 = lane & 7;

    for (int i = tid; i < 512; i += 128) {
        const int r = i >> 3, c = i & 7;
        const uint32_t so = (uint32_t)(r * 128 + ((c ^ (r & 7)) << 4));
        *(uint4*)(smem + AT_K + so) =
            *(const uint4*)(Q + hb + (size_t)(q0 + r) * DK + c * 8);
    }
    __syncthreads();

    const int arow = wid * 16 + (lane & 15);
    const int ach  = lane >> 4;
    uint32_t qf[4][4];
#pragma unroll
    for (int ks = 0; ks < 4; ks++) {
        const uint32_t co = (uint32_t)(((ks * 2 + ach) ^ rm8) << 4);
        ldsm_x4(qf[ks][0], qf[ks][1], qf[ks][2], qf[ks][3],
                sb + AT_K + arow * 128 + co);
    }
    __syncthreads();

    float oacc[8][4];
#pragma unroll
    for (int nj = 0; nj < 8; nj++)
#pragma unroll
        for (int c = 0; c < 4; c++) oacc[nj][c] = 0.0f;
    float mr0 = -1e30f, mr1 = -1e30f, lr0 = 0.0f, lr1 = 0.0f;

    const int knloc = (lane & 7) + ((lane >> 4) << 3);
    const int kch   = (lane >> 3) & 1;
    const int vrow_base = (lane & 7) + (((lane >> 3) & 1) << 3);
    const int vch   = lane >> 4;
    const int c0i   = 2 * (lane & 3);

    auto prefetch_kv = [&](int ch, int st) {
        const uint32_t base = sb + st * AT_STAGE;
        const int j0 = ch * 128;
#pragma unroll
        for (int i = tid; i < 1024; i += 128) {
            const int r = i >> 3, c = i & 7;
            const uint32_t so = (uint32_t)(r * 128 + ((c ^ (r & 7)) << 4));
            const size_t g = hb + (size_t)(j0 + r) * DK + c * 8;
            cp16(base + AT_K + so, K + g);
            cp16(base + AT_V + so, V + g);
        }
        CP_COMMIT();
    };

    prefetch_kv(0, 0);
    msk[0][tid] = mask[b * SEQ + tid];
    for (int ch = 0; ch < SEQ / 128; ch++) {
        if (ch + 1 < SEQ / 128) {
            prefetch_kv(ch + 1, (ch + 1) & 1);
            msk[(ch + 1) & 1][tid] = mask[b * SEQ + (ch + 1) * 128 + tid];
            CP_WAIT1();
        } else {
            CP_WAIT0();
        }
        __syncthreads();

        const uint32_t base = sb + (ch & 1) * AT_STAGE;
        const int* mk = msk[ch & 1];

        // S = Q K^T over 128 keys (16 n-tiles)
        float sacc[16][4];
#pragma unroll
        for (int nj = 0; nj < 16; nj++)
#pragma unroll
            for (int c = 0; c < 4; c++) sacc[nj][c] = 0.0f;

#pragma unroll
        for (int ks = 0; ks < 4; ks++) {
            const uint32_t co = (uint32_t)(((ks * 2 + kch) ^ rm8) << 4);
#pragma unroll
            for (int np = 0; np < 8; np++) {
                const int nrow = np * 16 + knloc;
                uint32_t k0, k1, k2, k3;
                ldsm_x4(k0, k1, k2, k3, base + AT_K + nrow * 128 + co);
                mma_fp16(sacc[np * 2],     qf[ks], k0, k1);
                mma_fp16(sacc[np * 2 + 1], qf[ks], k2, k3);
            }
        }

        // Mask + online softmax (base-2, fp16x2 exp)
#pragma unroll
        for (int nj = 0; nj < 16; nj++) {
            const int ki = nj * 8 + c0i;
            if (mk[ki] == 0)     { sacc[nj][0] = -1e9f; sacc[nj][2] = -1e9f; }
            if (mk[ki + 1] == 0) { sacc[nj][1] = -1e9f; sacc[nj][3] = -1e9f; }
        }
        float m0 = -1e30f, m1 = -1e30f;
#pragma unroll
        for (int nj = 0; nj < 16; nj++) {
            m0 = fmaxf(m0, fmaxf(sacc[nj][0], sacc[nj][1]));
            m1 = fmaxf(m1, fmaxf(sacc[nj][2], sacc[nj][3]));
        }
        m0 = fmaxf(m0, __shfl_xor_sync(0xffffffffu, m0, 1));
        m0 = fmaxf(m0, __shfl_xor_sync(0xffffffffu, m0, 2));
        m1 = fmaxf(m1, __shfl_xor_sync(0xffffffffu, m1, 1));
        m1 = fmaxf(m1, __shfl_xor_sync(0xffffffffu, m1, 2));
        const float mn0 = fmaxf(mr0, m0), mn1 = fmaxf(mr1, m1);
        const float al0 = ex2f(mr0 - mn0), al1 = ex2f(mr1 - mn1);
        mr0 = mn0; mr1 = mn1;

        float rs0 = 0.0f, rs1 = 0.0f;
        uint32_t phi[16][2];
        // groups of 4 tiles: half2 partial sums -> fp32 (bounded <=8 each)
#pragma unroll
        for (int g = 0; g < 4; g++) {
            __half2 hsA = __float2half2_rn(0.0f);
            __half2 hsB = __float2half2_rn(0.0f);
#pragma unroll
            for (int j = 0; j < 4; j++) {
                const int nj = g * 4 + j;
                phi[nj][0] = ex2h2(pack2h(sacc[nj][0] - mn0, sacc[nj][1] - mn0));
                phi[nj][1] = ex2h2(pack2h(sacc[nj][2] - mn1, sacc[nj][3] - mn1));
                hsA = __hadd2(hsA, *(__half2*)&phi[nj][0]);
                hsB = __hadd2(hsB, *(__half2*)&phi[nj][1]);
            }
            rs0 += __low2float(hsA) + __high2float(hsA);
            rs1 += __low2float(hsB) + __high2float(hsB);
        }
        rs0 += __shfl_xor_sync(0xffffffffu, rs0, 1);
        rs0 += __shfl_xor_sync(0xffffffffu, rs0, 2);
        rs1 += __shfl_xor_sync(0xffffffffu, rs1, 1);
        rs1 += __shfl_xor_sync(0xffffffffu, rs1, 2);
        lr0 = lr0 * al0 + rs0;
        lr1 = lr1 * al1 + rs1;
#pragma unroll
        for (int nj = 0; nj < 8; nj++) {
            oacc[nj][0] *= al0; oacc[nj][1] *= al0;
            oacc[nj][2] *= al1; oacc[nj][3] *= al1;
        }

        // O += P @ V over 128 keys (8 k-tiles)
#pragma unroll
        for (int kt = 0; kt < 8; kt++) {
            uint32_t pah[4] = { phi[2 * kt][0], phi[2 * kt][1],
                                phi[2 * kt + 1][0], phi[2 * kt + 1][1] };
            const int vrow = kt * 16 + vrow_base;
#pragma unroll
            for (int np = 0; np < 4; np++) {
                const uint32_t co = (uint32_t)(((np * 2 + vch) ^ rm8) << 4);
                uint32_t v0, v1, v2, v3;
                ldsm_x4_t(v0, v1, v2, v3, base + AT_V + vrow * 128 + co);
                mma_fp16(oacc[np * 2],     pah, v0, v1);
                mma_fp16(oacc[np * 2 + 1], pah, v2, v3);
            }
        }
        __syncthreads();
    }

    const float inv0 = 1.0f / lr0, inv1 = 1.0f / lr1;
    const int s0 = q0 + wid * 16 + (lane >> 2);
#pragma unroll
    for (int nj = 0; nj < 8; nj++) {
        const int d = nj * 8 + c0i;
#pragma unroll
        for (int half = 0; half < 2; half++) {
            const int s = s0 + half * 8;
            const float v0 = oacc[nj][half * 2]     * (half ? inv1 : inv0);
            const float v1 = oacc[nj][half * 2 + 1] * (half ? inv1 : inv0);
            const size_t oi = (size_t)(b * SEQ + s) * DMODEL + h * DK + d;
            *(uint32_t*)(Oh + oi) = pack2h(v0, v1);
        }
    }
}

// ---------------------------------------------------------------------------
// Launch
// ---------------------------------------------------------------------------
extern "C" void kernel_launch(void* const* d_in, const int* in_sizes, int n_in,
                              void* d_out, int out_size)
{
    const float* query = (const float*)d_in[0];
    const float* key   = (const float*)d_in[1];
    const float* value = (const float*)d_in[2];
    const int*   mask  = (const int*)  d_in[3];
    const float* Wq    = (const float*)d_in[4];
    const float* bq    = (const float*)d_in[5];
    const float* Wk    = (const float*)d_in[6];
    const float* bk    = (const float*)d_in[7];
    const float* Wv    = (const float*)d_in[8];
    const float* bv    = (const float*)d_in[9];
    const float* Wo    = (const float*)d_in[10];
    const float* bo    = (const float*)d_in[11];

    __half *q16, *k16, *v16, *ah, *al, *w16, *oh;
    cudaGetSymbolAddress((void**)&q16, g_q16);
    cudaGetSymbolAddress((void**)&k16, g_k16);
    cudaGetSymbolAddress((void**)&v16, g_v16);
    cudaGetSymbolAddress((void**)&ah, g_ah);
    cudaGetSymbolAddress((void**)&al, g_al);
    cudaGetSymbolAddress((void**)&w16, g_w16);
    cudaGetSymbolAddress((void**)&oh, g_oh);

    cudaFuncSetAttribute(tc_gemm_kernel,
                         cudaFuncAttributeMaxDynamicSharedMemorySize, GEMM_SMEM);
    cudaFuncSetAttribute(attn_mma_kernel,
                         cudaFuncAttributeMaxDynamicSharedMemorySize, ATTN_SMEM);

    const int a4 = NA_ / 4, w4 = NW_ / 4;

    cvt_split_h_kernel<<<dim3((a4 + 255) / 256, 3), 256>>>(
        query, key, value,
        ah, ah + NA_, ah + 2 * NA_,
        al, al + NA_, al + 2 * NA_, a4);
    cvt_h_kernel<<<dim3((w4 + 255) / 256, 4), 256>>>(
        Wq, Wk, Wv, Wo,
        w16, w16 + NW_, w16 + 2 * NW_, w16 + 3 * NW_, w4);

    const float qscale = 0.125f * 1.4426950408889634f;

    tc_gemm_kernel<<<dim3(DMODEL / 256, MTOT / 128, 3), 256, GEMM_SMEM>>>(
        ah, al, w16, bq, bk, bv, nullptr,
        q16, k16, v16, qscale, 1, 1);

    attn_mma_kernel<<<dim3(SEQ / 64, BATCH * HNUM), 128, ATTN_SMEM>>>(
        q16, k16, v16, mask, oh);

    tc_gemm_kernel<<<dim3(DMODEL / 256, MTOT / 128, 1), 256, GEMM_SMEM>>>(
        oh, nullptr, w16 + 3 * NW_, bo, nullptr, nullptr, (float*)d_out,
        nullptr, nullptr, nullptr, 1.0f, 0, 0);
}

// round 16
// speedup vs baseline: 1.8276x; 1.0077x over previous
#include <cuda_runtime.h>
#include <cuda_bf16.h>
#include <cuda_fp16.h>
#include <cstdint>
#include <math.h>

#define HNUM   12
#define DMODEL 768
#define BATCH  2
#define SEQ    2048
#define DK     64
#define MTOT   (BATCH * SEQ)          // 4096
#define NA_ (MTOT * DMODEL)           // 3145728
#define NW_ (DMODEL * DMODEL)         // 589824

// ---------------------------------------------------------------------------
// Scratch: all fp16. Input activations 2-term; weights & attn-out single.
// ---------------------------------------------------------------------------
__device__ __half g_q16[BATCH * HNUM * SEQ * DK];
__device__ __half g_k16[BATCH * HNUM * SEQ * DK];
__device__ __half g_v16[BATCH * HNUM * SEQ * DK];

__device__ __half g_ah[3 * NA_];
__device__ __half g_al[3 * NA_];
__device__ __half g_w16[4 * NW_];
__device__ __half g_oh[NA_];

// ---------------------------------------------------------------------------
// Helpers
// ---------------------------------------------------------------------------
__device__ __forceinline__ uint32_t smem_to_u32(const void* p) {
    uint32_t a;
    asm("{ .reg .u64 t; cvta.to.shared.u64 t, %1; cvt.u32.u64 %0, t; }"
        : "=r"(a) : "l"(p));
    return a;
}
__device__ __forceinline__ void cp16(uint32_t s, const void* g) {
    asm volatile("cp.async.cg.shared.global [%0], [%1], 16;" :: "r"(s), "l"(g));
}
#define CP_COMMIT() asm volatile("cp.async.commit_group;" ::: "memory")
#define CP_WAIT1()  asm volatile("cp.async.wait_group 1;" ::: "memory")
#define CP_WAIT0()  asm volatile("cp.async.wait_group 0;" ::: "memory")

__device__ __forceinline__ void ldsm_x4(uint32_t& r0, uint32_t& r1,
                                        uint32_t& r2, uint32_t& r3, uint32_t addr) {
    asm volatile("ldmatrix.sync.aligned.m8n8.x4.shared.b16 {%0,%1,%2,%3}, [%4];"
                 : "=r"(r0), "=r"(r1), "=r"(r2), "=r"(r3) : "r"(addr));
}
__device__ __forceinline__ void ldsm_x4_t(uint32_t& r0, uint32_t& r1,
                                          uint32_t& r2, uint32_t& r3, uint32_t addr) {
    asm volatile("ldmatrix.sync.aligned.m8n8.x4.trans.shared.b16 {%0,%1,%2,%3}, [%4];"
                 : "=r"(r0), "=r"(r1), "=r"(r2), "=r"(r3) : "r"(addr));
}
__device__ __forceinline__ void mma_fp16(float* c, const uint32_t* a,
                                         uint32_t b0, uint32_t b1) {
    asm volatile("mma.sync.aligned.m16n8k16.row.col.f32.f16.f16.f32 "
                 "{%0,%1,%2,%3}, {%4,%5,%6,%7}, {%8,%9}, {%0,%1,%2,%3};"
                 : "+f"(c[0]), "+f"(c[1]), "+f"(c[2]), "+f"(c[3])
                 : "r"(a[0]), "r"(a[1]), "r"(a[2]), "r"(a[3]), "r"(b0), "r"(b1));
}
__device__ __forceinline__ float ex2f(float x) {
    float y;
    asm("ex2.approx.ftz.f32 %0, %1;" : "=f"(y) : "f"(x));
    return y;
}
__device__ __forceinline__ uint32_t ex2h2(uint32_t x) {
    uint32_t y;
    asm("ex2.approx.f16x2 %0, %1;" : "=r"(y) : "r"(x));
    return y;
}
__device__ __forceinline__ uint32_t pack2h(float v0, float v1) {
    __half2 h = __floats2half2_rn(v0, v1);
    return *(uint32_t*)&h;
}
__device__ __forceinline__ void split2h(float v0, float v1,
                                        uint32_t& hp, uint32_t& lp) {
    __half2 h = __floats2half2_rn(v0, v1);
    hp = *(uint32_t*)&h;
    const float h0 = __half2float(__low2half(h));
    const float h1 = __half2float(__high2half(h));
    __half2 l = __floats2half2_rn(v0 - h0, v1 - h1);
    lp = *(uint32_t*)&l;
}

// ---------------------------------------------------------------------------
// fp32 -> fp16 hi/lo split (activations); blockIdx.y selects tensor
// ---------------------------------------------------------------------------
__global__ void __launch_bounds__(256) cvt_split_h_kernel(
    const float* x0, const float* x1, const float* x2,
    __half* h0p, __half* h1p, __half* h2p,
    __half* l0p, __half* l1p, __half* l2p, int n4)
{
    const int z = blockIdx.y;
    const float* x = (z == 0) ? x0 : (z == 1) ? x1 : x2;
    __half* hi = (z == 0) ? h0p : (z == 1) ? h1p : h2p;
    __half* lo = (z == 0) ? l0p : (z == 1) ? l1p : l2p;
    int i = blockIdx.x * 256 + threadIdx.x;
    if (i >= n4) return;
    float4 v = ((const float4*)x)[i];
    uint32_t hp0, lp0, hp1, lp1;
    split2h(v.x, v.y, hp0, lp0);
    split2h(v.z, v.w, hp1, lp1);
    ((uint32_t*)hi)[2 * i]     = hp0;
    ((uint32_t*)hi)[2 * i + 1] = hp1;
    ((uint32_t*)lo)[2 * i]     = lp0;
    ((uint32_t*)lo)[2 * i + 1] = lp1;
}

// fp32 -> single fp16 (weights); blockIdx.y selects tensor
__global__ void __launch_bounds__(256) cvt_h_kernel(
    const float* x0, const float* x1, const float* x2, const float* x3,
    __half* o0, __half* o1, __half* o2, __half* o3, int n4)
{
    const int z = blockIdx.y;
    const float* x = (z == 0) ? x0 : (z == 1) ? x1 : (z == 2) ? x2 : x3;
    __half* o = (z == 0) ? o0 : (z == 1) ? o1 : (z == 2) ? o2 : o3;
    int i = blockIdx.x * 256 + threadIdx.x;
    if (i >= n4) return;
    float4 v = ((const float4*)x)[i];
    ((uint32_t*)o)[2 * i]     = pack2h(v.x, v.y);
    ((uint32_t*)o)[2 * i + 1] = pack2h(v.z, v.w);
}

// ---------------------------------------------------------------------------
// HMMA GEMM (fp16): A (1 or 2 term) x W (1 term). 3-stage cp.async ring.
// Per chunk: CP_WAIT(stage) -> syncthreads -> compute -> prefetch(st+2).
// CTA tile 128x256, 8 warps (2M x 4N).
// ---------------------------------------------------------------------------
#define OFF_AH 0u
#define OFF_AL 16384u
#define OFF_B  32768u
#define STAGE_SZ 65536u
#define GEMM_SMEM 196608
#define GEMM_NCH (DMODEL / 64)   // 12

__global__ void __launch_bounds__(256, 1) tc_gemm_kernel(
    const __half* Abase_h, const __half* Abase_l, const __half* Wbase,
    const float* bias0, const float* bias1, const float* bias2,
    float* outf,
    __half* o0h, __half* o1h, __half* o2h,
    float scale0, int qkv_mode, int a_two_term)
{
    extern __shared__ __align__(16) char smem[];
    const uint32_t sb = smem_to_u32(smem);
    const int tid  = threadIdx.x;
    const int lane = tid & 31;
    const int wid  = tid >> 5;
    const int wm   = wid & 1;
    const int wn   = wid >> 1;
    const int bm = blockIdx.y * 128;
    const int bn = blockIdx.x * 256;
    const int z  = blockIdx.z;

    const __half* Ah = Abase_h + (size_t)z * NA_;
    const __half* Al = Abase_l ? (Abase_l + (size_t)z * NA_) : nullptr;
    const __half* W  = Wbase   + (size_t)z * NW_;
    const float* bias = (z == 0) ? bias0 : (z == 1) ? bias1 : bias2;
    const float scale = (z == 0) ? scale0 : 1.0f;
    __half* outh = (z == 0) ? o0h : (z == 1) ? o1h : o2h;

    float acc[4][8][4];
#pragma unroll
    for (int mi = 0; mi < 4; mi++)
#pragma unroll
        for (int nj = 0; nj < 8; nj++)
#pragma unroll
            for (int c = 0; c < 4; c++) acc[mi][nj][c] = 0.0f;

    const int a_row   = wm * 64 + (lane & 15);
    const int a_chalf = lane >> 4;
    const int b_nloc  = wn * 64 + (lane & 7) + ((lane >> 4) << 3);
    const int b_chalf = (lane >> 3) & 1;
    const int rm8     = lane & 7;

    auto prefetch = [&](int ch, int st) {
        const uint32_t base = sb + (uint32_t)st * STAGE_SZ;
        const int k0 = ch * 64;
#pragma unroll
        for (int i = tid; i < 1024; i += 256) {
            const int r = i >> 3, c = i & 7;
            const uint32_t so = (uint32_t)(r * 128 + ((c ^ (r & 7)) << 4));
            const size_t ga = (size_t)(bm + r) * DMODEL + k0 + c * 8;
            cp16(base + OFF_AH + so, Ah + ga);
            if (a_two_term) cp16(base + OFF_AL + so, Al + ga);
        }
#pragma unroll
        for (int i = tid; i < 2048; i += 256) {
            const int r = i >> 3, c = i & 7;
            const uint32_t so = (uint32_t)(r * 128 + ((c ^ (r & 7)) << 4));
            cp16(base + OFF_B + so, W + (size_t)(bn + r) * DMODEL + k0 + c * 8);
        }
        CP_COMMIT();
    };

    prefetch(0, 0);
    prefetch(1, 1);
    int st = 0;
    for (int ch = 0; ch < GEMM_NCH; ch++) {
        // wait for stage st's group (per-thread), THEN barrier for visibility
        if (ch + 1 < GEMM_NCH) CP_WAIT1(); else CP_WAIT0();
        __syncthreads();

        const uint32_t base = sb + (uint32_t)st * STAGE_SZ;
#pragma unroll
        for (int ks = 0; ks < 4; ks++) {
            uint32_t ahf[4][4], alf[4][4];
            const uint32_t aco = (uint32_t)(((ks * 2 + a_chalf) ^ rm8) << 4);
#pragma unroll
            for (int mi = 0; mi < 4; mi++) {
                const int row = a_row + mi * 16;
                ldsm_x4(ahf[mi][0], ahf[mi][1], ahf[mi][2], ahf[mi][3],
                        base + OFF_AH + row * 128 + aco);
                if (a_two_term)
                    ldsm_x4(alf[mi][0], alf[mi][1], alf[mi][2], alf[mi][3],
                            base + OFF_AL + row * 128 + aco);
            }
            const uint32_t bco = (uint32_t)(((ks * 2 + b_chalf) ^ rm8) << 4);
#pragma unroll
            for (int np = 0; np < 4; np++) {
                const int nrow = b_nloc + np * 16;
                uint32_t b0, b1, b2, b3;
                ldsm_x4(b0, b1, b2, b3, base + OFF_B + nrow * 128 + bco);
#pragma unroll
                for (int mi = 0; mi < 4; mi++) {
                    mma_fp16(acc[mi][np * 2],     ahf[mi], b0, b1);
                    mma_fp16(acc[mi][np * 2 + 1], ahf[mi], b2, b3);
                }
                if (a_two_term) {
#pragma unroll
                    for (int mi = 0; mi < 4; mi++) {
                        mma_fp16(acc[mi][np * 2],     alf[mi], b0, b1);
                        mma_fp16(acc[mi][np * 2 + 1], alf[mi], b2, b3);
                    }
                }
            }
        }

        // prefetch into stage (st+2)%3: its readers (chunk ch-1) all passed
        // the barrier at the top of this chunk.
        if (ch + 2 < GEMM_NCH) {
            int pf = st + 2; if (pf >= 3) pf -= 3;
            prefetch(ch + 2, pf);
        }
        st = (st + 1 < 3) ? st + 1 : 0;
    }

    const int erow = bm + wm * 64 + (lane >> 2);
    const int ecol = bn + wn * 64 + (lane & 3) * 2;
#pragma unroll
    for (int mi = 0; mi < 4; mi++) {
#pragma unroll
        for (int nj = 0; nj < 8; nj++) {
            const int gc = ecol + nj * 8;
            const float b0 = bias[gc], b1 = bias[gc + 1];
#pragma unroll
            for (int half = 0; half < 2; half++) {
                const int gr = erow + mi * 16 + half * 8;
                const float v0 = (acc[mi][nj][half * 2]     + b0) * scale;
                const float v1 = (acc[mi][nj][half * 2 + 1] + b1) * scale;
                if (!qkv_mode) {
                    *(float2*)(outf + (size_t)gr * DMODEL + gc) = make_float2(v0, v1);
                } else {
                    const int b = gr >> 11, s = gr & 2047;
                    const int h = gc >> 6,  d = gc & 63;
                    const size_t oi = (((size_t)b * HNUM + h) * SEQ + s) * DK + d;
                    *(uint32_t*)(outh + oi) = pack2h(v0, v1);
                }
            }
        }
    }
}

// ---------------------------------------------------------------------------
// MMA flash attention (fp16): 128-thread CTA, 128-key chunks, 3-stage
// cp.async ring; per chunk: CP_WAIT -> sync -> compute -> prefetch. 2 CTAs/SM.
// ---------------------------------------------------------------------------
#define AT_K 0u
#define AT_V 16384u
#define AT_STAGE 32768u
#define ATTN_SMEM 98304
#define AT_NCH (SEQ / 128)   // 16

__global__ void __launch_bounds__(128, 2) attn_mma_kernel(
    const __half* __restrict__ Q, const __half* __restrict__ K,
    const __half* __restrict__ V, const int* __restrict__ mask,
    __half* __restrict__ Oh)
{
    extern __shared__ __align__(16) char smem[];
    __shared__ int msk[3][128];
    const uint32_t sb = smem_to_u32(smem);
    const int tid = threadIdx.x, lane = tid & 31, wid = tid >> 5;
    const int bh = blockIdx.y, b = bh / HNUM, h = bh % HNUM;
    const int q0 = blockIdx.x * 64;
    const size_t hb = (size_t)bh * SEQ * DK;
    const int rm8 = lane & 7;

    // Stage Q tile in stage-0 K area, pull fragments
    for (int i = tid; i < 512; i += 128) {
        const int r = i >> 3, c = i & 7;
        const uint32_t so = (uint32_t)(r * 128 + ((c ^ (r & 7)) << 4));
        *(uint4*)(smem + AT_K + so) =
            *(const uint4*)(Q + hb + (size_t)(q0 + r) * DK + c * 8);
    }
    __syncthreads();

    const int arow = wid * 16 + (lane & 15);
    const int ach  = lane >> 4;
    uint32_t qf[4][4];
#pragma unroll
    for (int ks = 0; ks < 4; ks++) {
        const uint32_t co = (uint32_t)(((ks * 2 + ach) ^ rm8) << 4);
        ldsm_x4(qf[ks][0], qf[ks][1], qf[ks][2], qf[ks][3],
                sb + AT_K + arow * 128 + co);
    }
    __syncthreads();

    float oacc[8][4];
#pragma unroll
    for (int nj = 0; nj < 8; nj++)
#pragma unroll
        for (int c = 0; c < 4; c++) oacc[nj][c] = 0.0f;
    float mr0 = -1e30f, mr1 = -1e30f, lr0 = 0.0f, lr1 = 0.0f;

    const int knloc = (lane & 7) + ((lane >> 4) << 3);
    const int kch   = (lane >> 3) & 1;
    const int vrow_base = (lane & 7) + (((lane >> 3) & 1) << 3);
    const int vch   = lane >> 4;
    const int c0i   = 2 * (lane & 3);

    auto prefetch_kv = [&](int ch, int st) {
        const uint32_t base = sb + (uint32_t)st * AT_STAGE;
        const int j0 = ch * 128;
#pragma unroll
        for (int i = tid; i < 1024; i += 128) {
            const int r = i >> 3, c = i & 7;
            const uint32_t so = (uint32_t)(r * 128 + ((c ^ (r & 7)) << 4));
            const size_t g = hb + (size_t)(j0 + r) * DK + c * 8;
            cp16(base + AT_K + so, K + g);
            cp16(base + AT_V + so, V + g);
        }
        CP_COMMIT();
    };

    prefetch_kv(0, 0);
    prefetch_kv(1, 1);
    msk[0][tid] = mask[b * SEQ + tid];
    msk[1][tid] = mask[b * SEQ + 128 + tid];

    int st = 0;
    for (int ch = 0; ch < AT_NCH; ch++) {
        // wait for stage st's cp.async group, THEN barrier for visibility
        if (ch + 1 < AT_NCH) CP_WAIT1(); else CP_WAIT0();
        __syncthreads();

        const uint32_t base = sb + (uint32_t)st * AT_STAGE;
        const int* mk = msk[st];

        // S = Q K^T over 128 keys (16 n-tiles)
        float sacc[16][4];
#pragma unroll
        for (int nj = 0; nj < 16; nj++)
#pragma unroll
            for (int c = 0; c < 4; c++) sacc[nj][c] = 0.0f;

#pragma unroll
        for (int ks = 0; ks < 4; ks++) {
            const uint32_t co = (uint32_t)(((ks * 2 + kch) ^ rm8) << 4);
#pragma unroll
            for (int np = 0; np < 8; np++) {
                const int nrow = np * 16 + knloc;
                uint32_t k0, k1, k2, k3;
                ldsm_x4(k0, k1, k2, k3, base + AT_K + nrow * 128 + co);
                mma_fp16(sacc[np * 2],     qf[ks], k0, k1);
                mma_fp16(sacc[np * 2 + 1], qf[ks], k2, k3);
            }
        }

        // Mask + online softmax (base-2, fp16x2 exp)
#pragma unroll
        for (int nj = 0; nj < 16; nj++) {
            const int ki = nj * 8 + c0i;
            if (mk[ki] == 0)     { sacc[nj][0] = -1e9f; sacc[nj][2] = -1e9f; }
            if (mk[ki + 1] == 0) { sacc[nj][1] = -1e9f; sacc[nj][3] = -1e9f; }
        }
        float m0 = -1e30f, m1 = -1e30f;
#pragma unroll
        for (int nj = 0; nj < 16; nj++) {
            m0 = fmaxf(m0, fmaxf(sacc[nj][0], sacc[nj][1]));
            m1 = fmaxf(m1, fmaxf(sacc[nj][2], sacc[nj][3]));
        }
        m0 = fmaxf(m0, __shfl_xor_sync(0xffffffffu, m0, 1));
        m0 = fmaxf(m0, __shfl_xor_sync(0xffffffffu, m0, 2));
        m1 = fmaxf(m1, __shfl_xor_sync(0xffffffffu, m1, 1));
        m1 = fmaxf(m1, __shfl_xor_sync(0xffffffffu, m1, 2));
        const float mn0 = fmaxf(mr0, m0), mn1 = fmaxf(mr1, m1);
        const float al0 = ex2f(mr0 - mn0), al1 = ex2f(mr1 - mn1);
        mr0 = mn0; mr1 = mn1;

        float rs0 = 0.0f, rs1 = 0.0f;
        uint32_t phi[16][2];
#pragma unroll
        for (int g = 0; g < 4; g++) {
            __half2 hsA = __float2half2_rn(0.0f);
            __half2 hsB = __float2half2_rn(0.0f);
#pragma unroll
            for (int j = 0; j < 4; j++) {
                const int nj = g * 4 + j;
                phi[nj][0] = ex2h2(pack2h(sacc[nj][0] - mn0, sacc[nj][1] - mn0));
                phi[nj][1] = ex2h2(pack2h(sacc[nj][2] - mn1, sacc[nj][3] - mn1));
                hsA = __hadd2(hsA, *(__half2*)&phi[nj][0]);
                hsB = __hadd2(hsB, *(__half2*)&phi[nj][1]);
            }
            rs0 += __low2float(hsA) + __high2float(hsA);
            rs1 += __low2float(hsB) + __high2float(hsB);
        }
        rs0 += __shfl_xor_sync(0xffffffffu, rs0, 1);
        rs0 += __shfl_xor_sync(0xffffffffu, rs0, 2);
        rs1 += __shfl_xor_sync(0xffffffffu, rs1, 1);
        rs1 += __shfl_xor_sync(0xffffffffu, rs1, 2);
        lr0 = lr0 * al0 + rs0;
        lr1 = lr1 * al1 + rs1;
#pragma unroll
        for (int nj = 0; nj < 8; nj++) {
            oacc[nj][0] *= al0; oacc[nj][1] *= al0;
            oacc[nj][2] *= al1; oacc[nj][3] *= al1;
        }

        // O += P @ V over 128 keys (8 k-tiles)
#pragma unroll
        for (int kt = 0; kt < 8; kt++) {
            uint32_t pah[4] = { phi[2 * kt][0], phi[2 * kt][1],
                                phi[2 * kt + 1][0], phi[2 * kt + 1][1] };
            const int vrow = kt * 16 + vrow_base;
#pragma unroll
            for (int np = 0; np < 4; np++) {
                const uint32_t co = (uint32_t)(((np * 2 + vch) ^ rm8) << 4);
                uint32_t v0, v1, v2, v3;
                ldsm_x4_t(v0, v1, v2, v3, base + AT_V + vrow * 128 + co);
                mma_fp16(oacc[np * 2],     pah, v0, v1);
                mma_fp16(oacc[np * 2 + 1], pah, v2, v3);
            }
        }

        // prefetch into stage (st+2)%3 (readers finished before this chunk's
        // top barrier); same for its msk slot.
        if (ch + 2 < AT_NCH) {
            int pf = st + 2; if (pf >= 3) pf -= 3;
            prefetch_kv(ch + 2, pf);
            msk[pf][tid] = mask[b * SEQ + (ch + 2) * 128 + tid];
        }
        st = (st + 1 < 3) ? st + 1 : 0;
    }

    const float inv0 = 1.0f / lr0, inv1 = 1.0f / lr1;
    const int s0 = q0 + wid * 16 + (lane >> 2);
#pragma unroll
    for (int nj = 0; nj < 8; nj++) {
        const int d = nj * 8 + c0i;
#pragma unroll
        for (int half = 0; half < 2; half++) {
            const int s = s0 + half * 8;
            const float v0 = oacc[nj][half * 2]     * (half ? inv1 : inv0);
            const float v1 = oacc[nj][half * 2 + 1] * (half ? inv1 : inv0);
            const size_t oi = (size_t)(b * SEQ + s) * DMODEL + h * DK + d;
            *(uint32_t*)(Oh + oi) = pack2h(v0, v1);
        }
    }
}

// ---------------------------------------------------------------------------
// Launch
// ---------------------------------------------------------------------------
extern "C" void kernel_launch(void* const* d_in, const int* in_sizes, int n_in,
                              void* d_out, int out_size)
{
    const float* query = (const float*)d_in[0];
    const float* key   = (const float*)d_in[1];
    const float* value = (const float*)d_in[2];
    const int*   mask  = (const int*)  d_in[3];
    const float* Wq    = (const float*)d_in[4];
    const float* bq    = (const float*)d_in[5];
    const float* Wk    = (const float*)d_in[6];
    const float* bk    = (const float*)d_in[7];
    const float* Wv    = (const float*)d_in[8];
    const float* bv    = (const float*)d_in[9];
    const float* Wo    = (const float*)d_in[10];
    const float* bo    = (const float*)d_in[11];

    __half *q16, *k16, *v16, *ah, *al, *w16, *oh;
    cudaGetSymbolAddress((void**)&q16, g_q16);
    cudaGetSymbolAddress((void**)&k16, g_k16);
    cudaGetSymbolAddress((void**)&v16, g_v16);
    cudaGetSymbolAddress((void**)&ah, g_ah);
    cudaGetSymbolAddress((void**)&al, g_al);
    cudaGetSymbolAddress((void**)&w16, g_w16);
    cudaGetSymbolAddress((void**)&oh, g_oh);

    cudaFuncSetAttribute(tc_gemm_kernel,
                         cudaFuncAttributeMaxDynamicSharedMemorySize, GEMM_SMEM);
    cudaFuncSetAttribute(attn_mma_kernel,
                         cudaFuncAttributeMaxDynamicSharedMemorySize, ATTN_SMEM);

    const int a4 = NA_ / 4, w4 = NW_ / 4;

    cvt_split_h_kernel<<<dim3((a4 + 255) / 256, 3), 256>>>(
        query, key, value,
        ah, ah + NA_, ah + 2 * NA_,
        al, al + NA_, al + 2 * NA_, a4);
    cvt_h_kernel<<<dim3((w4 + 255) / 256, 4), 256>>>(
        Wq, Wk, Wv, Wo,
        w16, w16 + NW_, w16 + 2 * NW_, w16 + 3 * NW_, w4);

    const float qscale = 0.125f * 1.4426950408889634f;

    tc_gemm_kernel<<<dim3(DMODEL / 256, MTOT / 128, 3), 256, GEMM_SMEM>>>(
        ah, al, w16, bq, bk, bv, nullptr,
        q16, k16, v16, qscale, 1, 1);

    attn_mma_kernel<<<dim3(SEQ / 64, BATCH * HNUM), 128, ATTN_SMEM>>>(
        q16, k16, v16, mask, oh);

    tc_gemm_kernel<<<dim3(DMODEL / 256, MTOT / 128, 1), 256, GEMM_SMEM>>>(
        oh, nullptr, w16 + 3 * NW_, bo, nullptr, nullptr, (float*)d_out,
        nullptr, nullptr, nullptr, 1.0f, 0, 0);
}

// round 17
// speedup vs baseline: 1.8278x; 1.0001x over previous
#include <cuda_runtime.h>
#include <cuda_bf16.h>
#include <cuda_fp16.h>
#include <cstdint>
#include <math.h>

#define HNUM   12
#define DMODEL 768
#define BATCH  2
#define SEQ    2048
#define DK     64
#define MTOT   (BATCH * SEQ)          // 4096
#define NA_ (MTOT * DMODEL)           // 3145728
#define NW_ (DMODEL * DMODEL)         // 589824

// ---------------------------------------------------------------------------
// Scratch: all fp16. Input activations 2-term; weights & attn-out single.
// ---------------------------------------------------------------------------
__device__ __half g_q16[BATCH * HNUM * SEQ * DK];
__device__ __half g_k16[BATCH * HNUM * SEQ * DK];
__device__ __half g_v16[BATCH * HNUM * SEQ * DK];

__device__ __half g_ah[3 * NA_];
__device__ __half g_al[3 * NA_];
__device__ __half g_w16[4 * NW_];
__device__ __half g_oh[NA_];

// ---------------------------------------------------------------------------
// Helpers
// ---------------------------------------------------------------------------
__device__ __forceinline__ uint32_t smem_to_u32(const void* p) {
    uint32_t a;
    asm("{ .reg .u64 t; cvta.to.shared.u64 t, %1; cvt.u32.u64 %0, t; }"
        : "=r"(a) : "l"(p));
    return a;
}
__device__ __forceinline__ void cp16(uint32_t s, const void* g) {
    asm volatile("cp.async.cg.shared.global [%0], [%1], 16;" :: "r"(s), "l"(g));
}
#define CP_COMMIT() asm volatile("cp.async.commit_group;" ::: "memory")
#define CP_WAIT1()  asm volatile("cp.async.wait_group 1;" ::: "memory")
#define CP_WAIT0()  asm volatile("cp.async.wait_group 0;" ::: "memory")

__device__ __forceinline__ void ldsm_x4(uint32_t& r0, uint32_t& r1,
                                        uint32_t& r2, uint32_t& r3, uint32_t addr) {
    asm volatile("ldmatrix.sync.aligned.m8n8.x4.shared.b16 {%0,%1,%2,%3}, [%4];"
                 : "=r"(r0), "=r"(r1), "=r"(r2), "=r"(r3) : "r"(addr));
}
__device__ __forceinline__ void ldsm_x4_t(uint32_t& r0, uint32_t& r1,
                                          uint32_t& r2, uint32_t& r3, uint32_t addr) {
    asm volatile("ldmatrix.sync.aligned.m8n8.x4.trans.shared.b16 {%0,%1,%2,%3}, [%4];"
                 : "=r"(r0), "=r"(r1), "=r"(r2), "=r"(r3) : "r"(addr));
}
__device__ __forceinline__ void mma_fp16(float* c, const uint32_t* a,
                                         uint32_t b0, uint32_t b1) {
    asm volatile("mma.sync.aligned.m16n8k16.row.col.f32.f16.f16.f32 "
                 "{%0,%1,%2,%3}, {%4,%5,%6,%7}, {%8,%9}, {%0,%1,%2,%3};"
                 : "+f"(c[0]), "+f"(c[1]), "+f"(c[2]), "+f"(c[3])
                 : "r"(a[0]), "r"(a[1]), "r"(a[2]), "r"(a[3]), "r"(b0), "r"(b1));
}
__device__ __forceinline__ float ex2f(float x) {
    float y;
    asm("ex2.approx.ftz.f32 %0, %1;" : "=f"(y) : "f"(x));
    return y;
}
__device__ __forceinline__ uint32_t ex2h2(uint32_t x) {
    uint32_t y;
    asm("ex2.approx.f16x2 %0, %1;" : "=r"(y) : "r"(x));
    return y;
}
__device__ __forceinline__ uint32_t pack2h(float v0, float v1) {
    __half2 h = __floats2half2_rn(v0, v1);
    return *(uint32_t*)&h;
}
__device__ __forceinline__ void split2h(float v0, float v1,
                                        uint32_t& hp, uint32_t& lp) {
    __half2 h = __floats2half2_rn(v0, v1);
    hp = *(uint32_t*)&h;
    const float h0 = __half2float(__low2half(h));
    const float h1 = __half2float(__high2half(h));
    __half2 l = __floats2half2_rn(v0 - h0, v1 - h1);
    lp = *(uint32_t*)&l;
}

// ---------------------------------------------------------------------------
// fp32 -> fp16 hi/lo split (activations); blockIdx.y selects tensor
// ---------------------------------------------------------------------------
__global__ void __launch_bounds__(256) cvt_split_h_kernel(
    const float* x0, const float* x1, const float* x2,
    __half* h0p, __half* h1p, __half* h2p,
    __half* l0p, __half* l1p, __half* l2p, int n4)
{
    const int z = blockIdx.y;
    const float* x = (z == 0) ? x0 : (z == 1) ? x1 : x2;
    __half* hi = (z == 0) ? h0p : (z == 1) ? h1p : h2p;
    __half* lo = (z == 0) ? l0p : (z == 1) ? l1p : l2p;
    int i = blockIdx.x * 256 + threadIdx.x;
    if (i >= n4) return;
    float4 v = ((const float4*)x)[i];
    uint32_t hp0, lp0, hp1, lp1;
    split2h(v.x, v.y, hp0, lp0);
    split2h(v.z, v.w, hp1, lp1);
    ((uint32_t*)hi)[2 * i]     = hp0;
    ((uint32_t*)hi)[2 * i + 1] = hp1;
    ((uint32_t*)lo)[2 * i]     = lp0;
    ((uint32_t*)lo)[2 * i + 1] = lp1;
}

// fp32 -> single fp16 (weights); blockIdx.y selects tensor
__global__ void __launch_bounds__(256) cvt_h_kernel(
    const float* x0, const float* x1, const float* x2, const float* x3,
    __half* o0, __half* o1, __half* o2, __half* o3, int n4)
{
    const int z = blockIdx.y;
    const float* x = (z == 0) ? x0 : (z == 1) ? x1 : (z == 2) ? x2 : x3;
    __half* o = (z == 0) ? o0 : (z == 1) ? o1 : (z == 2) ? o2 : o3;
    int i = blockIdx.x * 256 + threadIdx.x;
    if (i >= n4) return;
    float4 v = ((const float4*)x)[i];
    ((uint32_t*)o)[2 * i]     = pack2h(v.x, v.y);
    ((uint32_t*)o)[2 * i + 1] = pack2h(v.z, v.w);
}

// ---------------------------------------------------------------------------
// HMMA GEMM (fp16): A (1 or 2 term) x W (1 term). 3-stage cp.async ring.
// Per chunk: CP_WAIT(stage) -> syncthreads -> compute -> prefetch(st+2).
// CTA tile 128x256, 8 warps (2M x 4N).
// ---------------------------------------------------------------------------
#define OFF_AH 0u
#define OFF_AL 16384u
#define OFF_B  32768u
#define STAGE_SZ 65536u
#define GEMM_SMEM 196608
#define GEMM_NCH (DMODEL / 64)   // 12

__global__ void __launch_bounds__(256, 1) tc_gemm_kernel(
    const __half* Abase_h, const __half* Abase_l, const __half* Wbase,
    const float* bias0, const float* bias1, const float* bias2,
    float* outf,
    __half* o0h, __half* o1h, __half* o2h,
    float scale0, int qkv_mode, int a_two_term)
{
    extern __shared__ __align__(16) char smem[];
    const uint32_t sb = smem_to_u32(smem);
    const int tid  = threadIdx.x;
    const int lane = tid & 31;
    const int wid  = tid >> 5;
    const int wm   = wid & 1;
    const int wn   = wid >> 1;
    const int bm = blockIdx.y * 128;
    const int bn = blockIdx.x * 256;
    const int z  = blockIdx.z;

    const __half* Ah = Abase_h + (size_t)z * NA_;
    const __half* Al = Abase_l ? (Abase_l + (size_t)z * NA_) : nullptr;
    const __half* W  = Wbase   + (size_t)z * NW_;
    const float* bias = (z == 0) ? bias0 : (z == 1) ? bias1 : bias2;
    const float scale = (z == 0) ? scale0 : 1.0f;
    __half* outh = (z == 0) ? o0h : (z == 1) ? o1h : o2h;

    float acc[4][8][4];
#pragma unroll
    for (int mi = 0; mi < 4; mi++)
#pragma unroll
        for (int nj = 0; nj < 8; nj++)
#pragma unroll
            for (int c = 0; c < 4; c++) acc[mi][nj][c] = 0.0f;

    const int a_row   = wm * 64 + (lane & 15);
    const int a_chalf = lane >> 4;
    const int b_nloc  = wn * 64 + (lane & 7) + ((lane >> 4) << 3);
    const int b_chalf = (lane >> 3) & 1;
    const int rm8     = lane & 7;

    auto prefetch = [&](int ch, int st) {
        const uint32_t base = sb + (uint32_t)st * STAGE_SZ;
        const int k0 = ch * 64;
#pragma unroll
        for (int i = tid; i < 1024; i += 256) {
            const int r = i >> 3, c = i & 7;
            const uint32_t so = (uint32_t)(r * 128 + ((c ^ (r & 7)) << 4));
            const size_t ga = (size_t)(bm + r) * DMODEL + k0 + c * 8;
            cp16(base + OFF_AH + so, Ah + ga);
            if (a_two_term) cp16(base + OFF_AL + so, Al + ga);
        }
#pragma unroll
        for (int i = tid; i < 2048; i += 256) {
            const int r = i >> 3, c = i & 7;
            const uint32_t so = (uint32_t)(r * 128 + ((c ^ (r & 7)) << 4));
            cp16(base + OFF_B + so, W + (size_t)(bn + r) * DMODEL + k0 + c * 8);
        }
        CP_COMMIT();
    };

    prefetch(0, 0);
    prefetch(1, 1);
    int st = 0;
    for (int ch = 0; ch < GEMM_NCH; ch++) {
        if (ch + 1 < GEMM_NCH) CP_WAIT1(); else CP_WAIT0();
        __syncthreads();

        const uint32_t base = sb + (uint32_t)st * STAGE_SZ;
#pragma unroll
        for (int ks = 0; ks < 4; ks++) {
            uint32_t ahf[4][4], alf[4][4];
            const uint32_t aco = (uint32_t)(((ks * 2 + a_chalf) ^ rm8) << 4);
#pragma unroll
            for (int mi = 0; mi < 4; mi++) {
                const int row = a_row + mi * 16;
                ldsm_x4(ahf[mi][0], ahf[mi][1], ahf[mi][2], ahf[mi][3],
                        base + OFF_AH + row * 128 + aco);
                if (a_two_term)
                    ldsm_x4(alf[mi][0], alf[mi][1], alf[mi][2], alf[mi][3],
                            base + OFF_AL + row * 128 + aco);
            }
            const uint32_t bco = (uint32_t)(((ks * 2 + b_chalf) ^ rm8) << 4);
#pragma unroll
            for (int np = 0; np < 4; np++) {
                const int nrow = b_nloc + np * 16;
                uint32_t b0, b1, b2, b3;
                ldsm_x4(b0, b1, b2, b3, base + OFF_B + nrow * 128 + bco);
#pragma unroll
                for (int mi = 0; mi < 4; mi++) {
                    mma_fp16(acc[mi][np * 2],     ahf[mi], b0, b1);
                    mma_fp16(acc[mi][np * 2 + 1], ahf[mi], b2, b3);
                }
                if (a_two_term) {
#pragma unroll
                    for (int mi = 0; mi < 4; mi++) {
                        mma_fp16(acc[mi][np * 2],     alf[mi], b0, b1);
                        mma_fp16(acc[mi][np * 2 + 1], alf[mi], b2, b3);
                    }
                }
            }
        }

        if (ch + 2 < GEMM_NCH) {
            int pf = st + 2; if (pf >= 3) pf -= 3;
            prefetch(ch + 2, pf);
        }
        st = (st + 1 < 3) ? st + 1 : 0;
    }

    const int erow = bm + wm * 64 + (lane >> 2);
    const int ecol = bn + wn * 64 + (lane & 3) * 2;
#pragma unroll
    for (int mi = 0; mi < 4; mi++) {
#pragma unroll
        for (int nj = 0; nj < 8; nj++) {
            const int gc = ecol + nj * 8;
            const float b0 = bias[gc], b1 = bias[gc + 1];
#pragma unroll
            for (int half = 0; half < 2; half++) {
                const int gr = erow + mi * 16 + half * 8;
                const float v0 = (acc[mi][nj][half * 2]     + b0) * scale;
                const float v1 = (acc[mi][nj][half * 2 + 1] + b1) * scale;
                if (!qkv_mode) {
                    *(float2*)(outf + (size_t)gr * DMODEL + gc) = make_float2(v0, v1);
                } else {
                    const int b = gr >> 11, s = gr & 2047;
                    const int h = gc >> 6,  d = gc & 63;
                    const size_t oi = (((size_t)b * HNUM + h) * SEQ + s) * DK + d;
                    *(uint32_t*)(outh + oi) = pack2h(v0, v1);
                }
            }
        }
    }
}

// ---------------------------------------------------------------------------
// MMA flash attention (fp16), PERSISTENT: 256 CTAs, each handles 3 jobs
// (b,h,q-tile). 128-thread CTA, 128-key chunks, 3-stage cp.async ring,
// 2 CTAs/SM -> single wave, zero tail.
// ---------------------------------------------------------------------------
#define AT_K 0u
#define AT_V 16384u
#define AT_STAGE 32768u
#define ATTN_SMEM 98304
#define AT_NCH (SEQ / 128)        // 16
#define AT_JOBS ((SEQ / 64) * BATCH * HNUM)   // 768
#define AT_GRID 256

__global__ void __launch_bounds__(128, 2) attn_mma_kernel(
    const __half* __restrict__ Q, const __half* __restrict__ K,
    const __half* __restrict__ V, const int* __restrict__ mask,
    __half* __restrict__ Oh)
{
    extern __shared__ __align__(16) char smem[];
    __shared__ int msk[3][128];
    const uint32_t sb = smem_to_u32(smem);
    const int tid = threadIdx.x, lane = tid & 31, wid = tid >> 5;
    const int rm8 = lane & 7;

    const int arow = wid * 16 + (lane & 15);
    const int ach  = lane >> 4;
    const int knloc = (lane & 7) + ((lane >> 4) << 3);
    const int kch   = (lane >> 3) & 1;
    const int vrow_base = (lane & 7) + (((lane >> 3) & 1) << 3);
    const int vch   = lane >> 4;
    const int c0i   = 2 * (lane & 3);

    for (int job = blockIdx.x; job < AT_JOBS; job += AT_GRID) {
        const int bh = job >> 5;              // job / 32 q-tiles
        const int qt = job & 31;
        const int b  = bh / HNUM, h = bh % HNUM;
        const int q0 = qt * 64;
        const size_t hb = (size_t)bh * SEQ * DK;

        // All warps finished reading ring smem of the previous job
        __syncthreads();

        // Stage Q tile in stage-0 K area, pull fragments
        for (int i = tid; i < 512; i += 128) {
            const int r = i >> 3, c = i & 7;
            const uint32_t so = (uint32_t)(r * 128 + ((c ^ (r & 7)) << 4));
            *(uint4*)(smem + AT_K + so) =
                *(const uint4*)(Q + hb + (size_t)(q0 + r) * DK + c * 8);
        }
        __syncthreads();

        uint32_t qf[4][4];
#pragma unroll
        for (int ks = 0; ks < 4; ks++) {
            const uint32_t co = (uint32_t)(((ks * 2 + ach) ^ rm8) << 4);
            ldsm_x4(qf[ks][0], qf[ks][1], qf[ks][2], qf[ks][3],
                    sb + AT_K + arow * 128 + co);
        }
        __syncthreads();

        float oacc[8][4];
#pragma unroll
        for (int nj = 0; nj < 8; nj++)
#pragma unroll
            for (int c = 0; c < 4; c++) oacc[nj][c] = 0.0f;
        float mr0 = -1e30f, mr1 = -1e30f, lr0 = 0.0f, lr1 = 0.0f;

        auto prefetch_kv = [&](int ch, int st) {
            const uint32_t base = sb + (uint32_t)st * AT_STAGE;
            const int j0 = ch * 128;
#pragma unroll
            for (int i = tid; i < 1024; i += 128) {
                const int r = i >> 3, c = i & 7;
                const uint32_t so = (uint32_t)(r * 128 + ((c ^ (r & 7)) << 4));
                const size_t g = hb + (size_t)(j0 + r) * DK + c * 8;
                cp16(base + AT_K + so, K + g);
                cp16(base + AT_V + so, V + g);
            }
            CP_COMMIT();
        };

        prefetch_kv(0, 0);
        prefetch_kv(1, 1);
        msk[0][tid] = mask[b * SEQ + tid];
        msk[1][tid] = mask[b * SEQ + 128 + tid];

        int st = 0;
        for (int ch = 0; ch < AT_NCH; ch++) {
            if (ch + 1 < AT_NCH) CP_WAIT1(); else CP_WAIT0();
            __syncthreads();

            const uint32_t base = sb + (uint32_t)st * AT_STAGE;
            const int* mk = msk[st];

            // S = Q K^T over 128 keys (16 n-tiles)
            float sacc[16][4];
#pragma unroll
            for (int nj = 0; nj < 16; nj++)
#pragma unroll
                for (int c = 0; c < 4; c++) sacc[nj][c] = 0.0f;

#pragma unroll
            for (int ks = 0; ks < 4; ks++) {
                const uint32_t co = (uint32_t)(((ks * 2 + kch) ^ rm8) << 4);
#pragma unroll
                for (int np = 0; np < 8; np++) {
                    const int nrow = np * 16 + knloc;
                    uint32_t k0, k1, k2, k3;
                    ldsm_x4(k0, k1, k2, k3, base + AT_K + nrow * 128 + co);
                    mma_fp16(sacc[np * 2],     qf[ks], k0, k1);
                    mma_fp16(sacc[np * 2 + 1], qf[ks], k2, k3);
                }
            }

            // Mask + online softmax (base-2, fp16x2 exp)
#pragma unroll
            for (int nj = 0; nj < 16; nj++) {
                const int ki = nj * 8 + c0i;
                if (mk[ki] == 0)     { sacc[nj][0] = -1e9f; sacc[nj][2] = -1e9f; }
                if (mk[ki + 1] == 0) { sacc[nj][1] = -1e9f; sacc[nj][3] = -1e9f; }
            }
            float m0 = -1e30f, m1 = -1e30f;
#pragma unroll
            for (int nj = 0; nj < 16; nj++) {
                m0 = fmaxf(m0, fmaxf(sacc[nj][0], sacc[nj][1]));
                m1 = fmaxf(m1, fmaxf(sacc[nj][2], sacc[nj][3]));
            }
            m0 = fmaxf(m0, __shfl_xor_sync(0xffffffffu, m0, 1));
            m0 = fmaxf(m0, __shfl_xor_sync(0xffffffffu, m0, 2));
            m1 = fmaxf(m1, __shfl_xor_sync(0xffffffffu, m1, 1));
            m1 = fmaxf(m1, __shfl_xor_sync(0xffffffffu, m1, 2));
            const float mn0 = fmaxf(mr0, m0), mn1 = fmaxf(mr1, m1);
            const float al0 = ex2f(mr0 - mn0), al1 = ex2f(mr1 - mn1);
            mr0 = mn0; mr1 = mn1;

            float rs0 = 0.0f, rs1 = 0.0f;
            uint32_t phi[16][2];
#pragma unroll
            for (int g = 0; g < 4; g++) {
                __half2 hsA = __float2half2_rn(0.0f);
                __half2 hsB = __float2half2_rn(0.0f);
#pragma unroll
                for (int j = 0; j < 4; j++) {
                    const int nj = g * 4 + j;
                    phi[nj][0] = ex2h2(pack2h(sacc[nj][0] - mn0, sacc[nj][1] - mn0));
                    phi[nj][1] = ex2h2(pack2h(sacc[nj][2] - mn1, sacc[nj][3] - mn1));
                    hsA = __hadd2(hsA, *(__half2*)&phi[nj][0]);
                    hsB = __hadd2(hsB, *(__half2*)&phi[nj][1]);
                }
                rs0 += __low2float(hsA) + __high2float(hsA);
                rs1 += __low2float(hsB) + __high2float(hsB);
            }
            rs0 += __shfl_xor_sync(0xffffffffu, rs0, 1);
            rs0 += __shfl_xor_sync(0xffffffffu, rs0, 2);
            rs1 += __shfl_xor_sync(0xffffffffu, rs1, 1);
            rs1 += __shfl_xor_sync(0xffffffffu, rs1, 2);
            lr0 = lr0 * al0 + rs0;
            lr1 = lr1 * al1 + rs1;
#pragma unroll
            for (int nj = 0; nj < 8; nj++) {
                oacc[nj][0] *= al0; oacc[nj][1] *= al0;
                oacc[nj][2] *= al1; oacc[nj][3] *= al1;
            }

            // O += P @ V over 128 keys (8 k-tiles)
#pragma unroll
            for (int kt = 0; kt < 8; kt++) {
                uint32_t pah[4] = { phi[2 * kt][0], phi[2 * kt][1],
                                    phi[2 * kt + 1][0], phi[2 * kt + 1][1] };
                const int vrow = kt * 16 + vrow_base;
#pragma unroll
                for (int np = 0; np < 4; np++) {
                    const uint32_t co = (uint32_t)(((np * 2 + vch) ^ rm8) << 4);
                    uint32_t v0, v1, v2, v3;
                    ldsm_x4_t(v0, v1, v2, v3, base + AT_V + vrow * 128 + co);
                    mma_fp16(oacc[np * 2],     pah, v0, v1);
                    mma_fp16(oacc[np * 2 + 1], pah, v2, v3);
                }
            }

            if (ch + 2 < AT_NCH) {
                int pf = st + 2; if (pf >= 3) pf -= 3;
                prefetch_kv(ch + 2, pf);
                msk[pf][tid] = mask[b * SEQ + (ch + 2) * 128 + tid];
            }
            st = (st + 1 < 3) ? st + 1 : 0;
        }

        const float inv0 = 1.0f / lr0, inv1 = 1.0f / lr1;
        const int s0 = q0 + wid * 16 + (lane >> 2);
#pragma unroll
        for (int nj = 0; nj < 8; nj++) {
            const int d = nj * 8 + c0i;
#pragma unroll
            for (int half = 0; half < 2; half++) {
                const int s = s0 + half * 8;
                const float v0 = oacc[nj][half * 2]     * (half ? inv1 : inv0);
                const float v1 = oacc[nj][half * 2 + 1] * (half ? inv1 : inv0);
                const size_t oi = (size_t)(b * SEQ + s) * DMODEL + h * DK + d;
                *(uint32_t*)(Oh + oi) = pack2h(v0, v1);
            }
        }
    }
}

// ---------------------------------------------------------------------------
// Launch
// ---------------------------------------------------------------------------
extern "C" void kernel_launch(void* const* d_in, const int* in_sizes, int n_in,
                              void* d_out, int out_size)
{
    const float* query = (const float*)d_in[0];
    const float* key   = (const float*)d_in[1];
    const float* value = (const float*)d_in[2];
    const int*   mask  = (const int*)  d_in[3];
    const float* Wq    = (const float*)d_in[4];
    const float* bq    = (const float*)d_in[5];
    const float* Wk    = (const float*)d_in[6];
    const float* bk    = (const float*)d_in[7];
    const float* Wv    = (const float*)d_in[8];
    const float* bv    = (const float*)d_in[9];
    const float* Wo    = (const float*)d_in[10];
    const float* bo    = (const float*)d_in[11];

    __half *q16, *k16, *v16, *ah, *al, *w16, *oh;
    cudaGetSymbolAddress((void**)&q16, g_q16);
    cudaGetSymbolAddress((void**)&k16, g_k16);
    cudaGetSymbolAddress((void**)&v16, g_v16);
    cudaGetSymbolAddress((void**)&ah, g_ah);
    cudaGetSymbolAddress((void**)&al, g_al);
    cudaGetSymbolAddress((void**)&w16, g_w16);
    cudaGetSymbolAddress((void**)&oh, g_oh);

    cudaFuncSetAttribute(tc_gemm_kernel,
                         cudaFuncAttributeMaxDynamicSharedMemorySize, GEMM_SMEM);
    cudaFuncSetAttribute(attn_mma_kernel,
                         cudaFuncAttributeMaxDynamicSharedMemorySize, ATTN_SMEM);

    const int a4 = NA_ / 4, w4 = NW_ / 4;

    cvt_split_h_kernel<<<dim3((a4 + 255) / 256, 3), 256>>>(
        query, key, value,
        ah, ah + NA_, ah + 2 * NA_,
        al, al + NA_, al + 2 * NA_, a4);
    cvt_h_kernel<<<dim3((w4 + 255) / 256, 4), 256>>>(
        Wq, Wk, Wv, Wo,
        w16, w16 + NW_, w16 + 2 * NW_, w16 + 3 * NW_, w4);

    const float qscale = 0.125f * 1.4426950408889634f;

    tc_gemm_kernel<<<dim3(DMODEL / 256, MTOT / 128, 3), 256, GEMM_SMEM>>>(
        ah, al, w16, bq, bk, bv, nullptr,
        q16, k16, v16, qscale, 1, 1);

    attn_mma_kernel<<<AT_GRID, 128, ATTN_SMEM>>>(
        q16, k16, v16, mask, oh);

    tc_gemm_kernel<<<dim3(DMODEL / 256, MTOT / 128, 1), 256, GEMM_SMEM>>>(
        oh, nullptr, w16 + 3 * NW_, bo, nullptr, nullptr, (float*)d_out,
        nullptr, nullptr, nullptr, 1.0f, 0, 0);
}